// round 6
// baseline (speedup 1.0000x reference)
#include <cuda_runtime.h>
#include <cuda_bf16.h>
#include <math.h>
#include <stdint.h>

#define B_SZ   4
#define SEQ    2048
#define DM     1024
#define ST     16
#define M_TOT  (B_SZ * SEQ)   // 8192 rows
#define CHUNKS 32
#define CLEN   (SEQ / CHUNKS) // 64
#define KSPLIT 4

// ---------------- scratch (static device globals; no allocation) ----------------
__device__ float g_delta[M_TOT * DM];              // 32 MB
__device__ float g_BC[M_TOT * 2 * ST];             // 1 MB
__device__ float g_BCp[KSPLIT * M_TOT * 2 * ST];   // 4 MB partials
__device__ float g_f[B_SZ * CHUNKS * DM * ST];     // 8 MB
__device__ float g_hinit[B_SZ * CHUNKS * DM * ST]; // 8 MB
__device__ float g_dtsum[B_SZ * CHUNKS * DM];      // 512 KB
__device__ __nv_bfloat16 g_xhi[M_TOT * DM];        // 16 MB
__device__ __nv_bfloat16 g_xlo[M_TOT * DM];        // 16 MB
__device__ __nv_bfloat16 g_wthi[DM * DM];          // 2 MB  (n,k)-major
__device__ __nv_bfloat16 g_wtlo[DM * DM];          // 2 MB

// ---------------- helpers ----------------
__device__ __forceinline__ float softplus_f(float z) {
    return fmaxf(z, 0.0f) + log1pf(expf(-fabsf(z)));
}
__device__ __forceinline__ uint32_t smem_u32(const void* p) {
    uint32_t a;
    asm("{ .reg .u64 t; cvta.to.shared.u64 t, %1; cvt.u32.u64 %0, t; }" : "=r"(a) : "l"(p));
    return a;
}

#define CP_ASYNC16(dst, src) \
    asm volatile("cp.async.cg.shared.global [%0], [%1], 16;" :: "r"(dst), "l"(src))
#define CP_COMMIT()  asm volatile("cp.async.commit_group;" ::: "memory")
#define CP_WAIT(N)   asm volatile("cp.async.wait_group %0;" :: "n"(N) : "memory")

__device__ __forceinline__ void ldsm_x4(uint32_t& r0, uint32_t& r1, uint32_t& r2, uint32_t& r3,
                                        uint32_t addr) {
    asm volatile("ldmatrix.sync.aligned.m8n8.x4.shared.b16 {%0,%1,%2,%3}, [%4];"
                 : "=r"(r0), "=r"(r1), "=r"(r2), "=r"(r3) : "r"(addr));
}
__device__ __forceinline__ void ldsm_x2(uint32_t& r0, uint32_t& r1, uint32_t addr) {
    asm volatile("ldmatrix.sync.aligned.m8n8.x2.shared.b16 {%0,%1}, [%2];"
                 : "=r"(r0), "=r"(r1) : "r"(addr));
}
__device__ __forceinline__ void mma_bf16(float& c0, float& c1, float& c2, float& c3,
                                         uint32_t a0, uint32_t a1, uint32_t a2, uint32_t a3,
                                         uint32_t b0, uint32_t b1) {
    asm volatile(
        "mma.sync.aligned.m16n8k16.row.col.f32.bf16.bf16.f32 "
        "{%0,%1,%2,%3}, {%4,%5,%6,%7}, {%8,%9}, {%0,%1,%2,%3};"
        : "+f"(c0), "+f"(c1), "+f"(c2), "+f"(c3)
        : "r"(a0), "r"(a1), "r"(a2), "r"(a3), "r"(b0), "r"(b1));
}

// =================================================================================
// Kernel 0a: convert x -> bf16 hi/lo
// =================================================================================
__global__ __launch_bounds__(256) void convert_x_kernel(const float* __restrict__ x)
{
    const int i = blockIdx.x * 256 + threadIdx.x;     // over 2M float4s
    float4 v = ((const float4*)x)[i];
    __nv_bfloat16 hx = __float2bfloat16_rn(v.x);
    __nv_bfloat16 hy = __float2bfloat16_rn(v.y);
    __nv_bfloat16 hz = __float2bfloat16_rn(v.z);
    __nv_bfloat16 hw = __float2bfloat16_rn(v.w);
    __nv_bfloat162* phi = (__nv_bfloat162*)g_xhi;
    __nv_bfloat162* plo = (__nv_bfloat162*)g_xlo;
    phi[i * 2 + 0] = __nv_bfloat162(hx, hy);
    phi[i * 2 + 1] = __nv_bfloat162(hz, hw);
    plo[i * 2 + 0] = __nv_bfloat162(__float2bfloat16_rn(v.x - __bfloat162float(hx)),
                                    __float2bfloat16_rn(v.y - __bfloat162float(hy)));
    plo[i * 2 + 1] = __nv_bfloat162(__float2bfloat16_rn(v.z - __bfloat162float(hz)),
                                    __float2bfloat16_rn(v.w - __bfloat162float(hw)));
}

// =================================================================================
// Kernel 0b: transpose+convert Wd -> Wt_hi/lo ((n,k)-major bf16)
// =================================================================================
__global__ __launch_bounds__(256) void transpose_w_kernel(const float* __restrict__ Wd)
{
    __shared__ float tile[32][33];
    const int x0 = blockIdx.x * 32;
    const int y0 = blockIdx.y * 32;
    const int tx = threadIdx.x & 31;
    const int ty = threadIdx.x >> 5;   // 0..7
#pragma unroll
    for (int i = 0; i < 32; i += 8)
        tile[ty + i][tx] = Wd[(y0 + ty + i) * DM + x0 + tx];
    __syncthreads();
#pragma unroll
    for (int i = 0; i < 32; i += 8) {
        float v = tile[tx][ty + i];
        __nv_bfloat16 h = __float2bfloat16_rn(v);
        g_wthi[(x0 + ty + i) * DM + y0 + tx] = h;
        g_wtlo[(x0 + ty + i) * DM + y0 + tx] = __float2bfloat16_rn(v - __bfloat162float(h));
    }
}

// =================================================================================
// Kernel 1: delta = softplus(x @ Wd + bd) via mma.sync bf16 3-term split.
// CTA 128x128, BK=32, 8 warps (2m x 4n), warp tile 64x32, cp.async double buffer.
// =================================================================================
#define ROWB   80
#define T_A_HI 0
#define T_A_LO 10240
#define T_B_HI 20480
#define T_B_LO 30720
#define BUFS   40960
#define GS_TOTAL (2 * BUFS)  // 81920
#define BK     32
#define NSLAB  (DM / BK)     // 32

__device__ __forceinline__ void gemm_load_slab(uint32_t sb, int buf, int row0, int col0,
                                               int k0, int tid)
{
    const uint32_t base = sb + buf * BUFS;
#pragma unroll
    for (int t = 0; t < 2; t++) {
        int op  = tid + t * 256;       // 0..511
        int row = op >> 2;             // 0..127
        int seg = op & 3;              // 0..3 (16B each)
        uint32_t doff = row * ROWB + seg * 16;
        const __nv_bfloat16* sa = &g_xhi[(row0 + row) * DM + k0 + seg * 8];
        CP_ASYNC16(base + T_A_HI + doff, sa);
        const __nv_bfloat16* sal = &g_xlo[(row0 + row) * DM + k0 + seg * 8];
        CP_ASYNC16(base + T_A_LO + doff, sal);
        const __nv_bfloat16* sbh = &g_wthi[(col0 + row) * DM + k0 + seg * 8];
        CP_ASYNC16(base + T_B_HI + doff, sbh);
        const __nv_bfloat16* sbl = &g_wtlo[(col0 + row) * DM + k0 + seg * 8];
        CP_ASYNC16(base + T_B_LO + doff, sbl);
    }
}

__global__ __launch_bounds__(256) void gemm_delta_mma(const float* __restrict__ bd)
{
    extern __shared__ char smem[];
    const uint32_t sb = smem_u32(smem);
    const int tid  = threadIdx.x;
    const int lane = tid & 31;
    const int warp = tid >> 5;
    const int wm   = warp & 1;
    const int wn   = warp >> 1;
    const int row0 = blockIdx.y * 128;
    const int col0 = blockIdx.x * 128;

    float acc[4][4][4];
#pragma unroll
    for (int i = 0; i < 4; i++)
#pragma unroll
        for (int j = 0; j < 4; j++)
#pragma unroll
            for (int k = 0; k < 4; k++) acc[i][j][k] = 0.0f;

    const int rlA = (lane & 7) + 8 * ((lane >> 3) & 1);
    const int cbA = (lane >> 4) * 16;
    const int rlB = lane & 7;
    const int cbB = ((lane >> 3) & 1) * 16;

    gemm_load_slab(sb, 0, row0, col0, 0, tid);
    CP_COMMIT();

    for (int s = 0; s < NSLAB; s++) {
        if (s + 1 < NSLAB) {
            gemm_load_slab(sb, (s + 1) & 1, row0, col0, (s + 1) * BK, tid);
            CP_COMMIT();
            CP_WAIT(1);
        } else {
            CP_WAIT(0);
        }
        __syncthreads();

        const uint32_t bufb = sb + (s & 1) * BUFS;
        const uint32_t aHi = bufb + T_A_HI + (wm * 64) * ROWB;
        const uint32_t aLo = bufb + T_A_LO + (wm * 64) * ROWB;
        const uint32_t bHi = bufb + T_B_HI + (wn * 32) * ROWB;
        const uint32_t bLo = bufb + T_B_LO + (wn * 32) * ROWB;

#pragma unroll
        for (int ks = 0; ks < 2; ks++) {
            const int ksb = ks * 32;
            uint32_t ah[4][4], al[4][4];
#pragma unroll
            for (int mf = 0; mf < 4; mf++) {
                uint32_t ao = (mf * 16 + rlA) * ROWB + ksb + cbA;
                ldsm_x4(ah[mf][0], ah[mf][1], ah[mf][2], ah[mf][3], aHi + ao);
                ldsm_x4(al[mf][0], al[mf][1], al[mf][2], al[mf][3], aLo + ao);
            }
            uint32_t bh[4][2], bl[4][2];
#pragma unroll
            for (int nf = 0; nf < 4; nf++) {
                uint32_t bo = (nf * 8 + rlB) * ROWB + ksb + cbB;
                ldsm_x2(bh[nf][0], bh[nf][1], bHi + bo);
                ldsm_x2(bl[nf][0], bl[nf][1], bLo + bo);
            }
#pragma unroll
            for (int mf = 0; mf < 4; mf++)
#pragma unroll
                for (int nf = 0; nf < 4; nf++) {
                    float* c = acc[mf][nf];
                    mma_bf16(c[0], c[1], c[2], c[3],
                             ah[mf][0], ah[mf][1], ah[mf][2], ah[mf][3],
                             bh[nf][0], bh[nf][1]);
                    mma_bf16(c[0], c[1], c[2], c[3],
                             ah[mf][0], ah[mf][1], ah[mf][2], ah[mf][3],
                             bl[nf][0], bl[nf][1]);
                    mma_bf16(c[0], c[1], c[2], c[3],
                             al[mf][0], al[mf][1], al[mf][2], al[mf][3],
                             bh[nf][0], bh[nf][1]);
                }
        }
        __syncthreads();
    }

    const int g   = lane >> 2;
    const int tig = lane & 3;
#pragma unroll
    for (int nf = 0; nf < 4; nf++) {
        const int col = col0 + wn * 32 + nf * 8 + tig * 2;
        const float b0v = bd[col];
        const float b1v = bd[col + 1];
#pragma unroll
        for (int mf = 0; mf < 4; mf++) {
            const int row = row0 + wm * 64 + mf * 16 + g;
            float* c = acc[mf][nf];
            float2 v0, v1;
            v0.x = softplus_f(c[0] + b0v);
            v0.y = softplus_f(c[1] + b1v);
            v1.x = softplus_f(c[2] + b0v);
            v1.y = softplus_f(c[3] + b1v);
            *(float2*)&g_delta[row * DM + col]       = v0;
            *(float2*)&g_delta[(row + 8) * DM + col] = v1;
        }
    }
}

// =================================================================================
// Kernel 2: B/C projections, split-K x4 into partial buffers (no atomics).
// grid = (128 row-groups, KSPLIT). Each block: 64 rows, K range 256.
// =================================================================================
__global__ __launch_bounds__(256) void proj_bc_kernel(
    const float* __restrict__ x,
    const float* __restrict__ Wb,
    const float* __restrict__ Wc)
{
    __shared__ float xs[64 * 65];
    __shared__ float ws[64 * 32];

    const int tid  = threadIdx.x;
    const int row0 = blockIdx.x * 64;
    const int kseg = blockIdx.y;
    const int rl   = tid >> 2;
    const int q    = tid & 3;

    float acc[8];
#pragma unroll
    for (int j = 0; j < 8; j++) acc[j] = 0.0f;

    const int kbeg = kseg * (DM / KSPLIT);
    for (int kc = 0; kc < DM / KSPLIT; kc += 64) {
        const int k0 = kbeg + kc;
#pragma unroll
        for (int i = 0; i < 4; i++) {
            int idx = tid + i * 256;
            int r   = idx >> 4;
            int c4  = idx & 15;
            float4 v = *(const float4*)&x[(row0 + r) * DM + k0 + c4 * 4];
            xs[r * 65 + c4 * 4 + 0] = v.x;
            xs[r * 65 + c4 * 4 + 1] = v.y;
            xs[r * 65 + c4 * 4 + 2] = v.z;
            xs[r * 65 + c4 * 4 + 3] = v.w;
        }
        {
            int r  = tid >> 2;
            int c4 = tid & 3;
            *(float4*)&ws[r * 32 + c4 * 4]      = *(const float4*)&Wb[(k0 + r) * ST + c4 * 4];
            *(float4*)&ws[r * 32 + 16 + c4 * 4] = *(const float4*)&Wc[(k0 + r) * ST + c4 * 4];
        }
        __syncthreads();

#pragma unroll 8
        for (int k = 0; k < 64; k++) {
            float  xv = xs[rl * 65 + k];
            float4 w0 = *(float4*)&ws[k * 32 + q * 8];
            float4 w1 = *(float4*)&ws[k * 32 + q * 8 + 4];
            acc[0] = fmaf(xv, w0.x, acc[0]);
            acc[1] = fmaf(xv, w0.y, acc[1]);
            acc[2] = fmaf(xv, w0.z, acc[2]);
            acc[3] = fmaf(xv, w0.w, acc[3]);
            acc[4] = fmaf(xv, w1.x, acc[4]);
            acc[5] = fmaf(xv, w1.y, acc[5]);
            acc[6] = fmaf(xv, w1.z, acc[6]);
            acc[7] = fmaf(xv, w1.w, acc[7]);
        }
        __syncthreads();
    }

    const int row = row0 + rl;
    float* dst = g_BCp + kseg * (M_TOT * 2 * ST);
#pragma unroll
    for (int j = 0; j < 8; j++) {
        int c = q * 8 + j;
        int isC = (c >= 16);
        int n = isC ? (c - 16) : c;
        int pos = (row * 8 + (n >> 1)) * 4 + (isC ? 2 : 0) + (n & 1);
        dst[pos] = acc[j];
    }
}

// Reduce partials + bias into g_BC (interleaved layout).
__global__ __launch_bounds__(256) void proj_reduce_kernel(
    const float* __restrict__ bb, const float* __restrict__ bc)
{
    const int g = blockIdx.x * 256 + threadIdx.x;   // over M_TOT*8 float4s
    const int s = g & 7;
    const float4* p = (const float4*)g_BCp;
    float4 v = p[g];
#pragma unroll
    for (int k = 1; k < KSPLIT; k++) {
        float4 w = p[k * (M_TOT * 8) + g];
        v.x += w.x; v.y += w.y; v.z += w.z; v.w += w.w;
    }
    v.x += bb[2 * s];
    v.y += bb[2 * s + 1];
    v.z += bc[2 * s];
    v.w += bc[2 * s + 1];
    ((float4*)g_BC)[g] = v;
}

// =================================================================================
// Kernel 3a / 3c: chunk-local scan.
// =================================================================================
template<bool FINAL>
__global__ __launch_bounds__(256) void scan_chunk_kernel(
    const float* __restrict__ x,
    const float* __restrict__ A_log,
    const float* __restrict__ D_skip,
    float* __restrict__ out)
{
    const int tid = threadIdx.x;
    const int dl  = tid >> 3;
    const int sub = tid & 7;
    const int dg  = blockIdx.x & 31;
    const int c   = (blockIdx.x >> 5) & (CHUNKS - 1);
    const int b   = blockIdx.x >> 10;
    const int d   = dg * 32 + dl;

    const float A0 = -expf(A_log[d * ST + sub * 2]);
    const float A1 = -expf(A_log[d * ST + sub * 2 + 1]);

    const int rowbase = b * SEQ + c * CLEN;
    const float*  dp  = g_delta + rowbase * DM + d;
    const float*  xp  = x       + rowbase * DM + d;
    const float4* bcp = (const float4*)g_BC + rowbase * 8 + sub;
    const int sidx    = ((b * CHUNKS + c) * DM + d) * ST + sub * 2;

    float h0, h1;
    float Dsk = 0.0f;
    float* op = 0;
    if (FINAL) {
        float2 hv = *(const float2*)&g_hinit[sidx];
        h0 = hv.x; h1 = hv.y;
        Dsk = D_skip[d];
        op  = out + rowbase * DM + d;
    } else {
        h0 = 0.0f; h1 = 0.0f;
    }
    float dts = 0.0f;

#pragma unroll 8
    for (int t = 0; t < CLEN; t++) {
        float  dt = dp[t * DM];
        float  xv = xp[t * DM];
        float4 bc = bcp[t * 8];
        float e0 = __expf(dt * A0);
        float e1 = __expf(dt * A1);
        float dx = dt * xv;
        h0 = fmaf(e0, h0, dx * bc.x);
        h1 = fmaf(e1, h1, dx * bc.y);
        if (FINAL) {
            float p = fmaf(h0, bc.z, h1 * bc.w);
            p += __shfl_xor_sync(0xffffffffu, p, 1);
            p += __shfl_xor_sync(0xffffffffu, p, 2);
            p += __shfl_xor_sync(0xffffffffu, p, 4);
            if (sub == 0) op[t * DM] = fmaf(xv, Dsk, p);
        } else {
            dts += dt;
        }
    }

    if (!FINAL) {
        *(float2*)&g_f[sidx] = make_float2(h0, h1);
        if (sub == 0) g_dtsum[(b * CHUNKS + c) * DM + d] = dts;
    }
}

// =================================================================================
// Kernel 3b: sequential combine across chunks.
// =================================================================================
__global__ __launch_bounds__(256) void scan_combine_kernel(
    const float* __restrict__ A_log)
{
    const int tid = blockIdx.x * blockDim.x + threadIdx.x;
    const int n = tid & 15;
    const int d = (tid >> 4) & (DM - 1);
    const int b = tid >> 14;

    const float A = -expf(A_log[d * ST + n]);
    float H = 0.0f;
#pragma unroll
    for (int c = 0; c < CHUNKS; c++) {
        const int base = (b * CHUNKS + c) * DM + d;
        g_hinit[base * ST + n] = H;
        float P = __expf(A * g_dtsum[base]);
        H = fmaf(P, H, g_f[base * ST + n]);
    }
}

// =================================================================================
// launch
// =================================================================================
extern "C" void kernel_launch(void* const* d_in, const int* in_sizes, int n_in,
                              void* d_out, int out_size)
{
    const float* x      = (const float*)d_in[0];
    const float* A_log  = (const float*)d_in[1];
    const float* D_skip = (const float*)d_in[2];
    const float* Wd     = (const float*)d_in[3];
    const float* bd     = (const float*)d_in[4];
    const float* Wb     = (const float*)d_in[5];
    const float* bb     = (const float*)d_in[6];
    const float* Wc     = (const float*)d_in[7];
    const float* bc     = (const float*)d_in[8];
    float* out = (float*)d_out;

    cudaFuncSetAttribute(gemm_delta_mma, cudaFuncAttributeMaxDynamicSharedMemorySize, GS_TOTAL);

    convert_x_kernel<<<(M_TOT * DM / 4) / 256, 256>>>(x);
    {
        dim3 tgrid(DM / 32, DM / 32);
        transpose_w_kernel<<<tgrid, 256>>>(Wd);
    }
    {
        dim3 grid(DM / 128, M_TOT / 128);   // (8, 64)
        gemm_delta_mma<<<grid, 256, GS_TOTAL>>>(bd);
    }
    {
        dim3 pgrid(M_TOT / 64, KSPLIT);     // (128, 4)
        proj_bc_kernel<<<pgrid, 256>>>(x, Wb, Wc);
    }
    proj_reduce_kernel<<<(M_TOT * 8) / 256, 256>>>(bb, bc);

    const int scan_grid = B_SZ * CHUNKS * (DM / 32);   // 4096
    scan_chunk_kernel<false><<<scan_grid, 256>>>(x, A_log, D_skip, out);
    scan_combine_kernel<<<(B_SZ * DM * ST) / 256, 256>>>(A_log);
    scan_chunk_kernel<true><<<scan_grid, 256>>>(x, A_log, D_skip, out);
}

// round 7
// speedup vs baseline: 1.2987x; 1.2987x over previous
#include <cuda_runtime.h>
#include <cuda_bf16.h>
#include <math.h>
#include <stdint.h>

#define B_SZ   4
#define SEQ    2048
#define DM     1024
#define ST     16
#define M_TOT  (B_SZ * SEQ)   // 8192 rows
#define CHUNKS 32
#define CLEN   (SEQ / CHUNKS) // 64
#define PKSEG  8

// ---------------- scratch (static device globals; no allocation) ----------------
__device__ float g_delta[M_TOT * DM];              // 32 MB
__device__ float g_BC[M_TOT * 2 * ST];             // 1 MB
__device__ float g_BCp[PKSEG * M_TOT * 2 * ST];    // 8 MB partials
__device__ float g_f[B_SZ * CHUNKS * DM * ST];     // 8 MB
__device__ float g_hinit[B_SZ * CHUNKS * DM * ST]; // 8 MB
__device__ float g_dtsum[B_SZ * CHUNKS * DM];      // 512 KB
__device__ __nv_bfloat16 g_xhi[M_TOT * DM];        // 16 MB
__device__ __nv_bfloat16 g_xlo[M_TOT * DM];        // 16 MB
__device__ __nv_bfloat16 g_wthi[DM * DM];          // 2 MB  (n,k)-major
__device__ __nv_bfloat16 g_wtlo[DM * DM];          // 2 MB
__device__ __nv_bfloat16 g_wbchi[32 * DM];         // 64 KB (n,k)-major [Wb;Wc]^T
__device__ __nv_bfloat16 g_wbclo[32 * DM];         // 64 KB

// ---------------- helpers ----------------
__device__ __forceinline__ float softplus_f(float z) {
    return fmaxf(z, 0.0f) + log1pf(expf(-fabsf(z)));
}
__device__ __forceinline__ uint32_t smem_u32(const void* p) {
    uint32_t a;
    asm("{ .reg .u64 t; cvta.to.shared.u64 t, %1; cvt.u32.u64 %0, t; }" : "=r"(a) : "l"(p));
    return a;
}

#define CP_ASYNC16(dst, src) \
    asm volatile("cp.async.cg.shared.global [%0], [%1], 16;" :: "r"(dst), "l"(src))
#define CP_COMMIT()  asm volatile("cp.async.commit_group;" ::: "memory")
#define CP_WAIT(N)   asm volatile("cp.async.wait_group %0;" :: "n"(N) : "memory")

__device__ __forceinline__ void ldsm_x4(uint32_t& r0, uint32_t& r1, uint32_t& r2, uint32_t& r3,
                                        uint32_t addr) {
    asm volatile("ldmatrix.sync.aligned.m8n8.x4.shared.b16 {%0,%1,%2,%3}, [%4];"
                 : "=r"(r0), "=r"(r1), "=r"(r2), "=r"(r3) : "r"(addr));
}
__device__ __forceinline__ void ldsm_x2(uint32_t& r0, uint32_t& r1, uint32_t addr) {
    asm volatile("ldmatrix.sync.aligned.m8n8.x2.shared.b16 {%0,%1}, [%2];"
                 : "=r"(r0), "=r"(r1) : "r"(addr));
}
__device__ __forceinline__ void mma_bf16(float& c0, float& c1, float& c2, float& c3,
                                         uint32_t a0, uint32_t a1, uint32_t a2, uint32_t a3,
                                         uint32_t b0, uint32_t b1) {
    asm volatile(
        "mma.sync.aligned.m16n8k16.row.col.f32.bf16.bf16.f32 "
        "{%0,%1,%2,%3}, {%4,%5,%6,%7}, {%8,%9}, {%0,%1,%2,%3};"
        : "+f"(c0), "+f"(c1), "+f"(c2), "+f"(c3)
        : "r"(a0), "r"(a1), "r"(a2), "r"(a3), "r"(b0), "r"(b1));
}

// =================================================================================
// Kernel 0a: convert x -> bf16 hi/lo
// =================================================================================
__global__ __launch_bounds__(256) void convert_x_kernel(const float* __restrict__ x)
{
    const int i = blockIdx.x * 256 + threadIdx.x;
    float4 v = ((const float4*)x)[i];
    __nv_bfloat16 hx = __float2bfloat16_rn(v.x);
    __nv_bfloat16 hy = __float2bfloat16_rn(v.y);
    __nv_bfloat16 hz = __float2bfloat16_rn(v.z);
    __nv_bfloat16 hw = __float2bfloat16_rn(v.w);
    __nv_bfloat162* phi = (__nv_bfloat162*)g_xhi;
    __nv_bfloat162* plo = (__nv_bfloat162*)g_xlo;
    phi[i * 2 + 0] = __nv_bfloat162(hx, hy);
    phi[i * 2 + 1] = __nv_bfloat162(hz, hw);
    plo[i * 2 + 0] = __nv_bfloat162(__float2bfloat16_rn(v.x - __bfloat162float(hx)),
                                    __float2bfloat16_rn(v.y - __bfloat162float(hy)));
    plo[i * 2 + 1] = __nv_bfloat162(__float2bfloat16_rn(v.z - __bfloat162float(hz)),
                                    __float2bfloat16_rn(v.w - __bfloat162float(hw)));
}

// =================================================================================
// Kernel 0b: transpose+convert Wd -> Wt_hi/lo ((n,k)-major bf16)
// =================================================================================
__global__ __launch_bounds__(256) void transpose_w_kernel(const float* __restrict__ Wd)
{
    __shared__ float tile[32][33];
    const int x0 = blockIdx.x * 32;
    const int y0 = blockIdx.y * 32;
    const int tx = threadIdx.x & 31;
    const int ty = threadIdx.x >> 5;
#pragma unroll
    for (int i = 0; i < 32; i += 8)
        tile[ty + i][tx] = Wd[(y0 + ty + i) * DM + x0 + tx];
    __syncthreads();
#pragma unroll
    for (int i = 0; i < 32; i += 8) {
        float v = tile[tx][ty + i];
        __nv_bfloat16 h = __float2bfloat16_rn(v);
        g_wthi[(x0 + ty + i) * DM + y0 + tx] = h;
        g_wtlo[(x0 + ty + i) * DM + y0 + tx] = __float2bfloat16_rn(v - __bfloat162float(h));
    }
}

// =================================================================================
// Kernel 0c: transpose+convert [Wb | Wc] -> g_wbc hi/lo (32 x 1024, (n,k)-major)
// =================================================================================
__global__ __launch_bounds__(256) void transpose_wbc_kernel(
    const float* __restrict__ Wb, const float* __restrict__ Wc)
{
    const int idx = blockIdx.x * 256 + threadIdx.x;   // 0..32767
    const int n = idx >> 10;
    const int k = idx & (DM - 1);
    float v = (n < 16) ? Wb[k * ST + n] : Wc[k * ST + (n - 16)];
    __nv_bfloat16 h = __float2bfloat16_rn(v);
    g_wbchi[n * DM + k] = h;
    g_wbclo[n * DM + k] = __float2bfloat16_rn(v - __bfloat162float(h));
}

// =================================================================================
// Kernel 1: delta = softplus(x @ Wd + bd) via mma.sync bf16 3-term split.
// =================================================================================
#define ROWB   80
#define T_A_HI 0
#define T_A_LO 10240
#define T_B_HI 20480
#define T_B_LO 30720
#define BUFS   40960
#define GS_TOTAL (2 * BUFS)  // 81920
#define BK     32
#define NSLAB  (DM / BK)     // 32

__device__ __forceinline__ void gemm_load_slab(uint32_t sb, int buf, int row0, int col0,
                                               int k0, int tid)
{
    const uint32_t base = sb + buf * BUFS;
#pragma unroll
    for (int t = 0; t < 2; t++) {
        int op  = tid + t * 256;
        int row = op >> 2;
        int seg = op & 3;
        uint32_t doff = row * ROWB + seg * 16;
        CP_ASYNC16(base + T_A_HI + doff, &g_xhi[(row0 + row) * DM + k0 + seg * 8]);
        CP_ASYNC16(base + T_A_LO + doff, &g_xlo[(row0 + row) * DM + k0 + seg * 8]);
        CP_ASYNC16(base + T_B_HI + doff, &g_wthi[(col0 + row) * DM + k0 + seg * 8]);
        CP_ASYNC16(base + T_B_LO + doff, &g_wtlo[(col0 + row) * DM + k0 + seg * 8]);
    }
}

__global__ __launch_bounds__(256) void gemm_delta_mma(const float* __restrict__ bd)
{
    extern __shared__ char smem[];
    const uint32_t sb = smem_u32(smem);
    const int tid  = threadIdx.x;
    const int lane = tid & 31;
    const int warp = tid >> 5;
    const int wm   = warp & 1;
    const int wn   = warp >> 1;
    const int row0 = blockIdx.y * 128;
    const int col0 = blockIdx.x * 128;

    float acc[4][4][4];
#pragma unroll
    for (int i = 0; i < 4; i++)
#pragma unroll
        for (int j = 0; j < 4; j++)
#pragma unroll
            for (int k = 0; k < 4; k++) acc[i][j][k] = 0.0f;

    const int rlA = (lane & 7) + 8 * ((lane >> 3) & 1);
    const int cbA = (lane >> 4) * 16;
    const int rlB = lane & 7;
    const int cbB = ((lane >> 3) & 1) * 16;

    gemm_load_slab(sb, 0, row0, col0, 0, tid);
    CP_COMMIT();

    for (int s = 0; s < NSLAB; s++) {
        if (s + 1 < NSLAB) {
            gemm_load_slab(sb, (s + 1) & 1, row0, col0, (s + 1) * BK, tid);
            CP_COMMIT();
            CP_WAIT(1);
        } else {
            CP_WAIT(0);
        }
        __syncthreads();

        const uint32_t bufb = sb + (s & 1) * BUFS;
        const uint32_t aHi = bufb + T_A_HI + (wm * 64) * ROWB;
        const uint32_t aLo = bufb + T_A_LO + (wm * 64) * ROWB;
        const uint32_t bHi = bufb + T_B_HI + (wn * 32) * ROWB;
        const uint32_t bLo = bufb + T_B_LO + (wn * 32) * ROWB;

#pragma unroll
        for (int ks = 0; ks < 2; ks++) {
            const int ksb = ks * 32;
            uint32_t ah[4][4], al[4][4];
#pragma unroll
            for (int mf = 0; mf < 4; mf++) {
                uint32_t ao = (mf * 16 + rlA) * ROWB + ksb + cbA;
                ldsm_x4(ah[mf][0], ah[mf][1], ah[mf][2], ah[mf][3], aHi + ao);
                ldsm_x4(al[mf][0], al[mf][1], al[mf][2], al[mf][3], aLo + ao);
            }
            uint32_t bh[4][2], bl[4][2];
#pragma unroll
            for (int nf = 0; nf < 4; nf++) {
                uint32_t bo = (nf * 8 + rlB) * ROWB + ksb + cbB;
                ldsm_x2(bh[nf][0], bh[nf][1], bHi + bo);
                ldsm_x2(bl[nf][0], bl[nf][1], bLo + bo);
            }
#pragma unroll
            for (int mf = 0; mf < 4; mf++)
#pragma unroll
                for (int nf = 0; nf < 4; nf++) {
                    float* c = acc[mf][nf];
                    mma_bf16(c[0], c[1], c[2], c[3],
                             ah[mf][0], ah[mf][1], ah[mf][2], ah[mf][3],
                             bh[nf][0], bh[nf][1]);
                    mma_bf16(c[0], c[1], c[2], c[3],
                             ah[mf][0], ah[mf][1], ah[mf][2], ah[mf][3],
                             bl[nf][0], bl[nf][1]);
                    mma_bf16(c[0], c[1], c[2], c[3],
                             al[mf][0], al[mf][1], al[mf][2], al[mf][3],
                             bh[nf][0], bh[nf][1]);
                }
        }
        __syncthreads();
    }

    const int g   = lane >> 2;
    const int tig = lane & 3;
#pragma unroll
    for (int nf = 0; nf < 4; nf++) {
        const int col = col0 + wn * 32 + nf * 8 + tig * 2;
        const float b0v = bd[col];
        const float b1v = bd[col + 1];
#pragma unroll
        for (int mf = 0; mf < 4; mf++) {
            const int row = row0 + wm * 64 + mf * 16 + g;
            float* c = acc[mf][nf];
            float2 v0, v1;
            v0.x = softplus_f(c[0] + b0v);
            v0.y = softplus_f(c[1] + b1v);
            v1.x = softplus_f(c[2] + b0v);
            v1.y = softplus_f(c[3] + b1v);
            *(float2*)&g_delta[row * DM + col]       = v0;
            *(float2*)&g_delta[(row + 8) * DM + col] = v1;
        }
    }
}

// =================================================================================
// Kernel 2: B/C projection via mma.sync bf16 3-term split, split-K x8.
// grid (64 row-blocks of 128, 8 ksegs). Block: M=128, N=32, K=128 (4 slabs of 32).
// 8 warps, warp tile 16x32. Partials -> g_BCp (interleaved layout).
// =================================================================================
#define PJ_A_HI 0
#define PJ_A_LO 10240
#define PJ_B_HI 20480
#define PJ_B_LO 23040
#define PJ_BUF  25600
#define PJ_TOTAL (2 * PJ_BUF)  // 51200

__device__ __forceinline__ void proj_load_slab(uint32_t sb, int buf, int row0, int k0, int tid)
{
    const uint32_t base = sb + buf * PJ_BUF;
#pragma unroll
    for (int t = 0; t < 2; t++) {
        int op  = tid + t * 256;
        int row = op >> 2;
        int seg = op & 3;
        uint32_t doff = row * ROWB + seg * 16;
        CP_ASYNC16(base + PJ_A_HI + doff, &g_xhi[(row0 + row) * DM + k0 + seg * 8]);
        CP_ASYNC16(base + PJ_A_LO + doff, &g_xlo[(row0 + row) * DM + k0 + seg * 8]);
    }
    {
        int row = (tid & 127) >> 2;      // 0..31
        int seg = tid & 3;
        uint32_t doff = row * ROWB + seg * 16;
        if (tid < 128)
            CP_ASYNC16(base + PJ_B_HI + doff, &g_wbchi[row * DM + k0 + seg * 8]);
        else
            CP_ASYNC16(base + PJ_B_LO + doff, &g_wbclo[row * DM + k0 + seg * 8]);
    }
}

__global__ __launch_bounds__(256) void proj_mma_kernel()
{
    extern __shared__ char smem[];
    const uint32_t sb = smem_u32(smem);
    const int tid  = threadIdx.x;
    const int lane = tid & 31;
    const int warp = tid >> 5;
    const int row0 = blockIdx.x * 128;
    const int kseg = blockIdx.y;
    const int kbeg = kseg * (DM / PKSEG);   // 128-wide K range

    float acc[4][4];
#pragma unroll
    for (int i = 0; i < 4; i++)
#pragma unroll
        for (int j = 0; j < 4; j++) acc[i][j] = 0.0f;

    const int rlA = (lane & 7) + 8 * ((lane >> 3) & 1);
    const int cbA = (lane >> 4) * 16;
    const int rlB = lane & 7;
    const int cbB = ((lane >> 3) & 1) * 16;

    proj_load_slab(sb, 0, row0, kbeg, tid);
    CP_COMMIT();

#pragma unroll
    for (int s = 0; s < 4; s++) {
        if (s + 1 < 4) {
            proj_load_slab(sb, (s + 1) & 1, row0, kbeg + (s + 1) * BK, tid);
            CP_COMMIT();
            CP_WAIT(1);
        } else {
            CP_WAIT(0);
        }
        __syncthreads();

        const uint32_t bufb = sb + (s & 1) * PJ_BUF;
        const uint32_t aHi = bufb + PJ_A_HI + (warp * 16) * ROWB;
        const uint32_t aLo = bufb + PJ_A_LO + (warp * 16) * ROWB;
        const uint32_t bHi = bufb + PJ_B_HI;
        const uint32_t bLo = bufb + PJ_B_LO;

#pragma unroll
        for (int ks = 0; ks < 2; ks++) {
            const int ksb = ks * 32;
            uint32_t ah[4], al[4];
            uint32_t ao = rlA * ROWB + ksb + cbA;
            ldsm_x4(ah[0], ah[1], ah[2], ah[3], aHi + ao);
            ldsm_x4(al[0], al[1], al[2], al[3], aLo + ao);
            uint32_t bh[4][2], bl[4][2];
#pragma unroll
            for (int nf = 0; nf < 4; nf++) {
                uint32_t bo = (nf * 8 + rlB) * ROWB + ksb + cbB;
                ldsm_x2(bh[nf][0], bh[nf][1], bHi + bo);
                ldsm_x2(bl[nf][0], bl[nf][1], bLo + bo);
            }
#pragma unroll
            for (int nf = 0; nf < 4; nf++) {
                float* c = acc[nf];
                mma_bf16(c[0], c[1], c[2], c[3], ah[0], ah[1], ah[2], ah[3],
                         bh[nf][0], bh[nf][1]);
                mma_bf16(c[0], c[1], c[2], c[3], ah[0], ah[1], ah[2], ah[3],
                         bl[nf][0], bl[nf][1]);
                mma_bf16(c[0], c[1], c[2], c[3], al[0], al[1], al[2], al[3],
                         bh[nf][0], bh[nf][1]);
            }
        }
        __syncthreads();
    }

    // partial store in interleaved layout
    const int g   = lane >> 2;
    const int tig = lane & 3;
    float* dst = g_BCp + kseg * (M_TOT * 2 * ST);
#pragma unroll
    for (int nf = 0; nf < 4; nf++) {
        const int cc  = nf * 8 + tig * 2;      // even, 0..30
        const int isC = (cc >= 16);
        const int n   = cc & 15;
        const int r0r = row0 + warp * 16 + g;
        float* c = acc[nf];
        *(float2*)&dst[(r0r * 8 + (n >> 1)) * 4 + isC * 2]       = make_float2(c[0], c[1]);
        *(float2*)&dst[((r0r + 8) * 8 + (n >> 1)) * 4 + isC * 2] = make_float2(c[2], c[3]);
    }
}

// Reduce partials + bias into g_BC (interleaved layout).
__global__ __launch_bounds__(256) void proj_reduce_kernel(
    const float* __restrict__ bb, const float* __restrict__ bc)
{
    const int g = blockIdx.x * 256 + threadIdx.x;   // over M_TOT*8 float4s
    const int s = g & 7;
    const float4* p = (const float4*)g_BCp;
    float4 v = p[g];
#pragma unroll
    for (int k = 1; k < PKSEG; k++) {
        float4 w = p[k * (M_TOT * 8) + g];
        v.x += w.x; v.y += w.y; v.z += w.z; v.w += w.w;
    }
    v.x += bb[2 * s];
    v.y += bb[2 * s + 1];
    v.z += bc[2 * s];
    v.w += bc[2 * s + 1];
    ((float4*)g_BC)[g] = v;
}

// =================================================================================
// Kernel 3a / 3c: chunk-local scan, 1 thread per channel d, 16 states in registers.
// Block = 256 d's; grid = B_SZ * CHUNKS * (DM/256) = 512.
// =================================================================================
template<bool FINAL>
__global__ __launch_bounds__(256) void scan_chunk_kernel(
    const float* __restrict__ x,
    const float* __restrict__ A_log,
    const float* __restrict__ D_skip,
    float* __restrict__ out)
{
    __shared__ float4 sbc[CLEN * 8];   // 8 KB: (B0,B1,C0,C1) per state-pair per t

    const int tid = threadIdx.x;
    const int db  = blockIdx.x & 3;
    const int c   = (blockIdx.x >> 2) & (CHUNKS - 1);
    const int b   = blockIdx.x >> 7;
    const int d   = db * 256 + tid;
    const int rowbase = b * SEQ + c * CLEN;

    // stage BC chunk into smem (512 float4s, 2 per thread)
    {
        const float4* src = (const float4*)g_BC + rowbase * 8;
        sbc[tid]       = src[tid];
        sbc[tid + 256] = src[tid + 256];
    }

    float A[16];
#pragma unroll
    for (int n = 0; n < 16; n += 4) {
        float4 v = *(const float4*)&A_log[d * ST + n];
        A[n]     = -expf(v.x);
        A[n + 1] = -expf(v.y);
        A[n + 2] = -expf(v.z);
        A[n + 3] = -expf(v.w);
    }

    const int sidx = ((b * CHUNKS + c) * DM + d) * ST;
    float h[16];
    float Dsk = 0.0f, dts = 0.0f;
    if (FINAL) {
#pragma unroll
        for (int n = 0; n < 16; n += 4) {
            float4 v = *(const float4*)&g_hinit[sidx + n];
            h[n] = v.x; h[n + 1] = v.y; h[n + 2] = v.z; h[n + 3] = v.w;
        }
        Dsk = D_skip[d];
    } else {
#pragma unroll
        for (int n = 0; n < 16; n++) h[n] = 0.0f;
    }
    __syncthreads();

    const float* dp = g_delta + rowbase * DM + d;
    const float* xp = x       + rowbase * DM + d;
    float*       op = out     + rowbase * DM + d;

#pragma unroll 2
    for (int t = 0; t < CLEN; t++) {
        float dt = dp[t * DM];
        float xv = xp[t * DM];
        float dx = dt * xv;
        float y  = 0.0f;
#pragma unroll
        for (int s = 0; s < 8; s++) {
            float4 bcv = sbc[t * 8 + s];
            float e0 = __expf(dt * A[2 * s]);
            float e1 = __expf(dt * A[2 * s + 1]);
            h[2 * s]     = fmaf(e0, h[2 * s],     dx * bcv.x);
            h[2 * s + 1] = fmaf(e1, h[2 * s + 1], dx * bcv.y);
            if (FINAL) {
                y = fmaf(h[2 * s], bcv.z, y);
                y = fmaf(h[2 * s + 1], bcv.w, y);
            }
        }
        if (FINAL) op[t * DM] = fmaf(xv, Dsk, y);
        else       dts += dt;
    }

    if (!FINAL) {
#pragma unroll
        for (int n = 0; n < 16; n += 4)
            *(float4*)&g_f[sidx + n] = make_float4(h[n], h[n + 1], h[n + 2], h[n + 3]);
        g_dtsum[(b * CHUNKS + c) * DM + d] = dts;
    }
}

// =================================================================================
// Kernel 3b: sequential combine across chunks.
// =================================================================================
__global__ __launch_bounds__(256) void scan_combine_kernel(
    const float* __restrict__ A_log)
{
    const int tid = blockIdx.x * blockDim.x + threadIdx.x;
    const int n = tid & 15;
    const int d = (tid >> 4) & (DM - 1);
    const int b = tid >> 14;

    const float A = -expf(A_log[d * ST + n]);
    float H = 0.0f;
#pragma unroll
    for (int c = 0; c < CHUNKS; c++) {
        const int base = (b * CHUNKS + c) * DM + d;
        g_hinit[base * ST + n] = H;
        float P = __expf(A * g_dtsum[base]);
        H = fmaf(P, H, g_f[base * ST + n]);
    }
}

// =================================================================================
// launch
// =================================================================================
extern "C" void kernel_launch(void* const* d_in, const int* in_sizes, int n_in,
                              void* d_out, int out_size)
{
    const float* x      = (const float*)d_in[0];
    const float* A_log  = (const float*)d_in[1];
    const float* D_skip = (const float*)d_in[2];
    const float* Wd     = (const float*)d_in[3];
    const float* bd     = (const float*)d_in[4];
    const float* Wb     = (const float*)d_in[5];
    const float* bb     = (const float*)d_in[6];
    const float* Wc     = (const float*)d_in[7];
    const float* bc     = (const float*)d_in[8];
    float* out = (float*)d_out;

    cudaFuncSetAttribute(gemm_delta_mma, cudaFuncAttributeMaxDynamicSharedMemorySize, GS_TOTAL);
    cudaFuncSetAttribute(proj_mma_kernel, cudaFuncAttributeMaxDynamicSharedMemorySize, PJ_TOTAL);

    convert_x_kernel<<<(M_TOT * DM / 4) / 256, 256>>>(x);
    {
        dim3 tgrid(DM / 32, DM / 32);
        transpose_w_kernel<<<tgrid, 256>>>(Wd);
    }
    transpose_wbc_kernel<<<(32 * DM) / 256, 256>>>(Wb, Wc);
    {
        dim3 grid(DM / 128, M_TOT / 128);   // (8, 64)
        gemm_delta_mma<<<grid, 256, GS_TOTAL>>>(bd);
    }
    {
        dim3 pgrid(M_TOT / 128, PKSEG);     // (64, 8)
        proj_mma_kernel<<<pgrid, 256, PJ_TOTAL>>>();
    }
    proj_reduce_kernel<<<(M_TOT * 8) / 256, 256>>>(bb, bc);

    const int scan_grid = B_SZ * CHUNKS * (DM / 256);   // 512
    scan_chunk_kernel<false><<<scan_grid, 256>>>(x, A_log, D_skip, out);
    scan_combine_kernel<<<(B_SZ * DM * ST) / 256, 256>>>(A_log);
    scan_chunk_kernel<true><<<scan_grid, 256>>>(x, A_log, D_skip, out);
}

// round 9
// speedup vs baseline: 1.3899x; 1.0702x over previous
#include <cuda_runtime.h>
#include <cuda_bf16.h>
#include <math.h>
#include <stdint.h>

#define B_SZ   4
#define SEQ    2048
#define DM     1024
#define ST     16
#define M_TOT  (B_SZ * SEQ)   // 8192 rows
#define CHUNKS 32
#define CLEN   (SEQ / CHUNKS) // 64
#define PKSEG  8

// ---------------- scratch (static device globals; no allocation) ----------------
__device__ float g_delta[M_TOT * DM];              // 32 MB
__device__ float g_BC[M_TOT * 2 * ST];             // 1 MB
__device__ float g_BCp[PKSEG * M_TOT * 2 * ST];    // 8 MB partials
__device__ float g_f[B_SZ * CHUNKS * DM * ST];     // 8 MB
__device__ float g_hinit[B_SZ * CHUNKS * DM * ST]; // 8 MB
__device__ float g_dtsum[B_SZ * CHUNKS * DM];      // 512 KB
__device__ __nv_bfloat16 g_xhi[M_TOT * DM];        // 16 MB
__device__ __nv_bfloat16 g_xlo[M_TOT * DM];        // 16 MB
__device__ __nv_bfloat16 g_wthi[DM * DM];          // 2 MB  (n,k)-major
__device__ __nv_bfloat16 g_wtlo[DM * DM];          // 2 MB
__device__ __nv_bfloat16 g_wbchi[32 * DM];         // 64 KB (n,k)-major [Wb;Wc]^T
__device__ __nv_bfloat16 g_wbclo[32 * DM];         // 64 KB

// ---------------- helpers ----------------
__device__ __forceinline__ float softplus_f(float z) {
    return fmaxf(z, 0.0f) + log1pf(expf(-fabsf(z)));
}
__device__ __forceinline__ uint32_t smem_u32(const void* p) {
    uint32_t a;
    asm("{ .reg .u64 t; cvta.to.shared.u64 t, %1; cvt.u32.u64 %0, t; }" : "=r"(a) : "l"(p));
    return a;
}

#define CP_ASYNC16(dst, src) \
    asm volatile("cp.async.cg.shared.global [%0], [%1], 16;" :: "r"(dst), "l"(src))
#define CP_COMMIT()  asm volatile("cp.async.commit_group;" ::: "memory")
#define CP_WAIT(N)   asm volatile("cp.async.wait_group %0;" :: "n"(N) : "memory")

__device__ __forceinline__ void ldsm_x4(uint32_t& r0, uint32_t& r1, uint32_t& r2, uint32_t& r3,
                                        uint32_t addr) {
    asm volatile("ldmatrix.sync.aligned.m8n8.x4.shared.b16 {%0,%1,%2,%3}, [%4];"
                 : "=r"(r0), "=r"(r1), "=r"(r2), "=r"(r3) : "r"(addr));
}
__device__ __forceinline__ void ldsm_x2(uint32_t& r0, uint32_t& r1, uint32_t addr) {
    asm volatile("ldmatrix.sync.aligned.m8n8.x2.shared.b16 {%0,%1}, [%2];"
                 : "=r"(r0), "=r"(r1) : "r"(addr));
}
__device__ __forceinline__ void mma_bf16(float& c0, float& c1, float& c2, float& c3,
                                         uint32_t a0, uint32_t a1, uint32_t a2, uint32_t a3,
                                         uint32_t b0, uint32_t b1) {
    asm volatile(
        "mma.sync.aligned.m16n8k16.row.col.f32.bf16.bf16.f32 "
        "{%0,%1,%2,%3}, {%4,%5,%6,%7}, {%8,%9}, {%0,%1,%2,%3};"
        : "+f"(c0), "+f"(c1), "+f"(c2), "+f"(c3)
        : "r"(a0), "r"(a1), "r"(a2), "r"(a3), "r"(b0), "r"(b1));
}

// =================================================================================
// Kernel 0a: convert x -> bf16 hi/lo
// =================================================================================
__global__ __launch_bounds__(256) void convert_x_kernel(const float* __restrict__ x)
{
    const int i = blockIdx.x * 256 + threadIdx.x;
    float4 v = ((const float4*)x)[i];
    __nv_bfloat16 hx = __float2bfloat16_rn(v.x);
    __nv_bfloat16 hy = __float2bfloat16_rn(v.y);
    __nv_bfloat16 hz = __float2bfloat16_rn(v.z);
    __nv_bfloat16 hw = __float2bfloat16_rn(v.w);
    __nv_bfloat162* phi = (__nv_bfloat162*)g_xhi;
    __nv_bfloat162* plo = (__nv_bfloat162*)g_xlo;
    phi[i * 2 + 0] = __nv_bfloat162(hx, hy);
    phi[i * 2 + 1] = __nv_bfloat162(hz, hw);
    plo[i * 2 + 0] = __nv_bfloat162(__float2bfloat16_rn(v.x - __bfloat162float(hx)),
                                    __float2bfloat16_rn(v.y - __bfloat162float(hy)));
    plo[i * 2 + 1] = __nv_bfloat162(__float2bfloat16_rn(v.z - __bfloat162float(hz)),
                                    __float2bfloat16_rn(v.w - __bfloat162float(hw)));
}

// =================================================================================
// Kernel 0b: transpose+convert Wd -> Wt_hi/lo ((n,k)-major bf16)
// =================================================================================
__global__ __launch_bounds__(256) void transpose_w_kernel(const float* __restrict__ Wd)
{
    __shared__ float tile[32][33];
    const int x0 = blockIdx.x * 32;
    const int y0 = blockIdx.y * 32;
    const int tx = threadIdx.x & 31;
    const int ty = threadIdx.x >> 5;
#pragma unroll
    for (int i = 0; i < 32; i += 8)
        tile[ty + i][tx] = Wd[(y0 + ty + i) * DM + x0 + tx];
    __syncthreads();
#pragma unroll
    for (int i = 0; i < 32; i += 8) {
        float v = tile[tx][ty + i];
        __nv_bfloat16 h = __float2bfloat16_rn(v);
        g_wthi[(x0 + ty + i) * DM + y0 + tx] = h;
        g_wtlo[(x0 + ty + i) * DM + y0 + tx] = __float2bfloat16_rn(v - __bfloat162float(h));
    }
}

// =================================================================================
// Kernel 0c: transpose+convert [Wb | Wc] -> g_wbc hi/lo (32 x 1024, (n,k)-major)
// =================================================================================
__global__ __launch_bounds__(256) void transpose_wbc_kernel(
    const float* __restrict__ Wb, const float* __restrict__ Wc)
{
    const int idx = blockIdx.x * 256 + threadIdx.x;   // 0..32767
    const int n = idx >> 10;
    const int k = idx & (DM - 1);
    float v = (n < 16) ? Wb[k * ST + n] : Wc[k * ST + (n - 16)];
    __nv_bfloat16 h = __float2bfloat16_rn(v);
    g_wbchi[n * DM + k] = h;
    g_wbclo[n * DM + k] = __float2bfloat16_rn(v - __bfloat162float(h));
}

// =================================================================================
// Kernel 1: delta = softplus(x @ Wd + bd) via mma.sync bf16 3-term split.
// __launch_bounds__(256, 2): regs capped at 128 so 2 CTAs/SM co-reside.
// Double-buffered cp.async; BOTH barriers per slab are required (the loop-end
// barrier prevents iteration s+1's prefetch from overwriting buffer s&1 while
// slower warps still read it).
// =================================================================================
#define ROWB   80
#define T_A_HI 0
#define T_A_LO 10240
#define T_B_HI 20480
#define T_B_LO 30720
#define BUFS   40960
#define GS_TOTAL (2 * BUFS)  // 81920
#define BK     32
#define NSLAB  (DM / BK)     // 32

__device__ __forceinline__ void gemm_load_slab(uint32_t sb, int buf, int row0, int col0,
                                               int k0, int tid)
{
    const uint32_t base = sb + buf * BUFS;
#pragma unroll
    for (int t = 0; t < 2; t++) {
        int op  = tid + t * 256;
        int row = op >> 2;
        int seg = op & 3;
        uint32_t doff = row * ROWB + seg * 16;
        CP_ASYNC16(base + T_A_HI + doff, &g_xhi[(row0 + row) * DM + k0 + seg * 8]);
        CP_ASYNC16(base + T_A_LO + doff, &g_xlo[(row0 + row) * DM + k0 + seg * 8]);
        CP_ASYNC16(base + T_B_HI + doff, &g_wthi[(col0 + row) * DM + k0 + seg * 8]);
        CP_ASYNC16(base + T_B_LO + doff, &g_wtlo[(col0 + row) * DM + k0 + seg * 8]);
    }
}

__global__ __launch_bounds__(256, 2) void gemm_delta_mma(const float* __restrict__ bd)
{
    extern __shared__ char smem[];
    const uint32_t sb = smem_u32(smem);
    const int tid  = threadIdx.x;
    const int lane = tid & 31;
    const int warp = tid >> 5;
    const int wm   = warp & 1;
    const int wn   = warp >> 1;
    const int row0 = blockIdx.y * 128;
    const int col0 = blockIdx.x * 128;

    float acc[4][4][4];
#pragma unroll
    for (int i = 0; i < 4; i++)
#pragma unroll
        for (int j = 0; j < 4; j++)
#pragma unroll
            for (int k = 0; k < 4; k++) acc[i][j][k] = 0.0f;

    const int rlA = (lane & 7) + 8 * ((lane >> 3) & 1);
    const int cbA = (lane >> 4) * 16;
    const int rlB = lane & 7;
    const int cbB = ((lane >> 3) & 1) * 16;

    gemm_load_slab(sb, 0, row0, col0, 0, tid);
    CP_COMMIT();

    for (int s = 0; s < NSLAB; s++) {
        if (s + 1 < NSLAB) {
            gemm_load_slab(sb, (s + 1) & 1, row0, col0, (s + 1) * BK, tid);
            CP_COMMIT();
            CP_WAIT(1);
        } else {
            CP_WAIT(0);
        }
        __syncthreads();

        const uint32_t bufb = sb + (s & 1) * BUFS;
        const uint32_t aHi = bufb + T_A_HI + (wm * 64) * ROWB;
        const uint32_t aLo = bufb + T_A_LO + (wm * 64) * ROWB;
        const uint32_t bHi = bufb + T_B_HI + (wn * 32) * ROWB;
        const uint32_t bLo = bufb + T_B_LO + (wn * 32) * ROWB;

#pragma unroll
        for (int ks = 0; ks < 2; ks++) {
            const int ksb = ks * 32;
            uint32_t ah[4][4], al[4][4];
#pragma unroll
            for (int mf = 0; mf < 4; mf++) {
                uint32_t ao = (mf * 16 + rlA) * ROWB + ksb + cbA;
                ldsm_x4(ah[mf][0], ah[mf][1], ah[mf][2], ah[mf][3], aHi + ao);
                ldsm_x4(al[mf][0], al[mf][1], al[mf][2], al[mf][3], aLo + ao);
            }
            uint32_t bh[4][2], bl[4][2];
#pragma unroll
            for (int nf = 0; nf < 4; nf++) {
                uint32_t bo = (nf * 8 + rlB) * ROWB + ksb + cbB;
                ldsm_x2(bh[nf][0], bh[nf][1], bHi + bo);
                ldsm_x2(bl[nf][0], bl[nf][1], bLo + bo);
            }
#pragma unroll
            for (int mf = 0; mf < 4; mf++)
#pragma unroll
                for (int nf = 0; nf < 4; nf++) {
                    float* c = acc[mf][nf];
                    mma_bf16(c[0], c[1], c[2], c[3],
                             ah[mf][0], ah[mf][1], ah[mf][2], ah[mf][3],
                             bh[nf][0], bh[nf][1]);
                    mma_bf16(c[0], c[1], c[2], c[3],
                             ah[mf][0], ah[mf][1], ah[mf][2], ah[mf][3],
                             bl[nf][0], bl[nf][1]);
                    mma_bf16(c[0], c[1], c[2], c[3],
                             al[mf][0], al[mf][1], al[mf][2], al[mf][3],
                             bh[nf][0], bh[nf][1]);
                }
        }
        __syncthreads();
    }

    const int g   = lane >> 2;
    const int tig = lane & 3;
#pragma unroll
    for (int nf = 0; nf < 4; nf++) {
        const int col = col0 + wn * 32 + nf * 8 + tig * 2;
        const float b0v = bd[col];
        const float b1v = bd[col + 1];
#pragma unroll
        for (int mf = 0; mf < 4; mf++) {
            const int row = row0 + wm * 64 + mf * 16 + g;
            float* c = acc[mf][nf];
            float2 v0, v1;
            v0.x = softplus_f(c[0] + b0v);
            v0.y = softplus_f(c[1] + b1v);
            v1.x = softplus_f(c[2] + b0v);
            v1.y = softplus_f(c[3] + b1v);
            *(float2*)&g_delta[row * DM + col]       = v0;
            *(float2*)&g_delta[(row + 8) * DM + col] = v1;
        }
    }
}

// =================================================================================
// Kernel 2: B/C projection via mma.sync bf16 3-term split, split-K x8.
// =================================================================================
#define PJ_A_HI 0
#define PJ_A_LO 10240
#define PJ_B_HI 20480
#define PJ_B_LO 23040
#define PJ_BUF  25600
#define PJ_TOTAL (2 * PJ_BUF)  // 51200

__device__ __forceinline__ void proj_load_slab(uint32_t sb, int buf, int row0, int k0, int tid)
{
    const uint32_t base = sb + buf * PJ_BUF;
#pragma unroll
    for (int t = 0; t < 2; t++) {
        int op  = tid + t * 256;
        int row = op >> 2;
        int seg = op & 3;
        uint32_t doff = row * ROWB + seg * 16;
        CP_ASYNC16(base + PJ_A_HI + doff, &g_xhi[(row0 + row) * DM + k0 + seg * 8]);
        CP_ASYNC16(base + PJ_A_LO + doff, &g_xlo[(row0 + row) * DM + k0 + seg * 8]);
    }
    {
        int row = (tid & 127) >> 2;      // 0..31
        int seg = tid & 3;
        uint32_t doff = row * ROWB + seg * 16;
        if (tid < 128)
            CP_ASYNC16(base + PJ_B_HI + doff, &g_wbchi[row * DM + k0 + seg * 8]);
        else
            CP_ASYNC16(base + PJ_B_LO + doff, &g_wbclo[row * DM + k0 + seg * 8]);
    }
}

__global__ __launch_bounds__(256, 2) void proj_mma_kernel()
{
    extern __shared__ char smem[];
    const uint32_t sb = smem_u32(smem);
    const int tid  = threadIdx.x;
    const int lane = tid & 31;
    const int warp = tid >> 5;
    const int row0 = blockIdx.x * 128;
    const int kseg = blockIdx.y;
    const int kbeg = kseg * (DM / PKSEG);   // 128-wide K range

    float acc[4][4];
#pragma unroll
    for (int i = 0; i < 4; i++)
#pragma unroll
        for (int j = 0; j < 4; j++) acc[i][j] = 0.0f;

    const int rlA = (lane & 7) + 8 * ((lane >> 3) & 1);
    const int cbA = (lane >> 4) * 16;
    const int rlB = lane & 7;
    const int cbB = ((lane >> 3) & 1) * 16;

    proj_load_slab(sb, 0, row0, kbeg, tid);
    CP_COMMIT();

#pragma unroll
    for (int s = 0; s < 4; s++) {
        if (s + 1 < 4) {
            proj_load_slab(sb, (s + 1) & 1, row0, kbeg + (s + 1) * BK, tid);
            CP_COMMIT();
            CP_WAIT(1);
        } else {
            CP_WAIT(0);
        }
        __syncthreads();

        const uint32_t bufb = sb + (s & 1) * PJ_BUF;
        const uint32_t aHi = bufb + PJ_A_HI + (warp * 16) * ROWB;
        const uint32_t aLo = bufb + PJ_A_LO + (warp * 16) * ROWB;
        const uint32_t bHi = bufb + PJ_B_HI;
        const uint32_t bLo = bufb + PJ_B_LO;

#pragma unroll
        for (int ks = 0; ks < 2; ks++) {
            const int ksb = ks * 32;
            uint32_t ah[4], al[4];
            uint32_t ao = rlA * ROWB + ksb + cbA;
            ldsm_x4(ah[0], ah[1], ah[2], ah[3], aHi + ao);
            ldsm_x4(al[0], al[1], al[2], al[3], aLo + ao);
            uint32_t bh[4][2], bl[4][2];
#pragma unroll
            for (int nf = 0; nf < 4; nf++) {
                uint32_t bo = (nf * 8 + rlB) * ROWB + ksb + cbB;
                ldsm_x2(bh[nf][0], bh[nf][1], bHi + bo);
                ldsm_x2(bl[nf][0], bl[nf][1], bLo + bo);
            }
#pragma unroll
            for (int nf = 0; nf < 4; nf++) {
                float* c = acc[nf];
                mma_bf16(c[0], c[1], c[2], c[3], ah[0], ah[1], ah[2], ah[3],
                         bh[nf][0], bh[nf][1]);
                mma_bf16(c[0], c[1], c[2], c[3], ah[0], ah[1], ah[2], ah[3],
                         bl[nf][0], bl[nf][1]);
                mma_bf16(c[0], c[1], c[2], c[3], al[0], al[1], al[2], al[3],
                         bh[nf][0], bh[nf][1]);
            }
        }
        __syncthreads();
    }

    // partial store in interleaved layout
    const int g   = lane >> 2;
    const int tig = lane & 3;
    float* dst = g_BCp + kseg * (M_TOT * 2 * ST);
#pragma unroll
    for (int nf = 0; nf < 4; nf++) {
        const int cc  = nf * 8 + tig * 2;      // even, 0..30
        const int isC = (cc >= 16);
        const int n   = cc & 15;
        const int r0r = row0 + warp * 16 + g;
        float* c = acc[nf];
        *(float2*)&dst[(r0r * 8 + (n >> 1)) * 4 + isC * 2]       = make_float2(c[0], c[1]);
        *(float2*)&dst[((r0r + 8) * 8 + (n >> 1)) * 4 + isC * 2] = make_float2(c[2], c[3]);
    }
}

// Reduce partials + bias into g_BC (interleaved layout).
__global__ __launch_bounds__(256) void proj_reduce_kernel(
    const float* __restrict__ bb, const float* __restrict__ bc)
{
    const int g = blockIdx.x * 256 + threadIdx.x;   // over M_TOT*8 float4s
    const int s = g & 7;
    const float4* p = (const float4*)g_BCp;
    float4 v = p[g];
#pragma unroll
    for (int k = 1; k < PKSEG; k++) {
        float4 w = p[k * (M_TOT * 8) + g];
        v.x += w.x; v.y += w.y; v.z += w.z; v.w += w.w;
    }
    v.x += bb[2 * s];
    v.y += bb[2 * s + 1];
    v.z += bc[2 * s];
    v.w += bc[2 * s + 1];
    ((float4*)g_BC)[g] = v;
}

// =================================================================================
// Kernel 3a / 3c: chunk-local scan, 1 thread per channel d, 16 states in registers.
// =================================================================================
template<bool FINAL>
__global__ __launch_bounds__(256) void scan_chunk_kernel(
    const float* __restrict__ x,
    const float* __restrict__ A_log,
    const float* __restrict__ D_skip,
    float* __restrict__ out)
{
    __shared__ float4 sbc[CLEN * 8];   // 8 KB

    const int tid = threadIdx.x;
    const int db  = blockIdx.x & 3;
    const int c   = (blockIdx.x >> 2) & (CHUNKS - 1);
    const int b   = blockIdx.x >> 7;
    const int d   = db * 256 + tid;
    const int rowbase = b * SEQ + c * CLEN;

    {
        const float4* src = (const float4*)g_BC + rowbase * 8;
        sbc[tid]       = src[tid];
        sbc[tid + 256] = src[tid + 256];
    }

    float A[16];
#pragma unroll
    for (int n = 0; n < 16; n += 4) {
        float4 v = *(const float4*)&A_log[d * ST + n];
        A[n]     = -expf(v.x);
        A[n + 1] = -expf(v.y);
        A[n + 2] = -expf(v.z);
        A[n + 3] = -expf(v.w);
    }

    const int sidx = ((b * CHUNKS + c) * DM + d) * ST;
    float h[16];
    float Dsk = 0.0f, dts = 0.0f;
    if (FINAL) {
#pragma unroll
        for (int n = 0; n < 16; n += 4) {
            float4 v = *(const float4*)&g_hinit[sidx + n];
            h[n] = v.x; h[n + 1] = v.y; h[n + 2] = v.z; h[n + 3] = v.w;
        }
        Dsk = D_skip[d];
    } else {
#pragma unroll
        for (int n = 0; n < 16; n++) h[n] = 0.0f;
    }
    __syncthreads();

    const float* dp = g_delta + rowbase * DM + d;
    const float* xp = x       + rowbase * DM + d;
    float*       op = out     + rowbase * DM + d;

#pragma unroll 2
    for (int t = 0; t < CLEN; t++) {
        float dt = dp[t * DM];
        float xv = xp[t * DM];
        float dx = dt * xv;
        float y  = 0.0f;
#pragma unroll
        for (int s = 0; s < 8; s++) {
            float4 bcv = sbc[t * 8 + s];
            float e0 = __expf(dt * A[2 * s]);
            float e1 = __expf(dt * A[2 * s + 1]);
            h[2 * s]     = fmaf(e0, h[2 * s],     dx * bcv.x);
            h[2 * s + 1] = fmaf(e1, h[2 * s + 1], dx * bcv.y);
            if (FINAL) {
                y = fmaf(h[2 * s], bcv.z, y);
                y = fmaf(h[2 * s + 1], bcv.w, y);
            }
        }
        if (FINAL) op[t * DM] = fmaf(xv, Dsk, y);
        else       dts += dt;
    }

    if (!FINAL) {
#pragma unroll
        for (int n = 0; n < 16; n += 4)
            *(float4*)&g_f[sidx + n] = make_float4(h[n], h[n + 1], h[n + 2], h[n + 3]);
        g_dtsum[(b * CHUNKS + c) * DM + d] = dts;
    }
}

// =================================================================================
// Kernel 3b: sequential combine across chunks.
// =================================================================================
__global__ __launch_bounds__(256) void scan_combine_kernel(
    const float* __restrict__ A_log)
{
    const int tid = blockIdx.x * blockDim.x + threadIdx.x;
    const int n = tid & 15;
    const int d = (tid >> 4) & (DM - 1);
    const int b = tid >> 14;

    const float A = -expf(A_log[d * ST + n]);
    float H = 0.0f;
#pragma unroll
    for (int c = 0; c < CHUNKS; c++) {
        const int base = (b * CHUNKS + c) * DM + d;
        g_hinit[base * ST + n] = H;
        float P = __expf(A * g_dtsum[base]);
        H = fmaf(P, H, g_f[base * ST + n]);
    }
}

// =================================================================================
// launch
// =================================================================================
extern "C" void kernel_launch(void* const* d_in, const int* in_sizes, int n_in,
                              void* d_out, int out_size)
{
    const float* x      = (const float*)d_in[0];
    const float* A_log  = (const float*)d_in[1];
    const float* D_skip = (const float*)d_in[2];
    const float* Wd     = (const float*)d_in[3];
    const float* bd     = (const float*)d_in[4];
    const float* Wb     = (const float*)d_in[5];
    const float* bb     = (const float*)d_in[6];
    const float* Wc     = (const float*)d_in[7];
    const float* bc     = (const float*)d_in[8];
    float* out = (float*)d_out;

    cudaFuncSetAttribute(gemm_delta_mma, cudaFuncAttributeMaxDynamicSharedMemorySize, GS_TOTAL);
    cudaFuncSetAttribute(proj_mma_kernel, cudaFuncAttributeMaxDynamicSharedMemorySize, PJ_TOTAL);

    convert_x_kernel<<<(M_TOT * DM / 4) / 256, 256>>>(x);
    {
        dim3 tgrid(DM / 32, DM / 32);
        transpose_w_kernel<<<tgrid, 256>>>(Wd);
    }
    transpose_wbc_kernel<<<(32 * DM) / 256, 256>>>(Wb, Wc);
    {
        dim3 grid(DM / 128, M_TOT / 128);   // (8, 64)
        gemm_delta_mma<<<grid, 256, GS_TOTAL>>>(bd);
    }
    {
        dim3 pgrid(M_TOT / 128, PKSEG);     // (64, 8)
        proj_mma_kernel<<<pgrid, 256, PJ_TOTAL>>>();
    }
    proj_reduce_kernel<<<(M_TOT * 8) / 256, 256>>>(bb, bc);

    const int scan_grid = B_SZ * CHUNKS * (DM / 256);   // 512
    scan_chunk_kernel<false><<<scan_grid, 256>>>(x, A_log, D_skip, out);
    scan_combine_kernel<<<(B_SZ * DM * ST) / 256, 256>>>(A_log);
    scan_chunk_kernel<true><<<scan_grid, 256>>>(x, A_log, D_skip, out);
}

// round 10
// speedup vs baseline: 1.4831x; 1.0671x over previous
#include <cuda_runtime.h>
#include <cuda_bf16.h>
#include <math.h>
#include <stdint.h>

#define B_SZ   4
#define SEQ    2048
#define DM     1024
#define ST     16
#define M_TOT  (B_SZ * SEQ)   // 8192 rows
#define CHUNKS 32
#define CLEN   (SEQ / CHUNKS) // 64
#define PKSEG  8

// ---------------- scratch (static device globals; no allocation) ----------------
__device__ float g_delta[M_TOT * DM];              // 32 MB
__device__ float g_BC[M_TOT * 2 * ST];             // 1 MB
__device__ float g_BCp[PKSEG * M_TOT * 2 * ST];    // 8 MB partials
__device__ float g_f[B_SZ * CHUNKS * DM * ST];     // 8 MB
__device__ float g_hinit[B_SZ * CHUNKS * DM * ST]; // 8 MB
__device__ float g_dtsum[B_SZ * CHUNKS * DM];      // 512 KB
__device__ __nv_bfloat16 g_xhi[M_TOT * DM];        // 16 MB
__device__ __nv_bfloat16 g_xlo[M_TOT * DM];        // 16 MB
__device__ __nv_bfloat16 g_wthi[DM * DM];          // 2 MB  (n,k)-major
__device__ __nv_bfloat16 g_wtlo[DM * DM];          // 2 MB
__device__ __nv_bfloat16 g_wbchi[32 * DM];         // 64 KB (n,k)-major [Wb;Wc]^T
__device__ __nv_bfloat16 g_wbclo[32 * DM];         // 64 KB

// ---------------- helpers ----------------
__device__ __forceinline__ float softplus_f(float z) {
    return fmaxf(z, 0.0f) + log1pf(expf(-fabsf(z)));
}
__device__ __forceinline__ uint32_t smem_u32(const void* p) {
    uint32_t a;
    asm("{ .reg .u64 t; cvta.to.shared.u64 t, %1; cvt.u32.u64 %0, t; }" : "=r"(a) : "l"(p));
    return a;
}

#define CP_ASYNC16(dst, src) \
    asm volatile("cp.async.cg.shared.global [%0], [%1], 16;" :: "r"(dst), "l"(src))
#define CP_COMMIT()  asm volatile("cp.async.commit_group;" ::: "memory")
#define CP_WAIT(N)   asm volatile("cp.async.wait_group %0;" :: "n"(N) : "memory")

__device__ __forceinline__ void ldsm_x4(uint32_t& r0, uint32_t& r1, uint32_t& r2, uint32_t& r3,
                                        uint32_t addr) {
    asm volatile("ldmatrix.sync.aligned.m8n8.x4.shared.b16 {%0,%1,%2,%3}, [%4];"
                 : "=r"(r0), "=r"(r1), "=r"(r2), "=r"(r3) : "r"(addr));
}
__device__ __forceinline__ void ldsm_x2(uint32_t& r0, uint32_t& r1, uint32_t addr) {
    asm volatile("ldmatrix.sync.aligned.m8n8.x2.shared.b16 {%0,%1}, [%2];"
                 : "=r"(r0), "=r"(r1) : "r"(addr));
}
__device__ __forceinline__ void mma_bf16(float& c0, float& c1, float& c2, float& c3,
                                         uint32_t a0, uint32_t a1, uint32_t a2, uint32_t a3,
                                         uint32_t b0, uint32_t b1) {
    asm volatile(
        "mma.sync.aligned.m16n8k16.row.col.f32.bf16.bf16.f32 "
        "{%0,%1,%2,%3}, {%4,%5,%6,%7}, {%8,%9}, {%0,%1,%2,%3};"
        : "+f"(c0), "+f"(c1), "+f"(c2), "+f"(c3)
        : "r"(a0), "r"(a1), "r"(a2), "r"(a3), "r"(b0), "r"(b1));
}

// 64B-row smem swizzle: rows of 4x16B segments; seg' = seg ^ ((row>>1)&3).
// Makes ldmatrix's 8-row access hit 8 distinct 16B banks without padding.
__device__ __forceinline__ uint32_t sw64(uint32_t o) {
    return o ^ (((o >> 7) & 3u) << 4);
}

// =================================================================================
// Kernel 0a: convert x -> bf16 hi/lo
// =================================================================================
__global__ __launch_bounds__(256) void convert_x_kernel(const float* __restrict__ x)
{
    const int i = blockIdx.x * 256 + threadIdx.x;
    float4 v = ((const float4*)x)[i];
    __nv_bfloat16 hx = __float2bfloat16_rn(v.x);
    __nv_bfloat16 hy = __float2bfloat16_rn(v.y);
    __nv_bfloat16 hz = __float2bfloat16_rn(v.z);
    __nv_bfloat16 hw = __float2bfloat16_rn(v.w);
    __nv_bfloat162* phi = (__nv_bfloat162*)g_xhi;
    __nv_bfloat162* plo = (__nv_bfloat162*)g_xlo;
    phi[i * 2 + 0] = __nv_bfloat162(hx, hy);
    phi[i * 2 + 1] = __nv_bfloat162(hz, hw);
    plo[i * 2 + 0] = __nv_bfloat162(__float2bfloat16_rn(v.x - __bfloat162float(hx)),
                                    __float2bfloat16_rn(v.y - __bfloat162float(hy)));
    plo[i * 2 + 1] = __nv_bfloat162(__float2bfloat16_rn(v.z - __bfloat162float(hz)),
                                    __float2bfloat16_rn(v.w - __bfloat162float(hw)));
}

// =================================================================================
// Kernel 0b: transpose+convert Wd -> Wt_hi/lo ((n,k)-major bf16)
// =================================================================================
__global__ __launch_bounds__(256) void transpose_w_kernel(const float* __restrict__ Wd)
{
    __shared__ float tile[32][33];
    const int x0 = blockIdx.x * 32;
    const int y0 = blockIdx.y * 32;
    const int tx = threadIdx.x & 31;
    const int ty = threadIdx.x >> 5;
#pragma unroll
    for (int i = 0; i < 32; i += 8)
        tile[ty + i][tx] = Wd[(y0 + ty + i) * DM + x0 + tx];
    __syncthreads();
#pragma unroll
    for (int i = 0; i < 32; i += 8) {
        float v = tile[tx][ty + i];
        __nv_bfloat16 h = __float2bfloat16_rn(v);
        g_wthi[(x0 + ty + i) * DM + y0 + tx] = h;
        g_wtlo[(x0 + ty + i) * DM + y0 + tx] = __float2bfloat16_rn(v - __bfloat162float(h));
    }
}

// =================================================================================
// Kernel 0c: transpose+convert [Wb | Wc] -> g_wbc hi/lo (32 x 1024, (n,k)-major)
// =================================================================================
__global__ __launch_bounds__(256) void transpose_wbc_kernel(
    const float* __restrict__ Wb, const float* __restrict__ Wc)
{
    const int idx = blockIdx.x * 256 + threadIdx.x;   // 0..32767
    const int n = idx >> 10;
    const int k = idx & (DM - 1);
    float v = (n < 16) ? Wb[k * ST + n] : Wc[k * ST + (n - 16)];
    __nv_bfloat16 h = __float2bfloat16_rn(v);
    g_wbchi[n * DM + k] = h;
    g_wbclo[n * DM + k] = __float2bfloat16_rn(v - __bfloat162float(h));
}

// =================================================================================
// Kernel 1: delta = softplus(x @ Wd + bd) via mma.sync bf16 3-term split.
// 3-stage cp.async ring, swizzled 64B rows (no padding), ONE barrier per slab.
// __launch_bounds__(256, 2): 2 CTAs/SM (2 x 96KB smem = 192KB).
// =================================================================================
#define T_A_HI 0
#define T_A_LO 8192
#define T_B_HI 16384
#define T_B_LO 24576
#define BUFS   32768
#define NSTAGE 3
#define GS_TOTAL (NSTAGE * BUFS)  // 98304
#define BK     32
#define NSLAB  (DM / BK)     // 32

__device__ __forceinline__ void gemm_load_slab(uint32_t sb, int stage, int row0, int col0,
                                               int k0, int tid)
{
    const uint32_t base = sb + stage * BUFS;
#pragma unroll
    for (int t = 0; t < 2; t++) {
        int op  = tid + t * 256;        // 0..511
        int row = op >> 2;              // 0..127
        int seg = op & 3;               // 0..3 (16B each)
        uint32_t doff = sw64((uint32_t)(row * 64 + seg * 16));
        CP_ASYNC16(base + T_A_HI + doff, &g_xhi[(row0 + row) * DM + k0 + seg * 8]);
        CP_ASYNC16(base + T_A_LO + doff, &g_xlo[(row0 + row) * DM + k0 + seg * 8]);
        CP_ASYNC16(base + T_B_HI + doff, &g_wthi[(col0 + row) * DM + k0 + seg * 8]);
        CP_ASYNC16(base + T_B_LO + doff, &g_wtlo[(col0 + row) * DM + k0 + seg * 8]);
    }
}

__global__ __launch_bounds__(256, 2) void gemm_delta_mma(const float* __restrict__ bd)
{
    extern __shared__ char smem[];
    const uint32_t sb = smem_u32(smem);
    const int tid  = threadIdx.x;
    const int lane = tid & 31;
    const int warp = tid >> 5;
    const int wm   = warp & 1;
    const int wn   = warp >> 1;
    const int row0 = blockIdx.y * 128;
    const int col0 = blockIdx.x * 128;

    float acc[4][4][4];
#pragma unroll
    for (int i = 0; i < 4; i++)
#pragma unroll
        for (int j = 0; j < 4; j++)
#pragma unroll
            for (int k = 0; k < 4; k++) acc[i][j][k] = 0.0f;

    const int rlA = (lane & 7) + 8 * ((lane >> 3) & 1);
    const int cA  = (lane >> 4) & 1;        // which 16B seg within k-half
    const int rlB = lane & 7;
    const int cB  = (lane >> 3) & 1;

    // Precompute swizzled ldmatrix offsets for ks=0. ks=1 offset = ks0 ^ 0x20
    // (swizzle seg' bit1 = ks ^ ((row>>2)&1); toggling ks toggles byte-bit 5).
    uint32_t aoff[4], boff[4];
#pragma unroll
    for (int mf = 0; mf < 4; mf++) {
        int row = wm * 64 + mf * 16 + rlA;
        aoff[mf] = sw64((uint32_t)(row * 64 + cA * 16));
    }
#pragma unroll
    for (int nf = 0; nf < 4; nf++) {
        int row = wn * 32 + nf * 8 + rlB;
        boff[nf] = sw64((uint32_t)(row * 64 + cB * 16));
    }

    // prologue: stages 0 and 1
    gemm_load_slab(sb, 0, row0, col0, 0, tid);
    CP_COMMIT();
    gemm_load_slab(sb, 1, row0, col0, BK, tid);
    CP_COMMIT();

    for (int s = 0; s < NSLAB; s++) {
        if (s + 1 < NSLAB) { CP_WAIT(1); } else { CP_WAIT(0); }
        __syncthreads();

        // prefetch slab s+2 into ring stage (s+2)%3 (== stage read in iter s-1;
        // the barrier above ordered all warps past that compute).
        if (s + 2 < NSLAB) {
            gemm_load_slab(sb, (s + 2) % NSTAGE, row0, col0, (s + 2) * BK, tid);
            CP_COMMIT();
        }

        const uint32_t bufb = sb + (s % NSTAGE) * BUFS;
        const uint32_t aHi = bufb + T_A_HI;
        const uint32_t aLo = bufb + T_A_LO;
        const uint32_t bHi = bufb + T_B_HI;
        const uint32_t bLo = bufb + T_B_LO;

#pragma unroll
        for (int ks = 0; ks < 2; ks++) {
            const uint32_t kx = ks ? 0x20u : 0u;
            uint32_t ah[4][4], al[4][4];
#pragma unroll
            for (int mf = 0; mf < 4; mf++) {
                uint32_t ao = aoff[mf] ^ kx;
                ldsm_x4(ah[mf][0], ah[mf][1], ah[mf][2], ah[mf][3], aHi + ao);
                ldsm_x4(al[mf][0], al[mf][1], al[mf][2], al[mf][3], aLo + ao);
            }
            uint32_t bh[4][2], bl[4][2];
#pragma unroll
            for (int nf = 0; nf < 4; nf++) {
                uint32_t bo = boff[nf] ^ kx;
                ldsm_x2(bh[nf][0], bh[nf][1], bHi + bo);
                ldsm_x2(bl[nf][0], bl[nf][1], bLo + bo);
            }
#pragma unroll
            for (int mf = 0; mf < 4; mf++)
#pragma unroll
                for (int nf = 0; nf < 4; nf++) {
                    float* c = acc[mf][nf];
                    mma_bf16(c[0], c[1], c[2], c[3],
                             ah[mf][0], ah[mf][1], ah[mf][2], ah[mf][3],
                             bh[nf][0], bh[nf][1]);
                    mma_bf16(c[0], c[1], c[2], c[3],
                             ah[mf][0], ah[mf][1], ah[mf][2], ah[mf][3],
                             bl[nf][0], bl[nf][1]);
                    mma_bf16(c[0], c[1], c[2], c[3],
                             al[mf][0], al[mf][1], al[mf][2], al[mf][3],
                             bh[nf][0], bh[nf][1]);
                }
        }
    }

    const int g   = lane >> 2;
    const int tig = lane & 3;
#pragma unroll
    for (int nf = 0; nf < 4; nf++) {
        const int col = col0 + wn * 32 + nf * 8 + tig * 2;
        const float b0v = bd[col];
        const float b1v = bd[col + 1];
#pragma unroll
        for (int mf = 0; mf < 4; mf++) {
            const int row = row0 + wm * 64 + mf * 16 + g;
            float* c = acc[mf][nf];
            float2 v0, v1;
            v0.x = softplus_f(c[0] + b0v);
            v0.y = softplus_f(c[1] + b1v);
            v1.x = softplus_f(c[2] + b0v);
            v1.y = softplus_f(c[3] + b1v);
            *(float2*)&g_delta[row * DM + col]       = v0;
            *(float2*)&g_delta[(row + 8) * DM + col] = v1;
        }
    }
}

// =================================================================================
// Kernel 2: B/C projection via mma.sync bf16 3-term split, split-K x8.
// (unchanged from R9: 80B padded rows, 2-stage, 2 barriers)
// =================================================================================
#define ROWB    80
#define PJ_A_HI 0
#define PJ_A_LO 10240
#define PJ_B_HI 20480
#define PJ_B_LO 23040
#define PJ_BUF  25600
#define PJ_TOTAL (2 * PJ_BUF)  // 51200

__device__ __forceinline__ void proj_load_slab(uint32_t sb, int buf, int row0, int k0, int tid)
{
    const uint32_t base = sb + buf * PJ_BUF;
#pragma unroll
    for (int t = 0; t < 2; t++) {
        int op  = tid + t * 256;
        int row = op >> 2;
        int seg = op & 3;
        uint32_t doff = row * ROWB + seg * 16;
        CP_ASYNC16(base + PJ_A_HI + doff, &g_xhi[(row0 + row) * DM + k0 + seg * 8]);
        CP_ASYNC16(base + PJ_A_LO + doff, &g_xlo[(row0 + row) * DM + k0 + seg * 8]);
    }
    {
        int row = (tid & 127) >> 2;      // 0..31
        int seg = tid & 3;
        uint32_t doff = row * ROWB + seg * 16;
        if (tid < 128)
            CP_ASYNC16(base + PJ_B_HI + doff, &g_wbchi[row * DM + k0 + seg * 8]);
        else
            CP_ASYNC16(base + PJ_B_LO + doff, &g_wbclo[row * DM + k0 + seg * 8]);
    }
}

__global__ __launch_bounds__(256, 2) void proj_mma_kernel()
{
    extern __shared__ char smem[];
    const uint32_t sb = smem_u32(smem);
    const int tid  = threadIdx.x;
    const int lane = tid & 31;
    const int warp = tid >> 5;
    const int row0 = blockIdx.x * 128;
    const int kseg = blockIdx.y;
    const int kbeg = kseg * (DM / PKSEG);   // 128-wide K range

    float acc[4][4];
#pragma unroll
    for (int i = 0; i < 4; i++)
#pragma unroll
        for (int j = 0; j < 4; j++) acc[i][j] = 0.0f;

    const int rlA = (lane & 7) + 8 * ((lane >> 3) & 1);
    const int cbA = (lane >> 4) * 16;
    const int rlB = lane & 7;
    const int cbB = ((lane >> 3) & 1) * 16;

    proj_load_slab(sb, 0, row0, kbeg, tid);
    CP_COMMIT();

#pragma unroll
    for (int s = 0; s < 4; s++) {
        if (s + 1 < 4) {
            proj_load_slab(sb, (s + 1) & 1, row0, kbeg + (s + 1) * BK, tid);
            CP_COMMIT();
            CP_WAIT(1);
        } else {
            CP_WAIT(0);
        }
        __syncthreads();

        const uint32_t bufb = sb + (s & 1) * PJ_BUF;
        const uint32_t aHi = bufb + PJ_A_HI + (warp * 16) * ROWB;
        const uint32_t aLo = bufb + PJ_A_LO + (warp * 16) * ROWB;
        const uint32_t bHi = bufb + PJ_B_HI;
        const uint32_t bLo = bufb + PJ_B_LO;

#pragma unroll
        for (int ks = 0; ks < 2; ks++) {
            const int ksb = ks * 32;
            uint32_t ah[4], al[4];
            uint32_t ao = rlA * ROWB + ksb + cbA;
            ldsm_x4(ah[0], ah[1], ah[2], ah[3], aHi + ao);
            ldsm_x4(al[0], al[1], al[2], al[3], aLo + ao);
            uint32_t bh[4][2], bl[4][2];
#pragma unroll
            for (int nf = 0; nf < 4; nf++) {
                uint32_t bo = (nf * 8 + rlB) * ROWB + ksb + cbB;
                ldsm_x2(bh[nf][0], bh[nf][1], bHi + bo);
                ldsm_x2(bl[nf][0], bl[nf][1], bLo + bo);
            }
#pragma unroll
            for (int nf = 0; nf < 4; nf++) {
                float* c = acc[nf];
                mma_bf16(c[0], c[1], c[2], c[3], ah[0], ah[1], ah[2], ah[3],
                         bh[nf][0], bh[nf][1]);
                mma_bf16(c[0], c[1], c[2], c[3], ah[0], ah[1], ah[2], ah[3],
                         bl[nf][0], bl[nf][1]);
                mma_bf16(c[0], c[1], c[2], c[3], al[0], al[1], al[2], al[3],
                         bh[nf][0], bh[nf][1]);
            }
        }
        __syncthreads();
    }

    // partial store in interleaved layout
    const int g   = lane >> 2;
    const int tig = lane & 3;
    float* dst = g_BCp + kseg * (M_TOT * 2 * ST);
#pragma unroll
    for (int nf = 0; nf < 4; nf++) {
        const int cc  = nf * 8 + tig * 2;      // even, 0..30
        const int isC = (cc >= 16);
        const int n   = cc & 15;
        const int r0r = row0 + warp * 16 + g;
        float* c = acc[nf];
        *(float2*)&dst[(r0r * 8 + (n >> 1)) * 4 + isC * 2]       = make_float2(c[0], c[1]);
        *(float2*)&dst[((r0r + 8) * 8 + (n >> 1)) * 4 + isC * 2] = make_float2(c[2], c[3]);
    }
}

// Reduce partials + bias into g_BC (interleaved layout).
__global__ __launch_bounds__(256) void proj_reduce_kernel(
    const float* __restrict__ bb, const float* __restrict__ bc)
{
    const int g = blockIdx.x * 256 + threadIdx.x;   // over M_TOT*8 float4s
    const int s = g & 7;
    const float4* p = (const float4*)g_BCp;
    float4 v = p[g];
#pragma unroll
    for (int k = 1; k < PKSEG; k++) {
        float4 w = p[k * (M_TOT * 8) + g];
        v.x += w.x; v.y += w.y; v.z += w.z; v.w += w.w;
    }
    v.x += bb[2 * s];
    v.y += bb[2 * s + 1];
    v.z += bc[2 * s];
    v.w += bc[2 * s + 1];
    ((float4*)g_BC)[g] = v;
}

// =================================================================================
// Kernel 3a / 3c: chunk-local scan, 1 thread per channel d, 16 states in registers.
// =================================================================================
template<bool FINAL>
__global__ __launch_bounds__(256) void scan_chunk_kernel(
    const float* __restrict__ x,
    const float* __restrict__ A_log,
    const float* __restrict__ D_skip,
    float* __restrict__ out)
{
    __shared__ float4 sbc[CLEN * 8];   // 8 KB

    const int tid = threadIdx.x;
    const int db  = blockIdx.x & 3;
    const int c   = (blockIdx.x >> 2) & (CHUNKS - 1);
    const int b   = blockIdx.x >> 7;
    const int d   = db * 256 + tid;
    const int rowbase = b * SEQ + c * CLEN;

    {
        const float4* src = (const float4*)g_BC + rowbase * 8;
        sbc[tid]       = src[tid];
        sbc[tid + 256] = src[tid + 256];
    }

    float A[16];
#pragma unroll
    for (int n = 0; n < 16; n += 4) {
        float4 v = *(const float4*)&A_log[d * ST + n];
        A[n]     = -expf(v.x);
        A[n + 1] = -expf(v.y);
        A[n + 2] = -expf(v.z);
        A[n + 3] = -expf(v.w);
    }

    const int sidx = ((b * CHUNKS + c) * DM + d) * ST;
    float h[16];
    float Dsk = 0.0f, dts = 0.0f;
    if (FINAL) {
#pragma unroll
        for (int n = 0; n < 16; n += 4) {
            float4 v = *(const float4*)&g_hinit[sidx + n];
            h[n] = v.x; h[n + 1] = v.y; h[n + 2] = v.z; h[n + 3] = v.w;
        }
        Dsk = D_skip[d];
    } else {
#pragma unroll
        for (int n = 0; n < 16; n++) h[n] = 0.0f;
    }
    __syncthreads();

    const float* dp = g_delta + rowbase * DM + d;
    const float* xp = x       + rowbase * DM + d;
    float*       op = out     + rowbase * DM + d;

#pragma unroll 2
    for (int t = 0; t < CLEN; t++) {
        float dt = dp[t * DM];
        float xv = xp[t * DM];
        float dx = dt * xv;
        float y  = 0.0f;
#pragma unroll
        for (int s = 0; s < 8; s++) {
            float4 bcv = sbc[t * 8 + s];
            float e0 = __expf(dt * A[2 * s]);
            float e1 = __expf(dt * A[2 * s + 1]);
            h[2 * s]     = fmaf(e0, h[2 * s],     dx * bcv.x);
            h[2 * s + 1] = fmaf(e1, h[2 * s + 1], dx * bcv.y);
            if (FINAL) {
                y = fmaf(h[2 * s], bcv.z, y);
                y = fmaf(h[2 * s + 1], bcv.w, y);
            }
        }
        if (FINAL) op[t * DM] = fmaf(xv, Dsk, y);
        else       dts += dt;
    }

    if (!FINAL) {
#pragma unroll
        for (int n = 0; n < 16; n += 4)
            *(float4*)&g_f[sidx + n] = make_float4(h[n], h[n + 1], h[n + 2], h[n + 3]);
        g_dtsum[(b * CHUNKS + c) * DM + d] = dts;
    }
}

// =================================================================================
// Kernel 3b: sequential combine across chunks.
// =================================================================================
__global__ __launch_bounds__(256) void scan_combine_kernel(
    const float* __restrict__ A_log)
{
    const int tid = blockIdx.x * blockDim.x + threadIdx.x;
    const int n = tid & 15;
    const int d = (tid >> 4) & (DM - 1);
    const int b = tid >> 14;

    const float A = -expf(A_log[d * ST + n]);
    float H = 0.0f;
#pragma unroll
    for (int c = 0; c < CHUNKS; c++) {
        const int base = (b * CHUNKS + c) * DM + d;
        g_hinit[base * ST + n] = H;
        float P = __expf(A * g_dtsum[base]);
        H = fmaf(P, H, g_f[base * ST + n]);
    }
}

// =================================================================================
// launch
// =================================================================================
extern "C" void kernel_launch(void* const* d_in, const int* in_sizes, int n_in,
                              void* d_out, int out_size)
{
    const float* x      = (const float*)d_in[0];
    const float* A_log  = (const float*)d_in[1];
    const float* D_skip = (const float*)d_in[2];
    const float* Wd     = (const float*)d_in[3];
    const float* bd     = (const float*)d_in[4];
    const float* Wb     = (const float*)d_in[5];
    const float* bb     = (const float*)d_in[6];
    const float* Wc     = (const float*)d_in[7];
    const float* bc     = (const float*)d_in[8];
    float* out = (float*)d_out;

    cudaFuncSetAttribute(gemm_delta_mma, cudaFuncAttributeMaxDynamicSharedMemorySize, GS_TOTAL);
    cudaFuncSetAttribute(proj_mma_kernel, cudaFuncAttributeMaxDynamicSharedMemorySize, PJ_TOTAL);

    convert_x_kernel<<<(M_TOT * DM / 4) / 256, 256>>>(x);
    {
        dim3 tgrid(DM / 32, DM / 32);
        transpose_w_kernel<<<tgrid, 256>>>(Wd);
    }
    transpose_wbc_kernel<<<(32 * DM) / 256, 256>>>(Wb, Wc);
    {
        dim3 grid(DM / 128, M_TOT / 128);   // (8, 64)
        gemm_delta_mma<<<grid, 256, GS_TOTAL>>>(bd);
    }
    {
        dim3 pgrid(M_TOT / 128, PKSEG);     // (64, 8)
        proj_mma_kernel<<<pgrid, 256, PJ_TOTAL>>>();
    }
    proj_reduce_kernel<<<(M_TOT * 8) / 256, 256>>>(bb, bc);

    const int scan_grid = B_SZ * CHUNKS * (DM / 256);   // 512
    scan_chunk_kernel<false><<<scan_grid, 256>>>(x, A_log, D_skip, out);
    scan_combine_kernel<<<(B_SZ * DM * ST) / 256, 256>>>(A_log);
    scan_chunk_kernel<true><<<scan_grid, 256>>>(x, A_log, D_skip, out);
}

// round 12
// speedup vs baseline: 1.5538x; 1.0476x over previous
#include <cuda_runtime.h>
#include <cuda_bf16.h>
#include <math.h>
#include <stdint.h>

#define B_SZ   4
#define SEQ    2048
#define DM     1024
#define ST     16
#define M_TOT  (B_SZ * SEQ)   // 8192 rows
#define CHUNKS 32
#define CLEN   (SEQ / CHUNKS) // 64
#define PKSEG  8

// ---------------- scratch (static device globals; no allocation) ----------------
__device__ float g_delta[M_TOT * DM];              // 32 MB
__device__ float g_BC[M_TOT * 2 * ST];             // 1 MB
__device__ float g_BCp[PKSEG * M_TOT * 2 * ST];    // 8 MB partials
__device__ float g_f[B_SZ * CHUNKS * DM * ST];     // 8 MB
__device__ float g_hinit[B_SZ * CHUNKS * DM * ST]; // 8 MB
__device__ float g_dtsum[B_SZ * CHUNKS * DM];      // 512 KB
__device__ __nv_bfloat16 g_xhi[M_TOT * DM];        // 16 MB
__device__ __nv_bfloat16 g_xlo[M_TOT * DM];        // 16 MB
__device__ __nv_bfloat16 g_wthi[DM * DM];          // 2 MB  (n,k)-major
__device__ __nv_bfloat16 g_wtlo[DM * DM];          // 2 MB
__device__ __nv_bfloat16 g_wbchi[32 * DM];         // 64 KB (n,k)-major [Wb;Wc]^T
__device__ __nv_bfloat16 g_wbclo[32 * DM];         // 64 KB

// ---------------- helpers ----------------
__device__ __forceinline__ float softplus_f(float z) {
    return fmaxf(z, 0.0f) + log1pf(expf(-fabsf(z)));
}
__device__ __forceinline__ uint32_t smem_u32(const void* p) {
    uint32_t a;
    asm("{ .reg .u64 t; cvta.to.shared.u64 t, %1; cvt.u32.u64 %0, t; }" : "=r"(a) : "l"(p));
    return a;
}

#define CP_ASYNC16(dst, src) \
    asm volatile("cp.async.cg.shared.global [%0], [%1], 16;" :: "r"(dst), "l"(src))
#define CP_COMMIT()  asm volatile("cp.async.commit_group;" ::: "memory")
#define CP_WAIT(N)   asm volatile("cp.async.wait_group %0;" :: "n"(N) : "memory")

__device__ __forceinline__ void ldsm_x4(uint32_t& r0, uint32_t& r1, uint32_t& r2, uint32_t& r3,
                                        uint32_t addr) {
    asm volatile("ldmatrix.sync.aligned.m8n8.x4.shared.b16 {%0,%1,%2,%3}, [%4];"
                 : "=r"(r0), "=r"(r1), "=r"(r2), "=r"(r3) : "r"(addr));
}
__device__ __forceinline__ void ldsm_x2(uint32_t& r0, uint32_t& r1, uint32_t addr) {
    asm volatile("ldmatrix.sync.aligned.m8n8.x2.shared.b16 {%0,%1}, [%2];"
                 : "=r"(r0), "=r"(r1) : "r"(addr));
}
__device__ __forceinline__ void mma_bf16(float& c0, float& c1, float& c2, float& c3,
                                         uint32_t a0, uint32_t a1, uint32_t a2, uint32_t a3,
                                         uint32_t b0, uint32_t b1) {
    asm volatile(
        "mma.sync.aligned.m16n8k16.row.col.f32.bf16.bf16.f32 "
        "{%0,%1,%2,%3}, {%4,%5,%6,%7}, {%8,%9}, {%0,%1,%2,%3};"
        : "+f"(c0), "+f"(c1), "+f"(c2), "+f"(c3)
        : "r"(a0), "r"(a1), "r"(a2), "r"(a3), "r"(b0), "r"(b1));
}

// 64B-row smem swizzle: rows of 4x16B segments; seg' = seg ^ ((row>>1)&3).
__device__ __forceinline__ uint32_t sw64(uint32_t o) {
    return o ^ (((o >> 7) & 3u) << 4);
}

// =================================================================================
// Kernel 0 (fused prologue): convert x (blocks 0..8191), transpose Wd (8192..9215),
// transpose [Wb|Wc] (9216..9343).
// =================================================================================
#define PRE_CONV_BLKS  (M_TOT * DM / 4 / 256)   // 8192
#define PRE_TW_BLKS    ((DM / 32) * (DM / 32))  // 1024
#define PRE_WBC_BLKS   ((32 * DM) / 256)        // 128
#define PRE_TOTAL_BLKS (PRE_CONV_BLKS + PRE_TW_BLKS + PRE_WBC_BLKS)

__global__ __launch_bounds__(256) void prologue_kernel(
    const float* __restrict__ x,  const float* __restrict__ Wd,
    const float* __restrict__ Wb, const float* __restrict__ Wc)
{
    __shared__ float tile[32][33];
    const int bid = blockIdx.x;
    const int tid = threadIdx.x;

    if (bid < PRE_CONV_BLKS) {
        const int i = bid * 256 + tid;
        float4 v = ((const float4*)x)[i];
        __nv_bfloat16 hx = __float2bfloat16_rn(v.x);
        __nv_bfloat16 hy = __float2bfloat16_rn(v.y);
        __nv_bfloat16 hz = __float2bfloat16_rn(v.z);
        __nv_bfloat16 hw = __float2bfloat16_rn(v.w);
        __nv_bfloat162* phi = (__nv_bfloat162*)g_xhi;
        __nv_bfloat162* plo = (__nv_bfloat162*)g_xlo;
        phi[i * 2 + 0] = __nv_bfloat162(hx, hy);
        phi[i * 2 + 1] = __nv_bfloat162(hz, hw);
        plo[i * 2 + 0] = __nv_bfloat162(__float2bfloat16_rn(v.x - __bfloat162float(hx)),
                                        __float2bfloat16_rn(v.y - __bfloat162float(hy)));
        plo[i * 2 + 1] = __nv_bfloat162(__float2bfloat16_rn(v.z - __bfloat162float(hz)),
                                        __float2bfloat16_rn(v.w - __bfloat162float(hw)));
    } else if (bid < PRE_CONV_BLKS + PRE_TW_BLKS) {
        const int r  = bid - PRE_CONV_BLKS;
        const int x0 = (r & 31) * 32;
        const int y0 = (r >> 5) * 32;
        const int tx = tid & 31;
        const int ty = tid >> 5;
#pragma unroll
        for (int i = 0; i < 32; i += 8)
            tile[ty + i][tx] = Wd[(y0 + ty + i) * DM + x0 + tx];
        __syncthreads();
#pragma unroll
        for (int i = 0; i < 32; i += 8) {
            float v = tile[tx][ty + i];
            __nv_bfloat16 h = __float2bfloat16_rn(v);
            g_wthi[(x0 + ty + i) * DM + y0 + tx] = h;
            g_wtlo[(x0 + ty + i) * DM + y0 + tx] = __float2bfloat16_rn(v - __bfloat162float(h));
        }
    } else {
        const int idx = (bid - PRE_CONV_BLKS - PRE_TW_BLKS) * 256 + tid;  // 0..32767
        const int n = idx >> 10;
        const int k = idx & (DM - 1);
        float v = (n < 16) ? Wb[k * ST + n] : Wc[k * ST + (n - 16)];
        __nv_bfloat16 h = __float2bfloat16_rn(v);
        g_wbchi[n * DM + k] = h;
        g_wbclo[n * DM + k] = __float2bfloat16_rn(v - __bfloat162float(h));
    }
}

// =================================================================================
// GEMM tile body (delta = softplus(x@Wd + bd)); 3-stage ring, swizzled 64B rows.
// =================================================================================
#define T_A_HI 0
#define T_A_LO 8192
#define T_B_HI 16384
#define T_B_LO 24576
#define BUFS   32768
#define NSTAGE 3
#define GS_TOTAL (NSTAGE * BUFS)  // 98304
#define BK     32
#define NSLAB  (DM / BK)     // 32

__device__ __forceinline__ void gemm_load_slab(uint32_t sb, int stage, int row0, int col0,
                                               int k0, int tid)
{
    const uint32_t base = sb + stage * BUFS;
#pragma unroll
    for (int t = 0; t < 2; t++) {
        int op  = tid + t * 256;        // 0..511
        int row = op >> 2;              // 0..127
        int seg = op & 3;               // 0..3 (16B each)
        uint32_t doff = sw64((uint32_t)(row * 64 + seg * 16));
        CP_ASYNC16(base + T_A_HI + doff, &g_xhi[(row0 + row) * DM + k0 + seg * 8]);
        CP_ASYNC16(base + T_A_LO + doff, &g_xlo[(row0 + row) * DM + k0 + seg * 8]);
        CP_ASYNC16(base + T_B_HI + doff, &g_wthi[(col0 + row) * DM + k0 + seg * 8]);
        CP_ASYNC16(base + T_B_LO + doff, &g_wtlo[(col0 + row) * DM + k0 + seg * 8]);
    }
}

__device__ void gemm_tile_body(uint32_t sb, int bx, int by, const float* __restrict__ bd)
{
    const int tid  = threadIdx.x;
    const int lane = tid & 31;
    const int warp = tid >> 5;
    const int wm   = warp & 1;
    const int wn   = warp >> 1;
    const int row0 = by * 128;
    const int col0 = bx * 128;

    float acc[4][4][4];
#pragma unroll
    for (int i = 0; i < 4; i++)
#pragma unroll
        for (int j = 0; j < 4; j++)
#pragma unroll
            for (int k = 0; k < 4; k++) acc[i][j][k] = 0.0f;

    const int rlA = (lane & 7) + 8 * ((lane >> 3) & 1);
    const int cA  = (lane >> 4) & 1;
    const int rlB = lane & 7;
    const int cB  = (lane >> 3) & 1;

    uint32_t aoff[4], boff[4];
#pragma unroll
    for (int mf = 0; mf < 4; mf++) {
        int row = wm * 64 + mf * 16 + rlA;
        aoff[mf] = sw64((uint32_t)(row * 64 + cA * 16));
    }
#pragma unroll
    for (int nf = 0; nf < 4; nf++) {
        int row = wn * 32 + nf * 8 + rlB;
        boff[nf] = sw64((uint32_t)(row * 64 + cB * 16));
    }

    gemm_load_slab(sb, 0, row0, col0, 0, tid);
    CP_COMMIT();
    gemm_load_slab(sb, 1, row0, col0, BK, tid);
    CP_COMMIT();

    for (int s = 0; s < NSLAB; s++) {
        if (s + 1 < NSLAB) { CP_WAIT(1); } else { CP_WAIT(0); }
        __syncthreads();

        if (s + 2 < NSLAB) {
            gemm_load_slab(sb, (s + 2) % NSTAGE, row0, col0, (s + 2) * BK, tid);
            CP_COMMIT();
        }

        const uint32_t bufb = sb + (s % NSTAGE) * BUFS;
        const uint32_t aHi = bufb + T_A_HI;
        const uint32_t aLo = bufb + T_A_LO;
        const uint32_t bHi = bufb + T_B_HI;
        const uint32_t bLo = bufb + T_B_LO;

#pragma unroll
        for (int ks = 0; ks < 2; ks++) {
            const uint32_t kx = ks ? 0x20u : 0u;
            uint32_t ah[4][4], al[4][4];
#pragma unroll
            for (int mf = 0; mf < 4; mf++) {
                uint32_t ao = aoff[mf] ^ kx;
                ldsm_x4(ah[mf][0], ah[mf][1], ah[mf][2], ah[mf][3], aHi + ao);
                ldsm_x4(al[mf][0], al[mf][1], al[mf][2], al[mf][3], aLo + ao);
            }
            uint32_t bh[4][2], bl[4][2];
#pragma unroll
            for (int nf = 0; nf < 4; nf++) {
                uint32_t bo = boff[nf] ^ kx;
                ldsm_x2(bh[nf][0], bh[nf][1], bHi + bo);
                ldsm_x2(bl[nf][0], bl[nf][1], bLo + bo);
            }
#pragma unroll
            for (int mf = 0; mf < 4; mf++)
#pragma unroll
                for (int nf = 0; nf < 4; nf++) {
                    float* c = acc[mf][nf];
                    mma_bf16(c[0], c[1], c[2], c[3],
                             ah[mf][0], ah[mf][1], ah[mf][2], ah[mf][3],
                             bh[nf][0], bh[nf][1]);
                    mma_bf16(c[0], c[1], c[2], c[3],
                             ah[mf][0], ah[mf][1], ah[mf][2], ah[mf][3],
                             bl[nf][0], bl[nf][1]);
                    mma_bf16(c[0], c[1], c[2], c[3],
                             al[mf][0], al[mf][1], al[mf][2], al[mf][3],
                             bh[nf][0], bh[nf][1]);
                }
        }
    }

    const int g   = lane >> 2;
    const int tig = lane & 3;
#pragma unroll
    for (int nf = 0; nf < 4; nf++) {
        const int col = col0 + wn * 32 + nf * 8 + tig * 2;
        const float b0v = bd[col];
        const float b1v = bd[col + 1];
#pragma unroll
        for (int mf = 0; mf < 4; mf++) {
            const int row = row0 + wm * 64 + mf * 16 + g;
            float* c = acc[mf][nf];
            float2 v0, v1;
            v0.x = softplus_f(c[0] + b0v);
            v0.y = softplus_f(c[1] + b1v);
            v1.x = softplus_f(c[2] + b0v);
            v1.y = softplus_f(c[3] + b1v);
            *(float2*)&g_delta[row * DM + col]       = v0;
            *(float2*)&g_delta[(row + 8) * DM + col] = v1;
        }
    }
}

// =================================================================================
// Proj tile body (B/C projection split-K x8, partials -> g_BCp)
// =================================================================================
#define ROWB    80
#define PJ_A_HI 0
#define PJ_A_LO 10240
#define PJ_B_HI 20480
#define PJ_B_LO 23040
#define PJ_BUF  25600

__device__ __forceinline__ void proj_load_slab(uint32_t sb, int buf, int row0, int k0, int tid)
{
    const uint32_t base = sb + buf * PJ_BUF;
#pragma unroll
    for (int t = 0; t < 2; t++) {
        int op  = tid + t * 256;
        int row = op >> 2;
        int seg = op & 3;
        uint32_t doff = row * ROWB + seg * 16;
        CP_ASYNC16(base + PJ_A_HI + doff, &g_xhi[(row0 + row) * DM + k0 + seg * 8]);
        CP_ASYNC16(base + PJ_A_LO + doff, &g_xlo[(row0 + row) * DM + k0 + seg * 8]);
    }
    {
        int row = (tid & 127) >> 2;      // 0..31
        int seg = tid & 3;
        uint32_t doff = row * ROWB + seg * 16;
        if (tid < 128)
            CP_ASYNC16(base + PJ_B_HI + doff, &g_wbchi[row * DM + k0 + seg * 8]);
        else
            CP_ASYNC16(base + PJ_B_LO + doff, &g_wbclo[row * DM + k0 + seg * 8]);
    }
}

__device__ void proj_tile_body(uint32_t sb, int pm, int kseg)
{
    const int tid  = threadIdx.x;
    const int lane = tid & 31;
    const int warp = tid >> 5;
    const int row0 = pm * 128;
    const int kbeg = kseg * (DM / PKSEG);

    float acc[4][4];
#pragma unroll
    for (int i = 0; i < 4; i++)
#pragma unroll
        for (int j = 0; j < 4; j++) acc[i][j] = 0.0f;

    const int rlA = (lane & 7) + 8 * ((lane >> 3) & 1);
    const int cbA = (lane >> 4) * 16;
    const int rlB = lane & 7;
    const int cbB = ((lane >> 3) & 1) * 16;

    proj_load_slab(sb, 0, row0, kbeg, tid);
    CP_COMMIT();

#pragma unroll
    for (int s = 0; s < 4; s++) {
        if (s + 1 < 4) {
            proj_load_slab(sb, (s + 1) & 1, row0, kbeg + (s + 1) * BK, tid);
            CP_COMMIT();
            CP_WAIT(1);
        } else {
            CP_WAIT(0);
        }
        __syncthreads();

        const uint32_t bufb = sb + (s & 1) * PJ_BUF;
        const uint32_t aHi = bufb + PJ_A_HI + (warp * 16) * ROWB;
        const uint32_t aLo = bufb + PJ_A_LO + (warp * 16) * ROWB;
        const uint32_t bHi = bufb + PJ_B_HI;
        const uint32_t bLo = bufb + PJ_B_LO;

#pragma unroll
        for (int ks = 0; ks < 2; ks++) {
            const int ksb = ks * 32;
            uint32_t ah[4], al[4];
            uint32_t ao = rlA * ROWB + ksb + cbA;
            ldsm_x4(ah[0], ah[1], ah[2], ah[3], aHi + ao);
            ldsm_x4(al[0], al[1], al[2], al[3], aLo + ao);
            uint32_t bh[4][2], bl[4][2];
#pragma unroll
            for (int nf = 0; nf < 4; nf++) {
                uint32_t bo = (nf * 8 + rlB) * ROWB + ksb + cbB;
                ldsm_x2(bh[nf][0], bh[nf][1], bHi + bo);
                ldsm_x2(bl[nf][0], bl[nf][1], bLo + bo);
            }
#pragma unroll
            for (int nf = 0; nf < 4; nf++) {
                float* c = acc[nf];
                mma_bf16(c[0], c[1], c[2], c[3], ah[0], ah[1], ah[2], ah[3],
                         bh[nf][0], bh[nf][1]);
                mma_bf16(c[0], c[1], c[2], c[3], ah[0], ah[1], ah[2], ah[3],
                         bl[nf][0], bl[nf][1]);
                mma_bf16(c[0], c[1], c[2], c[3], al[0], al[1], al[2], al[3],
                         bh[nf][0], bh[nf][1]);
            }
        }
        __syncthreads();
    }

    const int g   = lane >> 2;
    const int tig = lane & 3;
    float* dst = g_BCp + kseg * (M_TOT * 2 * ST);
#pragma unroll
    for (int nf = 0; nf < 4; nf++) {
        const int cc  = nf * 8 + tig * 2;
        const int isC = (cc >= 16);
        const int n   = cc & 15;
        const int r0r = row0 + warp * 16 + g;
        float* c = acc[nf];
        *(float2*)&dst[(r0r * 8 + (n >> 1)) * 4 + isC * 2]       = make_float2(c[0], c[1]);
        *(float2*)&dst[((r0r + 8) * 8 + (n >> 1)) * 4 + isC * 2] = make_float2(c[2], c[3]);
    }
}

// =================================================================================
// Kernel 1 (fused): blocks 0..511 gemm tiles, 512..1023 proj tiles.
// Proj blocks fill the gemm's wave-tail and tensor-idle gaps.
// =================================================================================
__global__ __launch_bounds__(256, 2) void fused_mma_kernel(const float* __restrict__ bd)
{
    extern __shared__ char smem[];
    const uint32_t sb = smem_u32(smem);
    const int bid = blockIdx.x;
    if (bid < 512) {
        gemm_tile_body(sb, bid & 7, bid >> 3, bd);
    } else {
        const int r = bid - 512;
        proj_tile_body(sb, r & 63, r >> 6);
    }
}

// Reduce partials + bias into g_BC (interleaved layout).
__global__ __launch_bounds__(256) void proj_reduce_kernel(
    const float* __restrict__ bb, const float* __restrict__ bc)
{
    const int g = blockIdx.x * 256 + threadIdx.x;
    const int s = g & 7;
    const float4* p = (const float4*)g_BCp;
    float4 v = p[g];
#pragma unroll
    for (int k = 1; k < PKSEG; k++) {
        float4 w = p[k * (M_TOT * 8) + g];
        v.x += w.x; v.y += w.y; v.z += w.z; v.w += w.w;
    }
    v.x += bb[2 * s];
    v.y += bb[2 * s + 1];
    v.z += bc[2 * s];
    v.w += bc[2 * s + 1];
    ((float4*)g_BC)[g] = v;
}

// =================================================================================
// Kernel 3a / 3c: chunk-local scan, 1 thread per channel d, 16 states in registers.
// =================================================================================
template<bool FINAL>
__global__ __launch_bounds__(256) void scan_chunk_kernel(
    const float* __restrict__ x,
    const float* __restrict__ A_log,
    const float* __restrict__ D_skip,
    float* __restrict__ out)
{
    __shared__ float4 sbc[CLEN * 8];   // 8 KB

    const int tid = threadIdx.x;
    const int db  = blockIdx.x & 3;
    const int c   = (blockIdx.x >> 2) & (CHUNKS - 1);
    const int b   = blockIdx.x >> 7;
    const int d   = db * 256 + tid;
    const int rowbase = b * SEQ + c * CLEN;

    {
        const float4* src = (const float4*)g_BC + rowbase * 8;
        sbc[tid]       = src[tid];
        sbc[tid + 256] = src[tid + 256];
    }

    float A[16];
#pragma unroll
    for (int n = 0; n < 16; n += 4) {
        float4 v = *(const float4*)&A_log[d * ST + n];
        A[n]     = -expf(v.x);
        A[n + 1] = -expf(v.y);
        A[n + 2] = -expf(v.z);
        A[n + 3] = -expf(v.w);
    }

    const int sidx = ((b * CHUNKS + c) * DM + d) * ST;
    float h[16];
    float Dsk = 0.0f, dts = 0.0f;
    if (FINAL) {
#pragma unroll
        for (int n = 0; n < 16; n += 4) {
            float4 v = *(const float4*)&g_hinit[sidx + n];
            h[n] = v.x; h[n + 1] = v.y; h[n + 2] = v.z; h[n + 3] = v.w;
        }
        Dsk = D_skip[d];
    } else {
#pragma unroll
        for (int n = 0; n < 16; n++) h[n] = 0.0f;
    }
    __syncthreads();

    const float* dp = g_delta + rowbase * DM + d;
    const float* xp = x       + rowbase * DM + d;
    float*       op = out     + rowbase * DM + d;

#pragma unroll 2
    for (int t = 0; t < CLEN; t++) {
        float dt = dp[t * DM];
        float xv = xp[t * DM];
        float dx = dt * xv;
        float y  = 0.0f;
#pragma unroll
        for (int s = 0; s < 8; s++) {
            float4 bcv = sbc[t * 8 + s];
            float e0 = __expf(dt * A[2 * s]);
            float e1 = __expf(dt * A[2 * s + 1]);
            h[2 * s]     = fmaf(e0, h[2 * s],     dx * bcv.x);
            h[2 * s + 1] = fmaf(e1, h[2 * s + 1], dx * bcv.y);
            if (FINAL) {
                y = fmaf(h[2 * s], bcv.z, y);
                y = fmaf(h[2 * s + 1], bcv.w, y);
            }
        }
        if (FINAL) op[t * DM] = fmaf(xv, Dsk, y);
        else       dts += dt;
    }

    if (!FINAL) {
#pragma unroll
        for (int n = 0; n < 16; n += 4)
            *(float4*)&g_f[sidx + n] = make_float4(h[n], h[n + 1], h[n + 2], h[n + 3]);
        g_dtsum[(b * CHUNKS + c) * DM + d] = dts;
    }
}

// =================================================================================
// Kernel 3b: sequential combine across chunks.
// =================================================================================
__global__ __launch_bounds__(256) void scan_combine_kernel(
    const float* __restrict__ A_log)
{
    const int tid = blockIdx.x * blockDim.x + threadIdx.x;
    const int n = tid & 15;
    const int d = (tid >> 4) & (DM - 1);
    const int b = tid >> 14;

    const float A = -expf(A_log[d * ST + n]);
    float H = 0.0f;
#pragma unroll
    for (int c = 0; c < CHUNKS; c++) {
        const int base = (b * CHUNKS + c) * DM + d;
        g_hinit[base * ST + n] = H;
        float P = __expf(A * g_dtsum[base]);
        H = fmaf(P, H, g_f[base * ST + n]);
    }
}

// =================================================================================
// launch — single stream; concurrency expressed inside the fused kernels.
// =================================================================================
extern "C" void kernel_launch(void* const* d_in, const int* in_sizes, int n_in,
                              void* d_out, int out_size)
{
    const float* x      = (const float*)d_in[0];
    const float* A_log  = (const float*)d_in[1];
    const float* D_skip = (const float*)d_in[2];
    const float* Wd     = (const float*)d_in[3];
    const float* bd     = (const float*)d_in[4];
    const float* Wb     = (const float*)d_in[5];
    const float* bb     = (const float*)d_in[6];
    const float* Wc     = (const float*)d_in[7];
    const float* bc     = (const float*)d_in[8];
    float* out = (float*)d_out;

    cudaFuncSetAttribute(fused_mma_kernel, cudaFuncAttributeMaxDynamicSharedMemorySize, GS_TOTAL);

    prologue_kernel<<<PRE_TOTAL_BLKS, 256>>>(x, Wd, Wb, Wc);
    fused_mma_kernel<<<1024, 256, GS_TOTAL>>>(bd);
    proj_reduce_kernel<<<(M_TOT * 8) / 256, 256>>>(bb, bc);

    const int scan_grid = B_SZ * CHUNKS * (DM / 256);   // 512
    scan_chunk_kernel<false><<<scan_grid, 256>>>(x, A_log, D_skip, out);
    scan_combine_kernel<<<(B_SZ * DM * ST) / 256, 256>>>(A_log);
    scan_chunk_kernel<true><<<scan_grid, 256>>>(x, A_log, D_skip, out);
}

// round 13
// speedup vs baseline: 1.5917x; 1.0244x over previous
#include <cuda_runtime.h>
#include <cuda_bf16.h>
#include <math.h>
#include <stdint.h>

#define B_SZ   4
#define SEQ    2048
#define DM     1024
#define ST     16
#define M_TOT  (B_SZ * SEQ)   // 8192 rows
#define CHUNKS 32
#define CLEN   (SEQ / CHUNKS) // 64
#define PKSEG  4

// ---------------- scratch (static device globals; no allocation) ----------------
__device__ float g_delta[M_TOT * DM];              // 32 MB
__device__ float g_BC[M_TOT * 2 * ST];             // 1 MB
__device__ float g_BCp[PKSEG * M_TOT * 2 * ST];    // 4 MB partials
__device__ float g_f[B_SZ * CHUNKS * DM * ST];     // 8 MB
__device__ float g_hinit[B_SZ * CHUNKS * DM * ST]; // 8 MB
__device__ float g_dtsum[B_SZ * CHUNKS * DM];      // 512 KB
__device__ __nv_bfloat16 g_xhi[M_TOT * DM];        // 16 MB
__device__ __nv_bfloat16 g_xlo[M_TOT * DM];        // 16 MB
__device__ __nv_bfloat16 g_wthi[DM * DM];          // 2 MB  (n,k)-major
__device__ __nv_bfloat16 g_wtlo[DM * DM];          // 2 MB
__device__ __nv_bfloat16 g_wbchi[32 * DM];         // 64 KB (n,k)-major [Wb;Wc]^T
__device__ __nv_bfloat16 g_wbclo[32 * DM];         // 64 KB

// ---------------- helpers ----------------
__device__ __forceinline__ float softplus_f(float z) {
    return fmaxf(z, 0.0f) + log1pf(expf(-fabsf(z)));
}
__device__ __forceinline__ uint32_t smem_u32(const void* p) {
    uint32_t a;
    asm("{ .reg .u64 t; cvta.to.shared.u64 t, %1; cvt.u32.u64 %0, t; }" : "=r"(a) : "l"(p));
    return a;
}

#define CP_ASYNC16(dst, src) \
    asm volatile("cp.async.cg.shared.global [%0], [%1], 16;" :: "r"(dst), "l"(src))
#define CP_COMMIT()  asm volatile("cp.async.commit_group;" ::: "memory")
#define CP_WAIT(N)   asm volatile("cp.async.wait_group %0;" :: "n"(N) : "memory")

__device__ __forceinline__ void ldsm_x4(uint32_t& r0, uint32_t& r1, uint32_t& r2, uint32_t& r3,
                                        uint32_t addr) {
    asm volatile("ldmatrix.sync.aligned.m8n8.x4.shared.b16 {%0,%1,%2,%3}, [%4];"
                 : "=r"(r0), "=r"(r1), "=r"(r2), "=r"(r3) : "r"(addr));
}
__device__ __forceinline__ void ldsm_x2(uint32_t& r0, uint32_t& r1, uint32_t addr) {
    asm volatile("ldmatrix.sync.aligned.m8n8.x2.shared.b16 {%0,%1}, [%2];"
                 : "=r"(r0), "=r"(r1) : "r"(addr));
}
__device__ __forceinline__ void mma_bf16(float& c0, float& c1, float& c2, float& c3,
                                         uint32_t a0, uint32_t a1, uint32_t a2, uint32_t a3,
                                         uint32_t b0, uint32_t b1) {
    asm volatile(
        "mma.sync.aligned.m16n8k16.row.col.f32.bf16.bf16.f32 "
        "{%0,%1,%2,%3}, {%4,%5,%6,%7}, {%8,%9}, {%0,%1,%2,%3};"
        : "+f"(c0), "+f"(c1), "+f"(c2), "+f"(c3)
        : "r"(a0), "r"(a1), "r"(a2), "r"(a3), "r"(b0), "r"(b1));
}

// 64B-row smem swizzle: rows of 4x16B segments; seg' = seg ^ ((row>>1)&3).
__device__ __forceinline__ uint32_t sw64(uint32_t o) {
    return o ^ (((o >> 7) & 3u) << 4);
}

// =================================================================================
// Kernel 0 (fused prologue): convert x (blocks 0..8191), transpose Wd (8192..9215),
// transpose [Wb|Wc] (9216..9343).
// =================================================================================
#define PRE_CONV_BLKS  (M_TOT * DM / 4 / 256)   // 8192
#define PRE_TW_BLKS    ((DM / 32) * (DM / 32))  // 1024
#define PRE_WBC_BLKS   ((32 * DM) / 256)        // 128
#define PRE_TOTAL_BLKS (PRE_CONV_BLKS + PRE_TW_BLKS + PRE_WBC_BLKS)

__global__ __launch_bounds__(256) void prologue_kernel(
    const float* __restrict__ x,  const float* __restrict__ Wd,
    const float* __restrict__ Wb, const float* __restrict__ Wc)
{
    __shared__ float tile[32][33];
    const int bid = blockIdx.x;
    const int tid = threadIdx.x;

    if (bid < PRE_CONV_BLKS) {
        const int i = bid * 256 + tid;
        float4 v = ((const float4*)x)[i];
        __nv_bfloat16 hx = __float2bfloat16_rn(v.x);
        __nv_bfloat16 hy = __float2bfloat16_rn(v.y);
        __nv_bfloat16 hz = __float2bfloat16_rn(v.z);
        __nv_bfloat16 hw = __float2bfloat16_rn(v.w);
        __nv_bfloat162* phi = (__nv_bfloat162*)g_xhi;
        __nv_bfloat162* plo = (__nv_bfloat162*)g_xlo;
        phi[i * 2 + 0] = __nv_bfloat162(hx, hy);
        phi[i * 2 + 1] = __nv_bfloat162(hz, hw);
        plo[i * 2 + 0] = __nv_bfloat162(__float2bfloat16_rn(v.x - __bfloat162float(hx)),
                                        __float2bfloat16_rn(v.y - __bfloat162float(hy)));
        plo[i * 2 + 1] = __nv_bfloat162(__float2bfloat16_rn(v.z - __bfloat162float(hz)),
                                        __float2bfloat16_rn(v.w - __bfloat162float(hw)));
    } else if (bid < PRE_CONV_BLKS + PRE_TW_BLKS) {
        const int r  = bid - PRE_CONV_BLKS;
        const int x0 = (r & 31) * 32;
        const int y0 = (r >> 5) * 32;
        const int tx = tid & 31;
        const int ty = tid >> 5;
#pragma unroll
        for (int i = 0; i < 32; i += 8)
            tile[ty + i][tx] = Wd[(y0 + ty + i) * DM + x0 + tx];
        __syncthreads();
#pragma unroll
        for (int i = 0; i < 32; i += 8) {
            float v = tile[tx][ty + i];
            __nv_bfloat16 h = __float2bfloat16_rn(v);
            g_wthi[(x0 + ty + i) * DM + y0 + tx] = h;
            g_wtlo[(x0 + ty + i) * DM + y0 + tx] = __float2bfloat16_rn(v - __bfloat162float(h));
        }
    } else {
        const int idx = (bid - PRE_CONV_BLKS - PRE_TW_BLKS) * 256 + tid;  // 0..32767
        const int n = idx >> 10;
        const int k = idx & (DM - 1);
        float v = (n < 16) ? Wb[k * ST + n] : Wc[k * ST + (n - 16)];
        __nv_bfloat16 h = __float2bfloat16_rn(v);
        g_wbchi[n * DM + k] = h;
        g_wbclo[n * DM + k] = __float2bfloat16_rn(v - __bfloat162float(h));
    }
}

// =================================================================================
// GEMM tile body (delta = softplus(x@Wd + bd)); 3-stage ring, swizzled 64B rows.
// =================================================================================
#define T_A_HI 0
#define T_A_LO 8192
#define T_B_HI 16384
#define T_B_LO 24576
#define BUFS   32768
#define NSTAGE 3
#define GS_TOTAL (NSTAGE * BUFS)  // 98304
#define BK     32
#define NSLAB  (DM / BK)     // 32

__device__ __forceinline__ void gemm_load_slab(uint32_t sb, int stage, int row0, int col0,
                                               int k0, int tid)
{
    const uint32_t base = sb + stage * BUFS;
#pragma unroll
    for (int t = 0; t < 2; t++) {
        int op  = tid + t * 256;        // 0..511
        int row = op >> 2;              // 0..127
        int seg = op & 3;               // 0..3 (16B each)
        uint32_t doff = sw64((uint32_t)(row * 64 + seg * 16));
        CP_ASYNC16(base + T_A_HI + doff, &g_xhi[(row0 + row) * DM + k0 + seg * 8]);
        CP_ASYNC16(base + T_A_LO + doff, &g_xlo[(row0 + row) * DM + k0 + seg * 8]);
        CP_ASYNC16(base + T_B_HI + doff, &g_wthi[(col0 + row) * DM + k0 + seg * 8]);
        CP_ASYNC16(base + T_B_LO + doff, &g_wtlo[(col0 + row) * DM + k0 + seg * 8]);
    }
}

__device__ void gemm_tile_body(uint32_t sb, int bx, int by, const float* __restrict__ bd)
{
    const int tid  = threadIdx.x;
    const int lane = tid & 31;
    const int warp = tid >> 5;
    const int wm   = warp & 1;
    const int wn   = warp >> 1;
    const int row0 = by * 128;
    const int col0 = bx * 128;

    float acc[4][4][4];
#pragma unroll
    for (int i = 0; i < 4; i++)
#pragma unroll
        for (int j = 0; j < 4; j++)
#pragma unroll
            for (int k = 0; k < 4; k++) acc[i][j][k] = 0.0f;

    const int rlA = (lane & 7) + 8 * ((lane >> 3) & 1);
    const int cA  = (lane >> 4) & 1;
    const int rlB = lane & 7;
    const int cB  = (lane >> 3) & 1;

    uint32_t aoff[4], boff[4];
#pragma unroll
    for (int mf = 0; mf < 4; mf++) {
        int row = wm * 64 + mf * 16 + rlA;
        aoff[mf] = sw64((uint32_t)(row * 64 + cA * 16));
    }
#pragma unroll
    for (int nf = 0; nf < 4; nf++) {
        int row = wn * 32 + nf * 8 + rlB;
        boff[nf] = sw64((uint32_t)(row * 64 + cB * 16));
    }

    gemm_load_slab(sb, 0, row0, col0, 0, tid);
    CP_COMMIT();
    gemm_load_slab(sb, 1, row0, col0, BK, tid);
    CP_COMMIT();

    for (int s = 0; s < NSLAB; s++) {
        if (s + 1 < NSLAB) { CP_WAIT(1); } else { CP_WAIT(0); }
        __syncthreads();

        if (s + 2 < NSLAB) {
            gemm_load_slab(sb, (s + 2) % NSTAGE, row0, col0, (s + 2) * BK, tid);
            CP_COMMIT();
        }

        const uint32_t bufb = sb + (s % NSTAGE) * BUFS;
        const uint32_t aHi = bufb + T_A_HI;
        const uint32_t aLo = bufb + T_A_LO;
        const uint32_t bHi = bufb + T_B_HI;
        const uint32_t bLo = bufb + T_B_LO;

#pragma unroll
        for (int ks = 0; ks < 2; ks++) {
            const uint32_t kx = ks ? 0x20u : 0u;
            uint32_t ah[4][4], al[4][4];
#pragma unroll
            for (int mf = 0; mf < 4; mf++) {
                uint32_t ao = aoff[mf] ^ kx;
                ldsm_x4(ah[mf][0], ah[mf][1], ah[mf][2], ah[mf][3], aHi + ao);
                ldsm_x4(al[mf][0], al[mf][1], al[mf][2], al[mf][3], aLo + ao);
            }
            uint32_t bh[4][2], bl[4][2];
#pragma unroll
            for (int nf = 0; nf < 4; nf++) {
                uint32_t bo = boff[nf] ^ kx;
                ldsm_x2(bh[nf][0], bh[nf][1], bHi + bo);
                ldsm_x2(bl[nf][0], bl[nf][1], bLo + bo);
            }
#pragma unroll
            for (int mf = 0; mf < 4; mf++)
#pragma unroll
                for (int nf = 0; nf < 4; nf++) {
                    float* c = acc[mf][nf];
                    mma_bf16(c[0], c[1], c[2], c[3],
                             ah[mf][0], ah[mf][1], ah[mf][2], ah[mf][3],
                             bh[nf][0], bh[nf][1]);
                    mma_bf16(c[0], c[1], c[2], c[3],
                             ah[mf][0], ah[mf][1], ah[mf][2], ah[mf][3],
                             bl[nf][0], bl[nf][1]);
                    mma_bf16(c[0], c[1], c[2], c[3],
                             al[mf][0], al[mf][1], al[mf][2], al[mf][3],
                             bh[nf][0], bh[nf][1]);
                }
        }
    }

    const int g   = lane >> 2;
    const int tig = lane & 3;
#pragma unroll
    for (int nf = 0; nf < 4; nf++) {
        const int col = col0 + wn * 32 + nf * 8 + tig * 2;
        const float b0v = bd[col];
        const float b1v = bd[col + 1];
#pragma unroll
        for (int mf = 0; mf < 4; mf++) {
            const int row = row0 + wm * 64 + mf * 16 + g;
            float* c = acc[mf][nf];
            float2 v0, v1;
            v0.x = softplus_f(c[0] + b0v);
            v0.y = softplus_f(c[1] + b1v);
            v1.x = softplus_f(c[2] + b0v);
            v1.y = softplus_f(c[3] + b1v);
            *(float2*)&g_delta[row * DM + col]       = v0;
            *(float2*)&g_delta[(row + 8) * DM + col] = v1;
        }
    }
}

// =================================================================================
// Proj tile body (B/C projection split-K x4, partials -> g_BCp). K=256 per block.
// =================================================================================
#define ROWB    80
#define PJ_A_HI 0
#define PJ_A_LO 10240
#define PJ_B_HI 20480
#define PJ_B_LO 23040
#define PJ_BUF  25600
#define NPJS    ((DM / PKSEG) / BK)   // 8 slabs

__device__ __forceinline__ void proj_load_slab(uint32_t sb, int buf, int row0, int k0, int tid)
{
    const uint32_t base = sb + buf * PJ_BUF;
#pragma unroll
    for (int t = 0; t < 2; t++) {
        int op  = tid + t * 256;
        int row = op >> 2;
        int seg = op & 3;
        uint32_t doff = row * ROWB + seg * 16;
        CP_ASYNC16(base + PJ_A_HI + doff, &g_xhi[(row0 + row) * DM + k0 + seg * 8]);
        CP_ASYNC16(base + PJ_A_LO + doff, &g_xlo[(row0 + row) * DM + k0 + seg * 8]);
    }
    {
        int row = (tid & 127) >> 2;      // 0..31
        int seg = tid & 3;
        uint32_t doff = row * ROWB + seg * 16;
        if (tid < 128)
            CP_ASYNC16(base + PJ_B_HI + doff, &g_wbchi[row * DM + k0 + seg * 8]);
        else
            CP_ASYNC16(base + PJ_B_LO + doff, &g_wbclo[row * DM + k0 + seg * 8]);
    }
}

__device__ void proj_tile_body(uint32_t sb, int pm, int kseg)
{
    const int tid  = threadIdx.x;
    const int lane = tid & 31;
    const int warp = tid >> 5;
    const int row0 = pm * 128;
    const int kbeg = kseg * (DM / PKSEG);

    float acc[4][4];
#pragma unroll
    for (int i = 0; i < 4; i++)
#pragma unroll
        for (int j = 0; j < 4; j++) acc[i][j] = 0.0f;

    const int rlA = (lane & 7) + 8 * ((lane >> 3) & 1);
    const int cbA = (lane >> 4) * 16;
    const int rlB = lane & 7;
    const int cbB = ((lane >> 3) & 1) * 16;

    proj_load_slab(sb, 0, row0, kbeg, tid);
    CP_COMMIT();

#pragma unroll
    for (int s = 0; s < NPJS; s++) {
        if (s + 1 < NPJS) {
            proj_load_slab(sb, (s + 1) & 1, row0, kbeg + (s + 1) * BK, tid);
            CP_COMMIT();
            CP_WAIT(1);
        } else {
            CP_WAIT(0);
        }
        __syncthreads();

        const uint32_t bufb = sb + (s & 1) * PJ_BUF;
        const uint32_t aHi = bufb + PJ_A_HI + (warp * 16) * ROWB;
        const uint32_t aLo = bufb + PJ_A_LO + (warp * 16) * ROWB;
        const uint32_t bHi = bufb + PJ_B_HI;
        const uint32_t bLo = bufb + PJ_B_LO;

#pragma unroll
        for (int ks = 0; ks < 2; ks++) {
            const int ksb = ks * 32;
            uint32_t ah[4], al[4];
            uint32_t ao = rlA * ROWB + ksb + cbA;
            ldsm_x4(ah[0], ah[1], ah[2], ah[3], aHi + ao);
            ldsm_x4(al[0], al[1], al[2], al[3], aLo + ao);
            uint32_t bh[4][2], bl[4][2];
#pragma unroll
            for (int nf = 0; nf < 4; nf++) {
                uint32_t bo = (nf * 8 + rlB) * ROWB + ksb + cbB;
                ldsm_x2(bh[nf][0], bh[nf][1], bHi + bo);
                ldsm_x2(bl[nf][0], bl[nf][1], bLo + bo);
            }
#pragma unroll
            for (int nf = 0; nf < 4; nf++) {
                float* c = acc[nf];
                mma_bf16(c[0], c[1], c[2], c[3], ah[0], ah[1], ah[2], ah[3],
                         bh[nf][0], bh[nf][1]);
                mma_bf16(c[0], c[1], c[2], c[3], ah[0], ah[1], ah[2], ah[3],
                         bl[nf][0], bl[nf][1]);
                mma_bf16(c[0], c[1], c[2], c[3], al[0], al[1], al[2], al[3],
                         bh[nf][0], bh[nf][1]);
            }
        }
        __syncthreads();
    }

    const int g   = lane >> 2;
    const int tig = lane & 3;
    float* dst = g_BCp + kseg * (M_TOT * 2 * ST);
#pragma unroll
    for (int nf = 0; nf < 4; nf++) {
        const int cc  = nf * 8 + tig * 2;
        const int isC = (cc >= 16);
        const int n   = cc & 15;
        const int r0r = row0 + warp * 16 + g;
        float* c = acc[nf];
        *(float2*)&dst[(r0r * 8 + (n >> 1)) * 4 + isC * 2]       = make_float2(c[0], c[1]);
        *(float2*)&dst[((r0r + 8) * 8 + (n >> 1)) * 4 + isC * 2] = make_float2(c[2], c[3]);
    }
}

// =================================================================================
// Kernel 1 (fused): blocks 0..511 gemm tiles, 512..767 proj tiles.
// =================================================================================
__global__ __launch_bounds__(256, 2) void fused_mma_kernel(const float* __restrict__ bd)
{
    extern __shared__ char smem[];
    const uint32_t sb = smem_u32(smem);
    const int bid = blockIdx.x;
    if (bid < 512) {
        gemm_tile_body(sb, bid & 7, bid >> 3, bd);
    } else {
        const int r = bid - 512;
        proj_tile_body(sb, r & 63, r >> 6);
    }
}

// Reduce partials + bias into g_BC (interleaved layout).
__global__ __launch_bounds__(256) void proj_reduce_kernel(
    const float* __restrict__ bb, const float* __restrict__ bc)
{
    const int g = blockIdx.x * 256 + threadIdx.x;
    const int s = g & 7;
    const float4* p = (const float4*)g_BCp;
    float4 v = p[g];
#pragma unroll
    for (int k = 1; k < PKSEG; k++) {
        float4 w = p[k * (M_TOT * 8) + g];
        v.x += w.x; v.y += w.y; v.z += w.z; v.w += w.w;
    }
    v.x += bb[2 * s];
    v.y += bb[2 * s + 1];
    v.z += bc[2 * s];
    v.w += bc[2 * s + 1];
    ((float4*)g_BC)[g] = v;
}

// =================================================================================
// Kernel 3a / 3c: chunk-local scan; packed f32x2 state updates (sm_100 f32x2 pipe).
// 1 thread per channel d, 16 states as 8 packed 64-bit registers.
// =================================================================================
#define LOG2E_F 1.4426950408889634f

template<bool FINAL>
__global__ __launch_bounds__(256) void scan_chunk_kernel(
    const float* __restrict__ x,
    const float* __restrict__ A_log,
    const float* __restrict__ D_skip,
    float* __restrict__ out)
{
    __shared__ float4 sbc[CLEN * 8];   // 8 KB

    const int tid = threadIdx.x;
    const int db  = blockIdx.x & 3;
    const int c   = (blockIdx.x >> 2) & (CHUNKS - 1);
    const int b   = blockIdx.x >> 7;
    const int d   = db * 256 + tid;
    const int rowbase = b * SEQ + c * CLEN;

    {
        const float4* src = (const float4*)g_BC + rowbase * 8;
        sbc[tid]       = src[tid];
        sbc[tid + 256] = src[tid + 256];
    }
    const uint32_t sbcu = smem_u32(sbc);

    // A2[n] = -exp(A_log[d,n]) * log2(e)  (ex2 argument scale folded in)
    float A2[16];
#pragma unroll
    for (int n = 0; n < 16; n += 4) {
        float4 v = *(const float4*)&A_log[d * ST + n];
        A2[n]     = -expf(v.x) * LOG2E_F;
        A2[n + 1] = -expf(v.y) * LOG2E_F;
        A2[n + 2] = -expf(v.z) * LOG2E_F;
        A2[n + 3] = -expf(v.w) * LOG2E_F;
    }

    const int sidx = ((b * CHUNKS + c) * DM + d) * ST;
    unsigned long long h[8];
    float Dsk = 0.0f, dts = 0.0f;
    if (FINAL) {
        const ulonglong2* hp = (const ulonglong2*)&g_hinit[sidx];
#pragma unroll
        for (int q = 0; q < 4; q++) {
            ulonglong2 v = hp[q];
            h[2 * q]     = v.x;
            h[2 * q + 1] = v.y;
        }
        Dsk = D_skip[d];
    } else {
#pragma unroll
        for (int s = 0; s < 8; s++) h[s] = 0ull;
    }
    __syncthreads();

    const float* dp = g_delta + rowbase * DM + d;
    const float* xp = x       + rowbase * DM + d;
    float*       op = out     + rowbase * DM + d;

#pragma unroll 2
    for (int t = 0; t < CLEN; t++) {
        float dt = dp[t * DM];
        float xv = xp[t * DM];
        float dx = dt * xv;
        unsigned long long dxpk;
        asm("mov.b64 %0, {%1, %1};" : "=l"(dxpk) : "f"(dx));
        unsigned long long ypk = 0ull;
        const uint32_t taddr = sbcu + (uint32_t)(t * 8) * 16u;
#pragma unroll
        for (int s = 0; s < 8; s++) {
            unsigned long long bpk, cpk;
            asm volatile("ld.shared.v2.u64 {%0, %1}, [%2];"
                         : "=l"(bpk), "=l"(cpk) : "r"(taddr + s * 16u));
            float a0 = dt * A2[2 * s];
            float a1 = dt * A2[2 * s + 1];
            float e0, e1;
            asm("ex2.approx.f32 %0, %1;" : "=f"(e0) : "f"(a0));
            asm("ex2.approx.f32 %0, %1;" : "=f"(e1) : "f"(a1));
            unsigned long long epk;
            asm("mov.b64 %0, {%1, %2};" : "=l"(epk) : "f"(e0), "f"(e1));
            unsigned long long dxB;
            asm("mul.rn.f32x2 %0, %1, %2;" : "=l"(dxB) : "l"(dxpk), "l"(bpk));
            asm("fma.rn.f32x2 %0, %1, %0, %2;" : "+l"(h[s]) : "l"(epk), "l"(dxB));
            if (FINAL)
                asm("fma.rn.f32x2 %0, %1, %2, %0;" : "+l"(ypk) : "l"(h[s]), "l"(cpk));
        }
        if (FINAL) {
            float y0, y1;
            asm("mov.b64 {%0, %1}, %2;" : "=f"(y0), "=f"(y1) : "l"(ypk));
            op[t * DM] = fmaf(xv, Dsk, y0 + y1);
        } else {
            dts += dt;
        }
    }

    if (!FINAL) {
        ulonglong2* fp = (ulonglong2*)&g_f[sidx];
#pragma unroll
        for (int q = 0; q < 4; q++) {
            ulonglong2 v;
            v.x = h[2 * q];
            v.y = h[2 * q + 1];
            fp[q] = v;
        }
        g_dtsum[(b * CHUNKS + c) * DM + d] = dts;
    }
}

// =================================================================================
// Kernel 3b: sequential combine across chunks. __restrict__ locals let ptxas hoist
// the (address-independent) loads above the serial H chain.
// =================================================================================
__global__ __launch_bounds__(256) void scan_combine_kernel(
    const float* __restrict__ A_log)
{
    const int tid = blockIdx.x * blockDim.x + threadIdx.x;
    const int n = tid & 15;
    const int d = (tid >> 4) & (DM - 1);
    const int b = tid >> 14;

    float* __restrict__       hi = g_hinit;
    const float* __restrict__ ff = g_f;
    const float* __restrict__ ds = g_dtsum;

    const float A = -expf(A_log[d * ST + n]);
    float H = 0.0f;
#pragma unroll
    for (int c = 0; c < CHUNKS; c++) {
        const int base = (b * CHUNKS + c) * DM + d;
        hi[base * ST + n] = H;
        float P = __expf(A * ds[base]);
        H = fmaf(P, H, ff[base * ST + n]);
    }
}

// =================================================================================
// launch — single stream; concurrency expressed inside the fused kernels.
// =================================================================================
extern "C" void kernel_launch(void* const* d_in, const int* in_sizes, int n_in,
                              void* d_out, int out_size)
{
    const float* x      = (const float*)d_in[0];
    const float* A_log  = (const float*)d_in[1];
    const float* D_skip = (const float*)d_in[2];
    const float* Wd     = (const float*)d_in[3];
    const float* bd     = (const float*)d_in[4];
    const float* Wb     = (const float*)d_in[5];
    const float* bb     = (const float*)d_in[6];
    const float* Wc     = (const float*)d_in[7];
    const float* bc     = (const float*)d_in[8];
    float* out = (float*)d_out;

    cudaFuncSetAttribute(fused_mma_kernel, cudaFuncAttributeMaxDynamicSharedMemorySize, GS_TOTAL);

    prologue_kernel<<<PRE_TOTAL_BLKS, 256>>>(x, Wd, Wb, Wc);
    fused_mma_kernel<<<512 + 64 * PKSEG, 256, GS_TOTAL>>>(bd);
    proj_reduce_kernel<<<(M_TOT * 8) / 256, 256>>>(bb, bc);

    const int scan_grid = B_SZ * CHUNKS * (DM / 256);   // 512
    scan_chunk_kernel<false><<<scan_grid, 256>>>(x, A_log, D_skip, out);
    scan_combine_kernel<<<(B_SZ * DM * ST) / 256, 256>>>(A_log);
    scan_chunk_kernel<true><<<scan_grid, 256>>>(x, A_log, D_skip, out);
}

// round 14
// speedup vs baseline: 1.6733x; 1.0513x over previous
#include <cuda_runtime.h>
#include <cuda_bf16.h>
#include <math.h>
#include <stdint.h>

#define B_SZ   4
#define SEQ    2048
#define DM     1024
#define ST     16
#define M_TOT  (B_SZ * SEQ)   // 8192 rows
#define CHUNKS 32
#define CLEN   (SEQ / CHUNKS) // 64
#define PKSEG  4

// ---------------- scratch (static device globals; no allocation) ----------------
__device__ float g_delta[M_TOT * DM];              // 32 MB
__device__ float g_BCp[PKSEG * M_TOT * 2 * ST];    // 4 MB partials
__device__ float g_f[B_SZ * CHUNKS * DM * ST];     // 8 MB
__device__ float g_hinit[B_SZ * CHUNKS * DM * ST]; // 8 MB
__device__ float g_dtsum[B_SZ * CHUNKS * DM];      // 512 KB
__device__ __nv_bfloat16 g_xhi[M_TOT * DM];        // 16 MB
__device__ __nv_bfloat16 g_xlo[M_TOT * DM];        // 16 MB
__device__ __nv_bfloat16 g_wthi[DM * DM];          // 2 MB  (n,k)-major
__device__ __nv_bfloat16 g_wtlo[DM * DM];          // 2 MB
__device__ __nv_bfloat16 g_wbchi[32 * DM];         // 64 KB (n,k)-major [Wb;Wc]^T
__device__ __nv_bfloat16 g_wbclo[32 * DM];         // 64 KB

// ---------------- helpers ----------------
__device__ __forceinline__ float softplus_f(float z) {
    return fmaxf(z, 0.0f) + log1pf(expf(-fabsf(z)));
}
__device__ __forceinline__ uint32_t smem_u32(const void* p) {
    uint32_t a;
    asm("{ .reg .u64 t; cvta.to.shared.u64 t, %1; cvt.u32.u64 %0, t; }" : "=r"(a) : "l"(p));
    return a;
}

#define CP_ASYNC16(dst, src) \
    asm volatile("cp.async.cg.shared.global [%0], [%1], 16;" :: "r"(dst), "l"(src))
#define CP_COMMIT()  asm volatile("cp.async.commit_group;" ::: "memory")
#define CP_WAIT(N)   asm volatile("cp.async.wait_group %0;" :: "n"(N) : "memory")

__device__ __forceinline__ void ldsm_x4(uint32_t& r0, uint32_t& r1, uint32_t& r2, uint32_t& r3,
                                        uint32_t addr) {
    asm volatile("ldmatrix.sync.aligned.m8n8.x4.shared.b16 {%0,%1,%2,%3}, [%4];"
                 : "=r"(r0), "=r"(r1), "=r"(r2), "=r"(r3) : "r"(addr));
}
__device__ __forceinline__ void ldsm_x2(uint32_t& r0, uint32_t& r1, uint32_t addr) {
    asm volatile("ldmatrix.sync.aligned.m8n8.x2.shared.b16 {%0,%1}, [%2];"
                 : "=r"(r0), "=r"(r1) : "r"(addr));
}
__device__ __forceinline__ void mma_bf16(float& c0, float& c1, float& c2, float& c3,
                                         uint32_t a0, uint32_t a1, uint32_t a2, uint32_t a3,
                                         uint32_t b0, uint32_t b1) {
    asm volatile(
        "mma.sync.aligned.m16n8k16.row.col.f32.bf16.bf16.f32 "
        "{%0,%1,%2,%3}, {%4,%5,%6,%7}, {%8,%9}, {%0,%1,%2,%3};"
        : "+f"(c0), "+f"(c1), "+f"(c2), "+f"(c3)
        : "r"(a0), "r"(a1), "r"(a2), "r"(a3), "r"(b0), "r"(b1));
}

// 64B-row smem swizzle: rows of 4x16B segments; seg' = seg ^ ((row>>1)&3).
__device__ __forceinline__ uint32_t sw64(uint32_t o) {
    return o ^ (((o >> 7) & 3u) << 4);
}

// =================================================================================
// Kernel 0 (fused prologue): convert x (blocks 0..8191), transpose Wd (8192..9215),
// transpose [Wb|Wc] (9216..9343).
// =================================================================================
#define PRE_CONV_BLKS  (M_TOT * DM / 4 / 256)   // 8192
#define PRE_TW_BLKS    ((DM / 32) * (DM / 32))  // 1024
#define PRE_WBC_BLKS   ((32 * DM) / 256)        // 128
#define PRE_TOTAL_BLKS (PRE_CONV_BLKS + PRE_TW_BLKS + PRE_WBC_BLKS)

__global__ __launch_bounds__(256) void prologue_kernel(
    const float* __restrict__ x,  const float* __restrict__ Wd,
    const float* __restrict__ Wb, const float* __restrict__ Wc)
{
    __shared__ float tile[32][33];
    const int bid = blockIdx.x;
    const int tid = threadIdx.x;

    if (bid < PRE_CONV_BLKS) {
        const int i = bid * 256 + tid;
        float4 v = ((const float4*)x)[i];
        __nv_bfloat16 hx = __float2bfloat16_rn(v.x);
        __nv_bfloat16 hy = __float2bfloat16_rn(v.y);
        __nv_bfloat16 hz = __float2bfloat16_rn(v.z);
        __nv_bfloat16 hw = __float2bfloat16_rn(v.w);
        __nv_bfloat162* phi = (__nv_bfloat162*)g_xhi;
        __nv_bfloat162* plo = (__nv_bfloat162*)g_xlo;
        phi[i * 2 + 0] = __nv_bfloat162(hx, hy);
        phi[i * 2 + 1] = __nv_bfloat162(hz, hw);
        plo[i * 2 + 0] = __nv_bfloat162(__float2bfloat16_rn(v.x - __bfloat162float(hx)),
                                        __float2bfloat16_rn(v.y - __bfloat162float(hy)));
        plo[i * 2 + 1] = __nv_bfloat162(__float2bfloat16_rn(v.z - __bfloat162float(hz)),
                                        __float2bfloat16_rn(v.w - __bfloat162float(hw)));
    } else if (bid < PRE_CONV_BLKS + PRE_TW_BLKS) {
        const int r  = bid - PRE_CONV_BLKS;
        const int x0 = (r & 31) * 32;
        const int y0 = (r >> 5) * 32;
        const int tx = tid & 31;
        const int ty = tid >> 5;
#pragma unroll
        for (int i = 0; i < 32; i += 8)
            tile[ty + i][tx] = Wd[(y0 + ty + i) * DM + x0 + tx];
        __syncthreads();
#pragma unroll
        for (int i = 0; i < 32; i += 8) {
            float v = tile[tx][ty + i];
            __nv_bfloat16 h = __float2bfloat16_rn(v);
            g_wthi[(x0 + ty + i) * DM + y0 + tx] = h;
            g_wtlo[(x0 + ty + i) * DM + y0 + tx] = __float2bfloat16_rn(v - __bfloat162float(h));
        }
    } else {
        const int idx = (bid - PRE_CONV_BLKS - PRE_TW_BLKS) * 256 + tid;  // 0..32767
        const int n = idx >> 10;
        const int k = idx & (DM - 1);
        float v = (n < 16) ? Wb[k * ST + n] : Wc[k * ST + (n - 16)];
        __nv_bfloat16 h = __float2bfloat16_rn(v);
        g_wbchi[n * DM + k] = h;
        g_wbclo[n * DM + k] = __float2bfloat16_rn(v - __bfloat162float(h));
    }
}

// =================================================================================
// GEMM tile body (delta = softplus(x@Wd + bd)); 3-stage ring, swizzled 64B rows.
// =================================================================================
#define T_A_HI 0
#define T_A_LO 8192
#define T_B_HI 16384
#define T_B_LO 24576
#define BUFS   32768
#define NSTAGE 3
#define GS_TOTAL (NSTAGE * BUFS)  // 98304
#define BK     32
#define NSLAB  (DM / BK)     // 32

__device__ __forceinline__ void gemm_load_slab(uint32_t sb, int stage, int row0, int col0,
                                               int k0, int tid)
{
    const uint32_t base = sb + stage * BUFS;
#pragma unroll
    for (int t = 0; t < 2; t++) {
        int op  = tid + t * 256;        // 0..511
        int row = op >> 2;              // 0..127
        int seg = op & 3;               // 0..3 (16B each)
        uint32_t doff = sw64((uint32_t)(row * 64 + seg * 16));
        CP_ASYNC16(base + T_A_HI + doff, &g_xhi[(row0 + row) * DM + k0 + seg * 8]);
        CP_ASYNC16(base + T_A_LO + doff, &g_xlo[(row0 + row) * DM + k0 + seg * 8]);
        CP_ASYNC16(base + T_B_HI + doff, &g_wthi[(col0 + row) * DM + k0 + seg * 8]);
        CP_ASYNC16(base + T_B_LO + doff, &g_wtlo[(col0 + row) * DM + k0 + seg * 8]);
    }
}

__device__ void gemm_tile_body(uint32_t sb, int bx, int by, const float* __restrict__ bd)
{
    const int tid  = threadIdx.x;
    const int lane = tid & 31;
    const int warp = tid >> 5;
    const int wm   = warp & 1;
    const int wn   = warp >> 1;
    const int row0 = by * 128;
    const int col0 = bx * 128;

    float acc[4][4][4];
#pragma unroll
    for (int i = 0; i < 4; i++)
#pragma unroll
        for (int j = 0; j < 4; j++)
#pragma unroll
            for (int k = 0; k < 4; k++) acc[i][j][k] = 0.0f;

    const int rlA = (lane & 7) + 8 * ((lane >> 3) & 1);
    const int cA  = (lane >> 4) & 1;
    const int rlB = lane & 7;
    const int cB  = (lane >> 3) & 1;

    uint32_t aoff[4], boff[4];
#pragma unroll
    for (int mf = 0; mf < 4; mf++) {
        int row = wm * 64 + mf * 16 + rlA;
        aoff[mf] = sw64((uint32_t)(row * 64 + cA * 16));
    }
#pragma unroll
    for (int nf = 0; nf < 4; nf++) {
        int row = wn * 32 + nf * 8 + rlB;
        boff[nf] = sw64((uint32_t)(row * 64 + cB * 16));
    }

    gemm_load_slab(sb, 0, row0, col0, 0, tid);
    CP_COMMIT();
    gemm_load_slab(sb, 1, row0, col0, BK, tid);
    CP_COMMIT();

    for (int s = 0; s < NSLAB; s++) {
        if (s + 1 < NSLAB) { CP_WAIT(1); } else { CP_WAIT(0); }
        __syncthreads();

        if (s + 2 < NSLAB) {
            gemm_load_slab(sb, (s + 2) % NSTAGE, row0, col0, (s + 2) * BK, tid);
            CP_COMMIT();
        }

        const uint32_t bufb = sb + (s % NSTAGE) * BUFS;
        const uint32_t aHi = bufb + T_A_HI;
        const uint32_t aLo = bufb + T_A_LO;
        const uint32_t bHi = bufb + T_B_HI;
        const uint32_t bLo = bufb + T_B_LO;

#pragma unroll
        for (int ks = 0; ks < 2; ks++) {
            const uint32_t kx = ks ? 0x20u : 0u;
            uint32_t ah[4][4], al[4][4];
#pragma unroll
            for (int mf = 0; mf < 4; mf++) {
                uint32_t ao = aoff[mf] ^ kx;
                ldsm_x4(ah[mf][0], ah[mf][1], ah[mf][2], ah[mf][3], aHi + ao);
                ldsm_x4(al[mf][0], al[mf][1], al[mf][2], al[mf][3], aLo + ao);
            }
            uint32_t bh[4][2], bl[4][2];
#pragma unroll
            for (int nf = 0; nf < 4; nf++) {
                uint32_t bo = boff[nf] ^ kx;
                ldsm_x2(bh[nf][0], bh[nf][1], bHi + bo);
                ldsm_x2(bl[nf][0], bl[nf][1], bLo + bo);
            }
#pragma unroll
            for (int mf = 0; mf < 4; mf++)
#pragma unroll
                for (int nf = 0; nf < 4; nf++) {
                    float* c = acc[mf][nf];
                    mma_bf16(c[0], c[1], c[2], c[3],
                             ah[mf][0], ah[mf][1], ah[mf][2], ah[mf][3],
                             bh[nf][0], bh[nf][1]);
                    mma_bf16(c[0], c[1], c[2], c[3],
                             ah[mf][0], ah[mf][1], ah[mf][2], ah[mf][3],
                             bl[nf][0], bl[nf][1]);
                    mma_bf16(c[0], c[1], c[2], c[3],
                             al[mf][0], al[mf][1], al[mf][2], al[mf][3],
                             bh[nf][0], bh[nf][1]);
                }
        }
    }

    const int g   = lane >> 2;
    const int tig = lane & 3;
#pragma unroll
    for (int nf = 0; nf < 4; nf++) {
        const int col = col0 + wn * 32 + nf * 8 + tig * 2;
        const float b0v = bd[col];
        const float b1v = bd[col + 1];
#pragma unroll
        for (int mf = 0; mf < 4; mf++) {
            const int row = row0 + wm * 64 + mf * 16 + g;
            float* c = acc[mf][nf];
            float2 v0, v1;
            v0.x = softplus_f(c[0] + b0v);
            v0.y = softplus_f(c[1] + b1v);
            v1.x = softplus_f(c[2] + b0v);
            v1.y = softplus_f(c[3] + b1v);
            *(float2*)&g_delta[row * DM + col]       = v0;
            *(float2*)&g_delta[(row + 8) * DM + col] = v1;
        }
    }
}

// =================================================================================
// Proj tile body (B/C projection split-K x4, partials -> g_BCp). K=256 per block.
// =================================================================================
#define ROWB    80
#define PJ_A_HI 0
#define PJ_A_LO 10240
#define PJ_B_HI 20480
#define PJ_B_LO 23040
#define PJ_BUF  25600
#define NPJS    ((DM / PKSEG) / BK)   // 8 slabs

__device__ __forceinline__ void proj_load_slab(uint32_t sb, int buf, int row0, int k0, int tid)
{
    const uint32_t base = sb + buf * PJ_BUF;
#pragma unroll
    for (int t = 0; t < 2; t++) {
        int op  = tid + t * 256;
        int row = op >> 2;
        int seg = op & 3;
        uint32_t doff = row * ROWB + seg * 16;
        CP_ASYNC16(base + PJ_A_HI + doff, &g_xhi[(row0 + row) * DM + k0 + seg * 8]);
        CP_ASYNC16(base + PJ_A_LO + doff, &g_xlo[(row0 + row) * DM + k0 + seg * 8]);
    }
    {
        int row = (tid & 127) >> 2;      // 0..31
        int seg = tid & 3;
        uint32_t doff = row * ROWB + seg * 16;
        if (tid < 128)
            CP_ASYNC16(base + PJ_B_HI + doff, &g_wbchi[row * DM + k0 + seg * 8]);
        else
            CP_ASYNC16(base + PJ_B_LO + doff, &g_wbclo[row * DM + k0 + seg * 8]);
    }
}

__device__ void proj_tile_body(uint32_t sb, int pm, int kseg)
{
    const int tid  = threadIdx.x;
    const int lane = tid & 31;
    const int warp = tid >> 5;
    const int row0 = pm * 128;
    const int kbeg = kseg * (DM / PKSEG);

    float acc[4][4];
#pragma unroll
    for (int i = 0; i < 4; i++)
#pragma unroll
        for (int j = 0; j < 4; j++) acc[i][j] = 0.0f;

    const int rlA = (lane & 7) + 8 * ((lane >> 3) & 1);
    const int cbA = (lane >> 4) * 16;
    const int rlB = lane & 7;
    const int cbB = ((lane >> 3) & 1) * 16;

    proj_load_slab(sb, 0, row0, kbeg, tid);
    CP_COMMIT();

#pragma unroll
    for (int s = 0; s < NPJS; s++) {
        if (s + 1 < NPJS) {
            proj_load_slab(sb, (s + 1) & 1, row0, kbeg + (s + 1) * BK, tid);
            CP_COMMIT();
            CP_WAIT(1);
        } else {
            CP_WAIT(0);
        }
        __syncthreads();

        const uint32_t bufb = sb + (s & 1) * PJ_BUF;
        const uint32_t aHi = bufb + PJ_A_HI + (warp * 16) * ROWB;
        const uint32_t aLo = bufb + PJ_A_LO + (warp * 16) * ROWB;
        const uint32_t bHi = bufb + PJ_B_HI;
        const uint32_t bLo = bufb + PJ_B_LO;

#pragma unroll
        for (int ks = 0; ks < 2; ks++) {
            const int ksb = ks * 32;
            uint32_t ah[4], al[4];
            uint32_t ao = rlA * ROWB + ksb + cbA;
            ldsm_x4(ah[0], ah[1], ah[2], ah[3], aHi + ao);
            ldsm_x4(al[0], al[1], al[2], al[3], aLo + ao);
            uint32_t bh[4][2], bl[4][2];
#pragma unroll
            for (int nf = 0; nf < 4; nf++) {
                uint32_t bo = (nf * 8 + rlB) * ROWB + ksb + cbB;
                ldsm_x2(bh[nf][0], bh[nf][1], bHi + bo);
                ldsm_x2(bl[nf][0], bl[nf][1], bLo + bo);
            }
#pragma unroll
            for (int nf = 0; nf < 4; nf++) {
                float* c = acc[nf];
                mma_bf16(c[0], c[1], c[2], c[3], ah[0], ah[1], ah[2], ah[3],
                         bh[nf][0], bh[nf][1]);
                mma_bf16(c[0], c[1], c[2], c[3], ah[0], ah[1], ah[2], ah[3],
                         bl[nf][0], bl[nf][1]);
                mma_bf16(c[0], c[1], c[2], c[3], al[0], al[1], al[2], al[3],
                         bh[nf][0], bh[nf][1]);
            }
        }
        __syncthreads();
    }

    const int g   = lane >> 2;
    const int tig = lane & 3;
    float* dst = g_BCp + kseg * (M_TOT * 2 * ST);
#pragma unroll
    for (int nf = 0; nf < 4; nf++) {
        const int cc  = nf * 8 + tig * 2;
        const int isC = (cc >= 16);
        const int n   = cc & 15;
        const int r0r = row0 + warp * 16 + g;
        float* c = acc[nf];
        *(float2*)&dst[(r0r * 8 + (n >> 1)) * 4 + isC * 2]       = make_float2(c[0], c[1]);
        *(float2*)&dst[((r0r + 8) * 8 + (n >> 1)) * 4 + isC * 2] = make_float2(c[2], c[3]);
    }
}

// =================================================================================
// Kernel 1 (fused): blocks 0..511 gemm tiles, 512..767 proj tiles.
// =================================================================================
__global__ __launch_bounds__(256, 2) void fused_mma_kernel(const float* __restrict__ bd)
{
    extern __shared__ char smem[];
    const uint32_t sb = smem_u32(smem);
    const int bid = blockIdx.x;
    if (bid < 512) {
        gemm_tile_body(sb, bid & 7, bid >> 3, bd);
    } else {
        const int r = bid - 512;
        proj_tile_body(sb, r & 63, r >> 6);
    }
}

// =================================================================================
// Kernel 3a / 3c: chunk-local scan; packed f32x2; BC partial-sum folded into staging
// (no proj_reduce kernel, no g_BC buffer).
// =================================================================================
#define LOG2E_F 1.4426950408889634f

template<bool FINAL>
__global__ __launch_bounds__(256) void scan_chunk_kernel(
    const float* __restrict__ x,
    const float* __restrict__ A_log,
    const float* __restrict__ D_skip,
    const float* __restrict__ bb,
    const float* __restrict__ bc,
    float* __restrict__ out)
{
    __shared__ float4 sbc[CLEN * 8];   // 8 KB

    const int tid = threadIdx.x;
    const int db  = blockIdx.x & 3;
    const int c   = (blockIdx.x >> 2) & (CHUNKS - 1);
    const int b   = blockIdx.x >> 7;
    const int d   = db * 256 + tid;
    const int rowbase = b * SEQ + c * CLEN;

    // stage BC: sum PKSEG partials + bias
    {
        const float4* __restrict__ pp = (const float4*)g_BCp;
        const int M8 = M_TOT * 8;
#pragma unroll
        for (int i0 = 0; i0 < 2; i0++) {
            const int i   = tid + i0 * 256;          // 0..511
            const int pos = rowbase * 8 + i;
            float4 v = pp[pos];
#pragma unroll
            for (int k = 1; k < PKSEG; k++) {
                float4 w = pp[k * M8 + pos];
                v.x += w.x; v.y += w.y; v.z += w.z; v.w += w.w;
            }
            const int s = i & 7;
            v.x += bb[2 * s];
            v.y += bb[2 * s + 1];
            v.z += bc[2 * s];
            v.w += bc[2 * s + 1];
            sbc[i] = v;
        }
    }
    const uint32_t sbcu = smem_u32(sbc);

    // A2 packed: (-exp(A_log)*log2e) pairs as f32x2
    unsigned long long A2p[8];
#pragma unroll
    for (int n = 0; n < 16; n += 4) {
        float4 v = *(const float4*)&A_log[d * ST + n];
        float a0 = -expf(v.x) * LOG2E_F;
        float a1 = -expf(v.y) * LOG2E_F;
        float a2 = -expf(v.z) * LOG2E_F;
        float a3 = -expf(v.w) * LOG2E_F;
        asm("mov.b64 %0, {%1, %2};" : "=l"(A2p[n / 2])     : "f"(a0), "f"(a1));
        asm("mov.b64 %0, {%1, %2};" : "=l"(A2p[n / 2 + 1]) : "f"(a2), "f"(a3));
    }

    const int sidx = ((b * CHUNKS + c) * DM + d) * ST;
    unsigned long long h[8];
    float Dsk = 0.0f, dts = 0.0f;
    if (FINAL) {
        const ulonglong2* hp = (const ulonglong2*)&g_hinit[sidx];
#pragma unroll
        for (int q = 0; q < 4; q++) {
            ulonglong2 v = hp[q];
            h[2 * q]     = v.x;
            h[2 * q + 1] = v.y;
        }
        Dsk = D_skip[d];
    } else {
#pragma unroll
        for (int s = 0; s < 8; s++) h[s] = 0ull;
    }
    __syncthreads();

    const float* dp = g_delta + rowbase * DM + d;
    const float* xp = x       + rowbase * DM + d;
    float*       op = out     + rowbase * DM + d;

    float dt = dp[0];
    float xv = xp[0];

#pragma unroll 4
    for (int t = 0; t < CLEN; t++) {
        float dt_n = 0.0f, xv_n = 0.0f;
        if (t + 1 < CLEN) {
            dt_n = dp[(t + 1) * DM];
            xv_n = xp[(t + 1) * DM];
        }
        float dx = dt * xv;
        unsigned long long dxpk, dtpk;
        asm("mov.b64 %0, {%1, %1};" : "=l"(dxpk) : "f"(dx));
        asm("mov.b64 %0, {%1, %1};" : "=l"(dtpk) : "f"(dt));
        unsigned long long ypk = 0ull;
        const uint32_t taddr = sbcu + (uint32_t)(t * 8) * 16u;
#pragma unroll
        for (int s = 0; s < 8; s++) {
            unsigned long long bpk, cpk;
            asm volatile("ld.shared.v2.u64 {%0, %1}, [%2];"
                         : "=l"(bpk), "=l"(cpk) : "r"(taddr + s * 16u));
            unsigned long long apk;
            asm("mul.rn.f32x2 %0, %1, %2;" : "=l"(apk) : "l"(dtpk), "l"(A2p[s]));
            float a0, a1;
            asm("mov.b64 {%0, %1}, %2;" : "=f"(a0), "=f"(a1) : "l"(apk));
            float e0, e1;
            asm("ex2.approx.f32 %0, %1;" : "=f"(e0) : "f"(a0));
            asm("ex2.approx.f32 %0, %1;" : "=f"(e1) : "f"(a1));
            unsigned long long epk;
            asm("mov.b64 %0, {%1, %2};" : "=l"(epk) : "f"(e0), "f"(e1));
            unsigned long long dxB;
            asm("mul.rn.f32x2 %0, %1, %2;" : "=l"(dxB) : "l"(dxpk), "l"(bpk));
            asm("fma.rn.f32x2 %0, %1, %0, %2;" : "+l"(h[s]) : "l"(epk), "l"(dxB));
            if (FINAL)
                asm("fma.rn.f32x2 %0, %1, %2, %0;" : "+l"(ypk) : "l"(h[s]), "l"(cpk));
        }
        if (FINAL) {
            float y0, y1;
            asm("mov.b64 {%0, %1}, %2;" : "=f"(y0), "=f"(y1) : "l"(ypk));
            op[t * DM] = fmaf(xv, Dsk, y0 + y1);
        } else {
            dts += dt;
        }
        dt = dt_n;
        xv = xv_n;
    }

    if (!FINAL) {
        ulonglong2* fp = (ulonglong2*)&g_f[sidx];
#pragma unroll
        for (int q = 0; q < 4; q++) {
            ulonglong2 v;
            v.x = h[2 * q];
            v.y = h[2 * q + 1];
            fp[q] = v;
        }
        g_dtsum[(b * CHUNKS + c) * DM + d] = dts;
    }
}

// =================================================================================
// Kernel 3b: sequential combine across chunks.
// =================================================================================
__global__ __launch_bounds__(256) void scan_combine_kernel(
    const float* __restrict__ A_log)
{
    const int tid = blockIdx.x * blockDim.x + threadIdx.x;
    const int n = tid & 15;
    const int d = (tid >> 4) & (DM - 1);
    const int b = tid >> 14;

    float* __restrict__       hi = g_hinit;
    const float* __restrict__ ff = g_f;
    const float* __restrict__ ds = g_dtsum;

    const float A = -expf(A_log[d * ST + n]);
    float H = 0.0f;
#pragma unroll
    for (int c = 0; c < CHUNKS; c++) {
        const int base = (b * CHUNKS + c) * DM + d;
        hi[base * ST + n] = H;
        float P = __expf(A * ds[base]);
        H = fmaf(P, H, ff[base * ST + n]);
    }
}

// =================================================================================
// launch — single stream; concurrency expressed inside the fused kernels.
// =================================================================================
extern "C" void kernel_launch(void* const* d_in, const int* in_sizes, int n_in,
                              void* d_out, int out_size)
{
    const float* x      = (const float*)d_in[0];
    const float* A_log  = (const float*)d_in[1];
    const float* D_skip = (const float*)d_in[2];
    const float* Wd     = (const float*)d_in[3];
    const float* bd     = (const float*)d_in[4];
    const float* Wb     = (const float*)d_in[5];
    const float* bb     = (const float*)d_in[6];
    const float* Wc     = (const float*)d_in[7];
    const float* bc     = (const float*)d_in[8];
    float* out = (float*)d_out;

    cudaFuncSetAttribute(fused_mma_kernel, cudaFuncAttributeMaxDynamicSharedMemorySize, GS_TOTAL);

    prologue_kernel<<<PRE_TOTAL_BLKS, 256>>>(x, Wd, Wb, Wc);
    fused_mma_kernel<<<512 + 64 * PKSEG, 256, GS_TOTAL>>>(bd);

    const int scan_grid = B_SZ * CHUNKS * (DM / 256);   // 512
    scan_chunk_kernel<false><<<scan_grid, 256>>>(x, A_log, D_skip, bb, bc, out);
    scan_combine_kernel<<<(B_SZ * DM * ST) / 256, 256>>>(A_log);
    scan_chunk_kernel<true><<<scan_grid, 256>>>(x, A_log, D_skip, bb, bc, out);
}

// round 15
// speedup vs baseline: 1.7962x; 1.0734x over previous
#include <cuda_runtime.h>
#include <cuda_bf16.h>
#include <math.h>
#include <stdint.h>

#define B_SZ   4
#define SEQ    2048
#define DM     1024
#define ST     16
#define M_TOT  (B_SZ * SEQ)   // 8192 rows
#define CHUNKS 64
#define CLEN   (SEQ / CHUNKS) // 32
#define PKSEG  4

// ---------------- scratch (static device globals; no allocation) ----------------
__device__ float g_delta[M_TOT * DM];              // 32 MB
__device__ float g_BCp[PKSEG * M_TOT * 2 * ST];    // 4 MB partials
__device__ float g_f[B_SZ * CHUNKS * DM * ST];     // 16 MB
__device__ float g_hinit[B_SZ * CHUNKS * DM * ST]; // 16 MB
__device__ float g_dtsum[B_SZ * CHUNKS * DM];      // 1 MB
__device__ __nv_bfloat16 g_xhi[M_TOT * DM];        // 16 MB
__device__ __nv_bfloat16 g_xlo[M_TOT * DM];        // 16 MB
__device__ __nv_bfloat16 g_wthi[DM * DM];          // 2 MB  (n,k)-major
__device__ __nv_bfloat16 g_wtlo[DM * DM];          // 2 MB
__device__ __nv_bfloat16 g_wbchi[32 * DM];         // 64 KB (n,k)-major [Wb;Wc]^T
__device__ __nv_bfloat16 g_wbclo[32 * DM];         // 64 KB

// ---------------- helpers ----------------
__device__ __forceinline__ float softplus_f(float z) {
    return fmaxf(z, 0.0f) + log1pf(expf(-fabsf(z)));
}
__device__ __forceinline__ uint32_t smem_u32(const void* p) {
    uint32_t a;
    asm("{ .reg .u64 t; cvta.to.shared.u64 t, %1; cvt.u32.u64 %0, t; }" : "=r"(a) : "l"(p));
    return a;
}

#define CP_ASYNC16(dst, src) \
    asm volatile("cp.async.cg.shared.global [%0], [%1], 16;" :: "r"(dst), "l"(src))
#define CP_COMMIT()  asm volatile("cp.async.commit_group;" ::: "memory")
#define CP_WAIT(N)   asm volatile("cp.async.wait_group %0;" :: "n"(N) : "memory")

__device__ __forceinline__ void ldsm_x4(uint32_t& r0, uint32_t& r1, uint32_t& r2, uint32_t& r3,
                                        uint32_t addr) {
    asm volatile("ldmatrix.sync.aligned.m8n8.x4.shared.b16 {%0,%1,%2,%3}, [%4];"
                 : "=r"(r0), "=r"(r1), "=r"(r2), "=r"(r3) : "r"(addr));
}
__device__ __forceinline__ void ldsm_x2(uint32_t& r0, uint32_t& r1, uint32_t addr) {
    asm volatile("ldmatrix.sync.aligned.m8n8.x2.shared.b16 {%0,%1}, [%2];"
                 : "=r"(r0), "=r"(r1) : "r"(addr));
}
__device__ __forceinline__ void mma_bf16(float& c0, float& c1, float& c2, float& c3,
                                         uint32_t a0, uint32_t a1, uint32_t a2, uint32_t a3,
                                         uint32_t b0, uint32_t b1) {
    asm volatile(
        "mma.sync.aligned.m16n8k16.row.col.f32.bf16.bf16.f32 "
        "{%0,%1,%2,%3}, {%4,%5,%6,%7}, {%8,%9}, {%0,%1,%2,%3};"
        : "+f"(c0), "+f"(c1), "+f"(c2), "+f"(c3)
        : "r"(a0), "r"(a1), "r"(a2), "r"(a3), "r"(b0), "r"(b1));
}

// 64B-row smem swizzle: rows of 4x16B segments; seg' = seg ^ ((row>>1)&3).
__device__ __forceinline__ uint32_t sw64(uint32_t o) {
    return o ^ (((o >> 7) & 3u) << 4);
}

// =================================================================================
// Kernel 0 (fused prologue): convert x (blocks 0..8191), transpose Wd (8192..9215),
// transpose [Wb|Wc] (9216..9343).
// =================================================================================
#define PRE_CONV_BLKS  (M_TOT * DM / 4 / 256)   // 8192
#define PRE_TW_BLKS    ((DM / 32) * (DM / 32))  // 1024
#define PRE_WBC_BLKS   ((32 * DM) / 256)        // 128
#define PRE_TOTAL_BLKS (PRE_CONV_BLKS + PRE_TW_BLKS + PRE_WBC_BLKS)

__global__ __launch_bounds__(256) void prologue_kernel(
    const float* __restrict__ x,  const float* __restrict__ Wd,
    const float* __restrict__ Wb, const float* __restrict__ Wc)
{
    __shared__ float tile[32][33];
    const int bid = blockIdx.x;
    const int tid = threadIdx.x;

    if (bid < PRE_CONV_BLKS) {
        const int i = bid * 256 + tid;
        float4 v = ((const float4*)x)[i];
        __nv_bfloat16 hx = __float2bfloat16_rn(v.x);
        __nv_bfloat16 hy = __float2bfloat16_rn(v.y);
        __nv_bfloat16 hz = __float2bfloat16_rn(v.z);
        __nv_bfloat16 hw = __float2bfloat16_rn(v.w);
        __nv_bfloat162* phi = (__nv_bfloat162*)g_xhi;
        __nv_bfloat162* plo = (__nv_bfloat162*)g_xlo;
        phi[i * 2 + 0] = __nv_bfloat162(hx, hy);
        phi[i * 2 + 1] = __nv_bfloat162(hz, hw);
        plo[i * 2 + 0] = __nv_bfloat162(__float2bfloat16_rn(v.x - __bfloat162float(hx)),
                                        __float2bfloat16_rn(v.y - __bfloat162float(hy)));
        plo[i * 2 + 1] = __nv_bfloat162(__float2bfloat16_rn(v.z - __bfloat162float(hz)),
                                        __float2bfloat16_rn(v.w - __bfloat162float(hw)));
    } else if (bid < PRE_CONV_BLKS + PRE_TW_BLKS) {
        const int r  = bid - PRE_CONV_BLKS;
        const int x0 = (r & 31) * 32;
        const int y0 = (r >> 5) * 32;
        const int tx = tid & 31;
        const int ty = tid >> 5;
#pragma unroll
        for (int i = 0; i < 32; i += 8)
            tile[ty + i][tx] = Wd[(y0 + ty + i) * DM + x0 + tx];
        __syncthreads();
#pragma unroll
        for (int i = 0; i < 32; i += 8) {
            float v = tile[tx][ty + i];
            __nv_bfloat16 h = __float2bfloat16_rn(v);
            g_wthi[(x0 + ty + i) * DM + y0 + tx] = h;
            g_wtlo[(x0 + ty + i) * DM + y0 + tx] = __float2bfloat16_rn(v - __bfloat162float(h));
        }
    } else {
        const int idx = (bid - PRE_CONV_BLKS - PRE_TW_BLKS) * 256 + tid;  // 0..32767
        const int n = idx >> 10;
        const int k = idx & (DM - 1);
        float v = (n < 16) ? Wb[k * ST + n] : Wc[k * ST + (n - 16)];
        __nv_bfloat16 h = __float2bfloat16_rn(v);
        g_wbchi[n * DM + k] = h;
        g_wbclo[n * DM + k] = __float2bfloat16_rn(v - __bfloat162float(h));
    }
}

// =================================================================================
// GEMM tile body (delta = softplus(x@Wd + bd)); 3-stage ring, swizzled 64B rows.
// =================================================================================
#define T_A_HI 0
#define T_A_LO 8192
#define T_B_HI 16384
#define T_B_LO 24576
#define BUFS   32768
#define NSTAGE 3
#define GS_TOTAL (NSTAGE * BUFS)  // 98304
#define BK     32
#define NSLAB  (DM / BK)     // 32

__device__ __forceinline__ void gemm_load_slab(uint32_t sb, int stage, int row0, int col0,
                                               int k0, int tid)
{
    const uint32_t base = sb + stage * BUFS;
#pragma unroll
    for (int t = 0; t < 2; t++) {
        int op  = tid + t * 256;        // 0..511
        int row = op >> 2;              // 0..127
        int seg = op & 3;               // 0..3 (16B each)
        uint32_t doff = sw64((uint32_t)(row * 64 + seg * 16));
        CP_ASYNC16(base + T_A_HI + doff, &g_xhi[(row0 + row) * DM + k0 + seg * 8]);
        CP_ASYNC16(base + T_A_LO + doff, &g_xlo[(row0 + row) * DM + k0 + seg * 8]);
        CP_ASYNC16(base + T_B_HI + doff, &g_wthi[(col0 + row) * DM + k0 + seg * 8]);
        CP_ASYNC16(base + T_B_LO + doff, &g_wtlo[(col0 + row) * DM + k0 + seg * 8]);
    }
}

__device__ void gemm_tile_body(uint32_t sb, int bx, int by, const float* __restrict__ bd)
{
    const int tid  = threadIdx.x;
    const int lane = tid & 31;
    const int warp = tid >> 5;
    const int wm   = warp & 1;
    const int wn   = warp >> 1;
    const int row0 = by * 128;
    const int col0 = bx * 128;

    float acc[4][4][4];
#pragma unroll
    for (int i = 0; i < 4; i++)
#pragma unroll
        for (int j = 0; j < 4; j++)
#pragma unroll
            for (int k = 0; k < 4; k++) acc[i][j][k] = 0.0f;

    const int rlA = (lane & 7) + 8 * ((lane >> 3) & 1);
    const int cA  = (lane >> 4) & 1;
    const int rlB = lane & 7;
    const int cB  = (lane >> 3) & 1;

    uint32_t aoff[4], boff[4];
#pragma unroll
    for (int mf = 0; mf < 4; mf++) {
        int row = wm * 64 + mf * 16 + rlA;
        aoff[mf] = sw64((uint32_t)(row * 64 + cA * 16));
    }
#pragma unroll
    for (int nf = 0; nf < 4; nf++) {
        int row = wn * 32 + nf * 8 + rlB;
        boff[nf] = sw64((uint32_t)(row * 64 + cB * 16));
    }

    gemm_load_slab(sb, 0, row0, col0, 0, tid);
    CP_COMMIT();
    gemm_load_slab(sb, 1, row0, col0, BK, tid);
    CP_COMMIT();

    for (int s = 0; s < NSLAB; s++) {
        if (s + 1 < NSLAB) { CP_WAIT(1); } else { CP_WAIT(0); }
        __syncthreads();

        if (s + 2 < NSLAB) {
            gemm_load_slab(sb, (s + 2) % NSTAGE, row0, col0, (s + 2) * BK, tid);
            CP_COMMIT();
        }

        const uint32_t bufb = sb + (s % NSTAGE) * BUFS;
        const uint32_t aHi = bufb + T_A_HI;
        const uint32_t aLo = bufb + T_A_LO;
        const uint32_t bHi = bufb + T_B_HI;
        const uint32_t bLo = bufb + T_B_LO;

#pragma unroll
        for (int ks = 0; ks < 2; ks++) {
            const uint32_t kx = ks ? 0x20u : 0u;
            uint32_t ah[4][4], al[4][4];
#pragma unroll
            for (int mf = 0; mf < 4; mf++) {
                uint32_t ao = aoff[mf] ^ kx;
                ldsm_x4(ah[mf][0], ah[mf][1], ah[mf][2], ah[mf][3], aHi + ao);
                ldsm_x4(al[mf][0], al[mf][1], al[mf][2], al[mf][3], aLo + ao);
            }
            uint32_t bh[4][2], bl[4][2];
#pragma unroll
            for (int nf = 0; nf < 4; nf++) {
                uint32_t bo = boff[nf] ^ kx;
                ldsm_x2(bh[nf][0], bh[nf][1], bHi + bo);
                ldsm_x2(bl[nf][0], bl[nf][1], bLo + bo);
            }
#pragma unroll
            for (int mf = 0; mf < 4; mf++)
#pragma unroll
                for (int nf = 0; nf < 4; nf++) {
                    float* c = acc[mf][nf];
                    mma_bf16(c[0], c[1], c[2], c[3],
                             ah[mf][0], ah[mf][1], ah[mf][2], ah[mf][3],
                             bh[nf][0], bh[nf][1]);
                    mma_bf16(c[0], c[1], c[2], c[3],
                             ah[mf][0], ah[mf][1], ah[mf][2], ah[mf][3],
                             bl[nf][0], bl[nf][1]);
                    mma_bf16(c[0], c[1], c[2], c[3],
                             al[mf][0], al[mf][1], al[mf][2], al[mf][3],
                             bh[nf][0], bh[nf][1]);
                }
        }
    }

    const int g   = lane >> 2;
    const int tig = lane & 3;
#pragma unroll
    for (int nf = 0; nf < 4; nf++) {
        const int col = col0 + wn * 32 + nf * 8 + tig * 2;
        const float b0v = bd[col];
        const float b1v = bd[col + 1];
#pragma unroll
        for (int mf = 0; mf < 4; mf++) {
            const int row = row0 + wm * 64 + mf * 16 + g;
            float* c = acc[mf][nf];
            float2 v0, v1;
            v0.x = softplus_f(c[0] + b0v);
            v0.y = softplus_f(c[1] + b1v);
            v1.x = softplus_f(c[2] + b0v);
            v1.y = softplus_f(c[3] + b1v);
            *(float2*)&g_delta[row * DM + col]       = v0;
            *(float2*)&g_delta[(row + 8) * DM + col] = v1;
        }
    }
}

// =================================================================================
// Proj tile body (B/C projection split-K x4, partials -> g_BCp). K=256 per block.
// =================================================================================
#define ROWB    80
#define PJ_A_HI 0
#define PJ_A_LO 10240
#define PJ_B_HI 20480
#define PJ_B_LO 23040
#define PJ_BUF  25600
#define NPJS    ((DM / PKSEG) / BK)   // 8 slabs

__device__ __forceinline__ void proj_load_slab(uint32_t sb, int buf, int row0, int k0, int tid)
{
    const uint32_t base = sb + buf * PJ_BUF;
#pragma unroll
    for (int t = 0; t < 2; t++) {
        int op  = tid + t * 256;
        int row = op >> 2;
        int seg = op & 3;
        uint32_t doff = row * ROWB + seg * 16;
        CP_ASYNC16(base + PJ_A_HI + doff, &g_xhi[(row0 + row) * DM + k0 + seg * 8]);
        CP_ASYNC16(base + PJ_A_LO + doff, &g_xlo[(row0 + row) * DM + k0 + seg * 8]);
    }
    {
        int row = (tid & 127) >> 2;      // 0..31
        int seg = tid & 3;
        uint32_t doff = row * ROWB + seg * 16;
        if (tid < 128)
            CP_ASYNC16(base + PJ_B_HI + doff, &g_wbchi[row * DM + k0 + seg * 8]);
        else
            CP_ASYNC16(base + PJ_B_LO + doff, &g_wbclo[row * DM + k0 + seg * 8]);
    }
}

__device__ void proj_tile_body(uint32_t sb, int pm, int kseg)
{
    const int tid  = threadIdx.x;
    const int lane = tid & 31;
    const int warp = tid >> 5;
    const int row0 = pm * 128;
    const int kbeg = kseg * (DM / PKSEG);

    float acc[4][4];
#pragma unroll
    for (int i = 0; i < 4; i++)
#pragma unroll
        for (int j = 0; j < 4; j++) acc[i][j] = 0.0f;

    const int rlA = (lane & 7) + 8 * ((lane >> 3) & 1);
    const int cbA = (lane >> 4) * 16;
    const int rlB = lane & 7;
    const int cbB = ((lane >> 3) & 1) * 16;

    proj_load_slab(sb, 0, row0, kbeg, tid);
    CP_COMMIT();

#pragma unroll
    for (int s = 0; s < NPJS; s++) {
        if (s + 1 < NPJS) {
            proj_load_slab(sb, (s + 1) & 1, row0, kbeg + (s + 1) * BK, tid);
            CP_COMMIT();
            CP_WAIT(1);
        } else {
            CP_WAIT(0);
        }
        __syncthreads();

        const uint32_t bufb = sb + (s & 1) * PJ_BUF;
        const uint32_t aHi = bufb + PJ_A_HI + (warp * 16) * ROWB;
        const uint32_t aLo = bufb + PJ_A_LO + (warp * 16) * ROWB;
        const uint32_t bHi = bufb + PJ_B_HI;
        const uint32_t bLo = bufb + PJ_B_LO;

#pragma unroll
        for (int ks = 0; ks < 2; ks++) {
            const int ksb = ks * 32;
            uint32_t ah[4], al[4];
            uint32_t ao = rlA * ROWB + ksb + cbA;
            ldsm_x4(ah[0], ah[1], ah[2], ah[3], aHi + ao);
            ldsm_x4(al[0], al[1], al[2], al[3], aLo + ao);
            uint32_t bh[4][2], bl[4][2];
#pragma unroll
            for (int nf = 0; nf < 4; nf++) {
                uint32_t bo = (nf * 8 + rlB) * ROWB + ksb + cbB;
                ldsm_x2(bh[nf][0], bh[nf][1], bHi + bo);
                ldsm_x2(bl[nf][0], bl[nf][1], bLo + bo);
            }
#pragma unroll
            for (int nf = 0; nf < 4; nf++) {
                float* c = acc[nf];
                mma_bf16(c[0], c[1], c[2], c[3], ah[0], ah[1], ah[2], ah[3],
                         bh[nf][0], bh[nf][1]);
                mma_bf16(c[0], c[1], c[2], c[3], ah[0], ah[1], ah[2], ah[3],
                         bl[nf][0], bl[nf][1]);
                mma_bf16(c[0], c[1], c[2], c[3], al[0], al[1], al[2], al[3],
                         bh[nf][0], bh[nf][1]);
            }
        }
        __syncthreads();
    }

    const int g   = lane >> 2;
    const int tig = lane & 3;
    float* dst = g_BCp + kseg * (M_TOT * 2 * ST);
#pragma unroll
    for (int nf = 0; nf < 4; nf++) {
        const int cc  = nf * 8 + tig * 2;
        const int isC = (cc >= 16);
        const int n   = cc & 15;
        const int r0r = row0 + warp * 16 + g;
        float* c = acc[nf];
        *(float2*)&dst[(r0r * 8 + (n >> 1)) * 4 + isC * 2]       = make_float2(c[0], c[1]);
        *(float2*)&dst[((r0r + 8) * 8 + (n >> 1)) * 4 + isC * 2] = make_float2(c[2], c[3]);
    }
}

// =================================================================================
// Kernel 1 (fused): blocks 0..511 gemm tiles, 512..767 proj tiles.
// =================================================================================
__global__ __launch_bounds__(256, 2) void fused_mma_kernel(const float* __restrict__ bd)
{
    extern __shared__ char smem[];
    const uint32_t sb = smem_u32(smem);
    const int bid = blockIdx.x;
    if (bid < 512) {
        gemm_tile_body(sb, bid & 7, bid >> 3, bd);
    } else {
        const int r = bid - 512;
        proj_tile_body(sb, r & 63, r >> 6);
    }
}

// =================================================================================
// Kernel 3a / 3c: chunk-local scan; packed f32x2; BC partial-sum folded into staging.
// CHUNKS=64 -> grid 1024 blocks for latency hiding.
// =================================================================================
#define LOG2E_F 1.4426950408889634f

template<bool FINAL>
__global__ __launch_bounds__(256) void scan_chunk_kernel(
    const float* __restrict__ x,
    const float* __restrict__ A_log,
    const float* __restrict__ D_skip,
    const float* __restrict__ bb,
    const float* __restrict__ bc,
    float* __restrict__ out)
{
    __shared__ float4 sbc[CLEN * 8];   // 4 KB

    const int tid = threadIdx.x;
    const int db  = blockIdx.x & 3;
    const int c   = (blockIdx.x >> 2) & (CHUNKS - 1);
    const int b   = blockIdx.x / (4 * CHUNKS);
    const int d   = db * 256 + tid;
    const int rowbase = b * SEQ + c * CLEN;

    // stage BC: sum PKSEG partials + bias
    {
        const float4* __restrict__ pp = (const float4*)g_BCp;
        const int M8 = M_TOT * 8;
        for (int i = tid; i < CLEN * 8; i += 256) {
            const int pos = rowbase * 8 + i;
            float4 v = pp[pos];
#pragma unroll
            for (int k = 1; k < PKSEG; k++) {
                float4 w = pp[k * M8 + pos];
                v.x += w.x; v.y += w.y; v.z += w.z; v.w += w.w;
            }
            const int s = i & 7;
            v.x += bb[2 * s];
            v.y += bb[2 * s + 1];
            v.z += bc[2 * s];
            v.w += bc[2 * s + 1];
            sbc[i] = v;
        }
    }
    const uint32_t sbcu = smem_u32(sbc);

    // A2 packed: (-exp(A_log)*log2e) pairs as f32x2
    unsigned long long A2p[8];
#pragma unroll
    for (int n = 0; n < 16; n += 4) {
        float4 v = *(const float4*)&A_log[d * ST + n];
        float a0 = -expf(v.x) * LOG2E_F;
        float a1 = -expf(v.y) * LOG2E_F;
        float a2 = -expf(v.z) * LOG2E_F;
        float a3 = -expf(v.w) * LOG2E_F;
        asm("mov.b64 %0, {%1, %2};" : "=l"(A2p[n / 2])     : "f"(a0), "f"(a1));
        asm("mov.b64 %0, {%1, %2};" : "=l"(A2p[n / 2 + 1]) : "f"(a2), "f"(a3));
    }

    const int sidx = ((b * CHUNKS + c) * DM + d) * ST;
    unsigned long long h[8];
    float Dsk = 0.0f, dts = 0.0f;
    if (FINAL) {
        const ulonglong2* hp = (const ulonglong2*)&g_hinit[sidx];
#pragma unroll
        for (int q = 0; q < 4; q++) {
            ulonglong2 v = hp[q];
            h[2 * q]     = v.x;
            h[2 * q + 1] = v.y;
        }
        Dsk = D_skip[d];
    } else {
#pragma unroll
        for (int s = 0; s < 8; s++) h[s] = 0ull;
    }
    __syncthreads();

    const float* dp = g_delta + rowbase * DM + d;
    const float* xp = x       + rowbase * DM + d;
    float*       op = out     + rowbase * DM + d;

    float dt = dp[0];
    float xv = xp[0];

#pragma unroll 4
    for (int t = 0; t < CLEN; t++) {
        float dt_n = 0.0f, xv_n = 0.0f;
        if (t + 1 < CLEN) {
            dt_n = dp[(t + 1) * DM];
            xv_n = xp[(t + 1) * DM];
        }
        float dx = dt * xv;
        unsigned long long dxpk, dtpk;
        asm("mov.b64 %0, {%1, %1};" : "=l"(dxpk) : "f"(dx));
        asm("mov.b64 %0, {%1, %1};" : "=l"(dtpk) : "f"(dt));
        unsigned long long ypk = 0ull;
        const uint32_t taddr = sbcu + (uint32_t)(t * 8) * 16u;
#pragma unroll
        for (int s = 0; s < 8; s++) {
            unsigned long long bpk, cpk;
            asm volatile("ld.shared.v2.u64 {%0, %1}, [%2];"
                         : "=l"(bpk), "=l"(cpk) : "r"(taddr + s * 16u));
            unsigned long long apk;
            asm("mul.rn.f32x2 %0, %1, %2;" : "=l"(apk) : "l"(dtpk), "l"(A2p[s]));
            float a0, a1;
            asm("mov.b64 {%0, %1}, %2;" : "=f"(a0), "=f"(a1) : "l"(apk));
            float e0, e1;
            asm("ex2.approx.f32 %0, %1;" : "=f"(e0) : "f"(a0));
            asm("ex2.approx.f32 %0, %1;" : "=f"(e1) : "f"(a1));
            unsigned long long epk;
            asm("mov.b64 %0, {%1, %2};" : "=l"(epk) : "f"(e0), "f"(e1));
            unsigned long long dxB;
            asm("mul.rn.f32x2 %0, %1, %2;" : "=l"(dxB) : "l"(dxpk), "l"(bpk));
            asm("fma.rn.f32x2 %0, %1, %0, %2;" : "+l"(h[s]) : "l"(epk), "l"(dxB));
            if (FINAL)
                asm("fma.rn.f32x2 %0, %1, %2, %0;" : "+l"(ypk) : "l"(h[s]), "l"(cpk));
        }
        if (FINAL) {
            float y0, y1;
            asm("mov.b64 {%0, %1}, %2;" : "=f"(y0), "=f"(y1) : "l"(ypk));
            op[t * DM] = fmaf(xv, Dsk, y0 + y1);
        } else {
            dts += dt;
        }
        dt = dt_n;
        xv = xv_n;
    }

    if (!FINAL) {
        ulonglong2* fp = (ulonglong2*)&g_f[sidx];
#pragma unroll
        for (int q = 0; q < 4; q++) {
            ulonglong2 v;
            v.x = h[2 * q];
            v.y = h[2 * q + 1];
            fp[q] = v;
        }
        g_dtsum[(b * CHUNKS + c) * DM + d] = dts;
    }
}

// =================================================================================
// Kernel 3b: sequential combine; batch-preload P and f so the LDG/MUFU latency
// pipelines instead of serializing with the H chain.
// =================================================================================
__global__ __launch_bounds__(256) void scan_combine_kernel(
    const float* __restrict__ A_log)
{
    const int tid = blockIdx.x * blockDim.x + threadIdx.x;
    const int n = tid & 15;
    const int d = (tid >> 4) & (DM - 1);
    const int b = tid >> 14;

    float* __restrict__       hi = g_hinit;
    const float* __restrict__ ff = g_f;
    const float* __restrict__ ds = g_dtsum;

    const float A = -expf(A_log[d * ST + n]);
    float H = 0.0f;
#pragma unroll
    for (int c0 = 0; c0 < CHUNKS; c0 += 16) {
        float Pv[16], fv[16];
#pragma unroll
        for (int j = 0; j < 16; j++) {
            const int base = (b * CHUNKS + c0 + j) * DM + d;
            Pv[j] = __expf(A * ds[base]);
            fv[j] = ff[base * ST + n];
        }
#pragma unroll
        for (int j = 0; j < 16; j++) {
            const int base = (b * CHUNKS + c0 + j) * DM + d;
            hi[base * ST + n] = H;
            H = fmaf(Pv[j], H, fv[j]);
        }
    }
}

// =================================================================================
// launch — single stream; concurrency expressed inside the fused kernels.
// =================================================================================
extern "C" void kernel_launch(void* const* d_in, const int* in_sizes, int n_in,
                              void* d_out, int out_size)
{
    const float* x      = (const float*)d_in[0];
    const float* A_log  = (const float*)d_in[1];
    const float* D_skip = (const float*)d_in[2];
    const float* Wd     = (const float*)d_in[3];
    const float* bd     = (const float*)d_in[4];
    const float* Wb     = (const float*)d_in[5];
    const float* bb     = (const float*)d_in[6];
    const float* Wc     = (const float*)d_in[7];
    const float* bc     = (const float*)d_in[8];
    float* out = (float*)d_out;

    cudaFuncSetAttribute(fused_mma_kernel, cudaFuncAttributeMaxDynamicSharedMemorySize, GS_TOTAL);

    prologue_kernel<<<PRE_TOTAL_BLKS, 256>>>(x, Wd, Wb, Wc);
    fused_mma_kernel<<<512 + 64 * PKSEG, 256, GS_TOTAL>>>(bd);

    const int scan_grid = B_SZ * CHUNKS * (DM / 256);   // 1024
    scan_chunk_kernel<false><<<scan_grid, 256>>>(x, A_log, D_skip, bb, bc, out);
    scan_combine_kernel<<<(B_SZ * DM * ST) / 256, 256>>>(A_log);
    scan_chunk_kernel<true><<<scan_grid, 256>>>(x, A_log, D_skip, bb, bc, out);
}